// round 9
// baseline (speedup 1.0000x reference)
#include <cuda_runtime.h>
#include <cuda_fp16.h>
#include <math.h>
#include <stdint.h>

// ---------------- problem constants ----------------
#define Bc 2
#define Sc 2048
#define Dc 1024
#define Hc 16
#define DHc 64
#define Fc 4096
#define Ec 8
#define NTOK (Bc * Sc)
#define LN_EPS 1e-6f

// ---------------- fp32 scratch ----------------
static const size_t F_ATTN  = 0;
static const size_t F_INT   = F_ATTN + (size_t)NTOK * Dc;
static const size_t F_MOE   = F_INT  + (size_t)NTOK * Dc;
static const size_t F_GATE  = F_MOE  + (size_t)NTOK * Dc;
static const size_t F_QKVB  = F_GATE + (size_t)NTOK * Ec;
static const size_t F_TOTAL = F_QKVB + 3 * (size_t)Dc;
__device__ float g_f32[F_TOTAL];

// ---------------- fp16 scratch ----------------
static const size_t H_HID  = 0;
static const size_t H_Q    = H_HID + (size_t)NTOK * Dc;
static const size_t H_K    = H_Q   + (size_t)NTOK * Dc;     // contiguous with Q
static const size_t H_VT   = H_K   + (size_t)NTOK * Dc;     // [B,H,DH,S]
static const size_t H_CTX  = H_VT  + (size_t)NTOK * Dc;
static const size_t H_INT  = H_CTX + (size_t)NTOK * Dc;
static const size_t H_MSK  = H_INT + (size_t)NTOK * Dc;                 // fp16 mask [B,S,S]
static const size_t H_HB   = H_MSK + (size_t)Bc * Sc * Sc;
static const size_t H_P2   = H_HB  + (size_t)Ec * NTOK * Fc;
static const size_t H_WQ   = H_P2  + (size_t)Ec * NTOK * Dc;
static const size_t H_W1   = H_WQ  + 4 * (size_t)Dc * Dc;   // [E][N=F,K=D]
static const size_t H_W2   = H_W1  + (size_t)Ec * Dc * Fc;  // [E][N=D,K=F]
static const size_t H_TOTAL= H_W2  + (size_t)Ec * Fc * Dc;
__device__ __half g_f16[H_TOTAL];

// ---------------- PTX helpers ----------------
__device__ __forceinline__ uint32_t smem_u32(const void* p) {
    uint32_t a;
    asm("{ .reg .u64 t; cvta.to.shared.u64 t, %1; cvt.u32.u64 %0, t; }" : "=r"(a) : "l"(p));
    return a;
}
__device__ __forceinline__ void cp16(uint32_t s, const void* g) {
    asm volatile("cp.async.cg.shared.global [%0], [%1], 16;" :: "r"(s), "l"(g));
}
#define CP_COMMIT() asm volatile("cp.async.commit_group;" ::: "memory")
#define CP_WAIT(n)  asm volatile("cp.async.wait_group %0;" :: "n"(n) : "memory")

__device__ __forceinline__ void ldm_x4(uint32_t* r, uint32_t addr) {
    asm volatile("ldmatrix.sync.aligned.m8n8.x4.shared.b16 {%0,%1,%2,%3}, [%4];"
        : "=r"(r[0]), "=r"(r[1]), "=r"(r[2]), "=r"(r[3]) : "r"(addr));
}
__device__ __forceinline__ void mma16816(float* c, const uint32_t* a, const uint32_t* b) {
    asm volatile(
        "mma.sync.aligned.m16n8k16.row.col.f32.f16.f16.f32 "
        "{%0,%1,%2,%3}, {%4,%5,%6,%7}, {%8,%9}, {%0,%1,%2,%3};"
        : "+f"(c[0]), "+f"(c[1]), "+f"(c[2]), "+f"(c[3])
        : "r"(a[0]), "r"(a[1]), "r"(a[2]), "r"(a[3]), "r"(b[0]), "r"(b[1]));
}

__device__ __forceinline__ float gelu_tanh(float x) {
    float x3 = x * x * x;
    float t  = tanhf(0.7978845608028654f * (x + 0.044715f * x3));
    return 0.5f * x * (1.0f + t);
}
__device__ __forceinline__ uint32_t pack_h2(float a, float b) {
    __half2 h = __floats2half2_rn(a, b);
    return *reinterpret_cast<uint32_t*>(&h);
}

// ============================================================================
// HMMA GEMM: C[MT,NT tiles] = A[M,K] * B[N,K]^T   (fp16 K-major operands)
// MT=128: 256 thr, 8 warps 4Mx2N (warp 32 x NT/2).
// MT=256: 512 thr, 16 warps 4Mx4N (warp 64 x NT/4).
// BK=64 (4 ks steps), 3-stage cp.async, ONE __syncthreads per chunk.
// EPI: 0 = fp32 C = acc + bias?
//      1 = fp16 C16 = gelu(acc + bias)
//      6 = fp16 C16 = acc + bias?
//      9 = QKV route: hh<2 plain fp16; hh==2 V^T scatter
// ============================================================================
#define SPAD 72
#define STAGES 3

template <int MT, int NT, int EPI>
__global__ __launch_bounds__(MT * 2)
void hgemm(const __half* __restrict__ A, const __half* __restrict__ B,
           float* __restrict__ C, __half* __restrict__ C16,
           const float* __restrict__ bias,
           int K, int lda, int ldb, int ldc, int Hdim,
           long long aOB, long long aOH, long long bOB, long long bOH,
           long long cOB, long long cOH, long long biasOH)
{
    extern __shared__ __half smem[];

    constexpr int THREADS = MT * 2;
    constexpr int NWARP   = THREADS / 32;
    constexpr int WM      = MT / 4;          // 32 or 64
    constexpr int WN      = NT / (NWARP / 4);// NT/2 or NT/4
    constexpr int MI      = WM / 16;         // 2 or 4
    constexpr int NF      = WN / 8;          // 8 or 4

    const int tid = threadIdx.x, wid = tid >> 5, lane = tid & 31;
    const int wm = wid & 3, wn = wid >> 2;

    const int m0 = blockIdx.y * MT, n0 = blockIdx.x * NT;
    const int z = blockIdx.z, bb = z / Hdim, hh = z - bb * Hdim;
    A += (size_t)bb * aOB + (size_t)hh * aOH;
    B += (size_t)bb * bOB + (size_t)hh * bOH;
    if (bias) bias += (size_t)hh * biasOH;
    const long long coff = (long long)bb * cOB + (long long)hh * cOH;

    const uint32_t ABUF = (uint32_t)MT * SPAD * 2;
    const uint32_t BBUF = (uint32_t)NT * SPAD * 2;
    const uint32_t abase = smem_u32(smem);
    const uint32_t bbase = abase + STAGES * ABUF;

    const uint32_t a_off = (uint32_t)((wm * WM + (lane & 15)) * (SPAD * 2) + ((lane >> 4) * 8) * 2);
    const uint32_t b_off = (uint32_t)((wn * WN + (lane & 7) + ((lane >> 4) << 3)) * (SPAD * 2)
                                      + (((lane >> 3) & 1) * 8) * 2);

    float acc[MI][NF][4];
#pragma unroll
    for (int i = 0; i < MI; i++)
#pragma unroll
        for (int j = 0; j < NF; j++)
#pragma unroll
            for (int r = 0; r < 4; r++) acc[i][j][r] = 0.0f;

    const int nc = K >> 6;

    auto load_tile = [&](int c, int buf) {
        const __half* Ab = A + (size_t)m0 * lda + (size_t)c * 64;
#pragma unroll
        for (int it = 0; it < MT * 8 / THREADS; it++) {
            int lin = it * THREADS + tid;
            int row = lin >> 3, seg = lin & 7;
            cp16(abase + buf * ABUF + row * (SPAD * 2) + seg * 16,
                 Ab + (size_t)row * lda + seg * 8);
        }
        const __half* Bb = B + (size_t)n0 * ldb + (size_t)c * 64;
#pragma unroll
        for (int it = 0; it < NT * 8 / THREADS; it++) {
            int lin = it * THREADS + tid;
            int row = lin >> 3, seg = lin & 7;
            cp16(bbase + buf * BBUF + row * (SPAD * 2) + seg * 16,
                 Bb + (size_t)row * ldb + seg * 8);
        }
    };

#pragma unroll
    for (int s = 0; s < STAGES - 1; s++) {
        if (s < nc) load_tile(s, s);
        CP_COMMIT();
    }

    for (int c = 0; c < nc; c++) {
        CP_WAIT(STAGES - 2);
        __syncthreads();
        const int nxt = c + STAGES - 1;
        if (nxt < nc) load_tile(nxt, nxt % STAGES);
        CP_COMMIT();

        const int buf = c % STAGES;
        const uint32_t ab = abase + buf * ABUF + a_off;
        const uint32_t bbf = bbase + buf * BBUF + b_off;

#pragma unroll
        for (int ks = 0; ks < 4; ks++) {
            uint32_t af[MI][4];
#pragma unroll
            for (int mi = 0; mi < MI; mi++)
                ldm_x4(af[mi], ab + mi * 16 * (SPAD * 2) + ks * 32);
            uint32_t bf[NF][2];
#pragma unroll
            for (int p = 0; p < NF / 2; p++) {
                uint32_t t[4];
                ldm_x4(t, bbf + p * 16 * (SPAD * 2) + ks * 32);
                bf[2 * p][0] = t[0]; bf[2 * p][1] = t[1];
                bf[2 * p + 1][0] = t[2]; bf[2 * p + 1][1] = t[3];
            }
#pragma unroll
            for (int mi = 0; mi < MI; mi++)
#pragma unroll
                for (int nj = 0; nj < NF; nj++)
                    mma16816(acc[mi][nj], af[mi], bf[nj]);
        }
    }

#pragma unroll
    for (int mi = 0; mi < MI; mi++) {
#pragma unroll
        for (int nj = 0; nj < NF; nj++) {
            const int r0 = m0 + wm * WM + mi * 16 + (lane >> 2);
            const int cc = n0 + wn * WN + nj * 8 + (lane & 3) * 2;
#pragma unroll
            for (int h = 0; h < 2; h++) {
                const int row = r0 + h * 8;
                const float v0 = acc[mi][nj][2 * h + 0];
                const float v1 = acc[mi][nj][2 * h + 1];
                if (EPI == 0) {
                    float b0 = bias ? bias[cc] : 0.f, b1 = bias ? bias[cc + 1] : 0.f;
                    float2 o = make_float2(v0 + b0, v1 + b1);
                    *(float2*)(C + coff + (size_t)row * ldc + cc) = o;
                } else if (EPI == 1 || EPI == 6) {
                    float o0 = v0 + (bias ? bias[cc] : 0.f);
                    float o1 = v1 + (bias ? bias[cc + 1] : 0.f);
                    if (EPI == 1) { o0 = gelu_tanh(o0); o1 = gelu_tanh(o1); }
                    *(uint32_t*)(C16 + coff + (size_t)row * ldc + cc) = pack_h2(o0, o1);
                } else if (EPI == 9) {
                    float o0 = v0 + bias[cc];
                    float o1 = v1 + bias[cc + 1];
                    if (hh < 2) {
                        *(uint32_t*)(C16 + coff + (size_t)row * ldc + cc) = pack_h2(o0, o1);
                    } else {
                        const int b_ = row >> 11, s_ = row & 2047;
                        const int h0 = cc >> 6, d0 = cc & 63;
                        const int h1 = (cc + 1) >> 6, d1 = (cc + 1) & 63;
                        C16[coff + ((size_t)((b_ * Hc + h0) * DHc + d0)) * Sc + s_] = __float2half(o0);
                        C16[coff + ((size_t)((b_ * Hc + h1) * DHc + d1)) * Sc + s_] = __float2half(o1);
                    }
                }
            }
        }
    }
}

static const int SMEM_128 = STAGES * (128 + 128) * SPAD * 2;  // 110592
static const int SMEM_256 = STAGES * (256 + 128) * SPAD * 2;  // 165888

// ============================================================================
// FlashAttention-2 fused attention. Grid: (S/128 q-tiles, B*H).
// 256 threads = 8 warps; warp = 16 q rows (q-tile 128).
// KV tiles of 128, double-buffered cp.async. Mask fp16 [B,S,S].
// ============================================================================
#define SP1 72     // K/Q smem row stride (halves)
#define SP2 136    // V^T smem row stride (halves)
static const int SMEM_FA = 128 * SP1 * 2 + 2 * 128 * SP1 * 2 + 2 * 64 * SP2 * 2; // 90112

__global__ __launch_bounds__(256)
void flash_attn(const __half* __restrict__ Qg, const __half* __restrict__ Kg,
                const __half* __restrict__ Vt, const __half* __restrict__ Mk,
                __half* __restrict__ Og)
{
    extern __shared__ __half sm[];
    const int tid = threadIdx.x, wid = tid >> 5, lane = tid & 31;
    const int q0 = blockIdx.x * 128;
    const int z = blockIdx.y, bb = z >> 4, hh = z & 15;

    const uint32_t qs  = smem_u32(sm);
    const uint32_t ks0 = qs + 128 * SP1 * 2;
    const uint32_t KBUF = 128 * SP1 * 2;
    const uint32_t vs0 = ks0 + 2 * KBUF;
    const uint32_t VBUF = 64 * SP2 * 2;

    const __half* Qb = Qg + ((size_t)bb * Sc + q0) * Dc + hh * DHc;
    const __half* Kb = Kg + (size_t)bb * Sc * Dc + hh * DHc;
    const __half* Vb = Vt + ((size_t)(bb * Hc + hh)) * DHc * Sc;
    const __half* Mb = Mk + (size_t)bb * Sc * Sc;

    auto loadKV = [&](int t, int buf) {
        const __half* ksrc = Kb + (size_t)(t * 128) * Dc;
#pragma unroll
        for (int it = 0; it < 4; it++) {
            int lin = it * 256 + tid, row = lin >> 3, seg = lin & 7;
            cp16(ks0 + buf * KBUF + row * (SP1 * 2) + seg * 16, ksrc + (size_t)row * Dc + seg * 8);
        }
#pragma unroll
        for (int it = 0; it < 4; it++) {
            int lin = it * 256 + tid, row = lin >> 4, seg = lin & 15;
            cp16(vs0 + buf * VBUF + row * (SP2 * 2) + seg * 16,
                 Vb + (size_t)row * Sc + t * 128 + seg * 8);
        }
    };

    // prologue: Q + KV(0)
#pragma unroll
    for (int it = 0; it < 4; it++) {
        int lin = it * 256 + tid, row = lin >> 3, seg = lin & 7;
        cp16(qs + row * (SP1 * 2) + seg * 16, Qb + (size_t)row * Dc + seg * 8);
    }
    loadKV(0, 0);
    CP_COMMIT();

    const uint32_t a_q = qs + (wid * 16 + (lane & 15)) * (SP1 * 2) + ((lane >> 4) * 8) * 2;
    const uint32_t b_k = (uint32_t)(((lane & 7) + ((lane >> 4) << 3)) * (SP1 * 2) + (((lane >> 3) & 1) * 8) * 2);
    const uint32_t b_v = (uint32_t)(((lane & 7) + ((lane >> 4) << 3)) * (SP2 * 2) + (((lane >> 3) & 1) * 8) * 2);

    const int r = lane >> 2;
    const int qrow = q0 + wid * 16 + r;        // this thread's row (and +8)

    float o[8][4];
#pragma unroll
    for (int j = 0; j < 8; j++) { o[j][0] = o[j][1] = o[j][2] = o[j][3] = 0.f; }
    float rm0 = -1e30f, rm1 = -1e30f, rl0 = 0.f, rl1 = 0.f;

    for (int t = 0; t < Sc / 128; t++) {
        __syncthreads();                       // all warps done with compute t-1
        if (t + 1 < Sc / 128) loadKV(t + 1, (t + 1) & 1);
        CP_COMMIT();
        CP_WAIT(1);
        __syncthreads();

        const uint32_t kb = ks0 + (t & 1) * KBUF + b_k;
        const uint32_t vb = vs0 + (t & 1) * VBUF + b_v;

        // ---- S = Q K^T  (16 q rows x 128 k cols per warp)
        float s[16][4];
#pragma unroll
        for (int j = 0; j < 16; j++) { s[j][0] = s[j][1] = s[j][2] = s[j][3] = 0.f; }
#pragma unroll
        for (int ks = 0; ks < 4; ks++) {
            uint32_t af[4];
            ldm_x4(af, a_q + ks * 32);
#pragma unroll
            for (int p = 0; p < 8; p++) {
                uint32_t tt[4];
                ldm_x4(tt, kb + p * 16 * (SP1 * 2) + ks * 32);
                mma16816(s[2 * p], af, tt);
                mma16816(s[2 * p + 1], af, tt + 2);
            }
        }

        // ---- scale + mask + row max
        const __half* mr0 = Mb + (size_t)qrow * Sc + t * 128 + (lane & 3) * 2;
        const __half* mr1 = mr0 + 8 * Sc;
        float tm0 = -1e30f, tm1 = -1e30f;
#pragma unroll
        for (int j = 0; j < 16; j++) {
            float2 m0 = __half22float2(*(const __half2*)(mr0 + j * 8));
            float2 m1 = __half22float2(*(const __half2*)(mr1 + j * 8));
            s[j][0] = s[j][0] * 0.125f + m0.x;
            s[j][1] = s[j][1] * 0.125f + m0.y;
            s[j][2] = s[j][2] * 0.125f + m1.x;
            s[j][3] = s[j][3] * 0.125f + m1.y;
            tm0 = fmaxf(tm0, fmaxf(s[j][0], s[j][1]));
            tm1 = fmaxf(tm1, fmaxf(s[j][2], s[j][3]));
        }
#pragma unroll
        for (int off = 1; off <= 2; off <<= 1) {
            tm0 = fmaxf(tm0, __shfl_xor_sync(0xffffffffu, tm0, off));
            tm1 = fmaxf(tm1, __shfl_xor_sync(0xffffffffu, tm1, off));
        }
        const float mn0 = fmaxf(rm0, tm0), mn1 = fmaxf(rm1, tm1);
        const float cr0 = __expf(rm0 - mn0), cr1 = __expf(rm1 - mn1);
        rm0 = mn0; rm1 = mn1;

        // ---- exp + pack P
        uint32_t pk[16][2];
        float ps0 = 0.f, ps1 = 0.f;
#pragma unroll
        for (int j = 0; j < 16; j++) {
            float p0 = __expf(s[j][0] - mn0), p1 = __expf(s[j][1] - mn0);
            float p2 = __expf(s[j][2] - mn1), p3 = __expf(s[j][3] - mn1);
            ps0 += p0 + p1; ps1 += p2 + p3;
            pk[j][0] = pack_h2(p0, p1);
            pk[j][1] = pack_h2(p2, p3);
        }
#pragma unroll
        for (int off = 1; off <= 2; off <<= 1) {
            ps0 += __shfl_xor_sync(0xffffffffu, ps0, off);
            ps1 += __shfl_xor_sync(0xffffffffu, ps1, off);
        }
        rl0 = rl0 * cr0 + ps0;
        rl1 = rl1 * cr1 + ps1;

        // ---- rescale O
#pragma unroll
        for (int j = 0; j < 8; j++) {
            o[j][0] *= cr0; o[j][1] *= cr0;
            o[j][2] *= cr1; o[j][3] *= cr1;
        }

        // ---- O += P @ V
#pragma unroll
        for (int ks = 0; ks < 8; ks++) {
            uint32_t af[4] = { pk[2 * ks][0], pk[2 * ks][1], pk[2 * ks + 1][0], pk[2 * ks + 1][1] };
#pragma unroll
            for (int p = 0; p < 4; p++) {
                uint32_t tt[4];
                ldm_x4(tt, vb + p * 16 * (SP2 * 2) + ks * 32);
                mma16816(o[2 * p], af, tt);
                mma16816(o[2 * p + 1], af, tt + 2);
            }
        }
    }

    // ---- write O
    const float i0 = 1.0f / rl0, i1 = 1.0f / rl1;
    __half* or0 = Og + ((size_t)bb * Sc + qrow) * Dc + hh * DHc + (lane & 3) * 2;
    __half* or1 = or0 + 8 * Dc;
#pragma unroll
    for (int j = 0; j < 8; j++) {
        *(uint32_t*)(or0 + j * 8) = pack_h2(o[j][0] * i0, o[j][1] * i0);
        *(uint32_t*)(or1 + j * 8) = pack_h2(o[j][2] * i1, o[j][3] * i1);
    }
}

// ---------------- small kernels ----------------
__global__ void convpack(const float* __restrict__ s, __half* __restrict__ d,
                         const float* __restrict__ bq, const float* __restrict__ bk,
                         const float* __restrict__ bv, float* __restrict__ qkvb)
{
    int i = blockIdx.x * blockDim.x + threadIdx.x;
    if (i < NTOK * Dc / 4) {
        float4 v = ((const float4*)s)[i];
        uint2 u;
        u.x = pack_h2(v.x, v.y); u.y = pack_h2(v.z, v.w);
        ((uint2*)d)[i] = u;
    }
    if (i < Dc) { qkvb[i] = bq[i]; qkvb[Dc + i] = bk[i]; qkvb[2 * Dc + i] = bv[i]; }
}

__global__ void maskconv(const float* __restrict__ s, __half* __restrict__ d)
{
    int i = blockIdx.x * blockDim.x + threadIdx.x;
    float4 v = ((const float4*)s)[i];
    uint2 u;
    u.x = pack_h2(v.x, v.y); u.y = pack_h2(v.z, v.w);
    ((uint2*)d)[i] = u;
}

__global__ void tconv_all(const float* __restrict__ wq, const float* __restrict__ wk,
                          const float* __restrict__ wv, const float* __restrict__ wo,
                          const float* __restrict__ w1, const float* __restrict__ w2,
                          __half* __restrict__ dstbase)
{
    __shared__ float t[32][33];
    int b = blockIdx.x;
    const float* src; __half* dst; int K, N;
    if (b < 4096) {
        int m = b >> 10; b &= 1023;
        src = (m == 0) ? wq : (m == 1) ? wk : (m == 2) ? wv : wo;
        dst = dstbase + (size_t)m * Dc * Dc; K = Dc; N = Dc;
    } else if (b < 4096 + 32768) {
        b -= 4096; int e = b >> 12; b &= 4095;
        src = w1 + (size_t)e * Dc * Fc;
        dst = dstbase + 4 * (size_t)Dc * Dc + (size_t)e * Dc * Fc; K = Dc; N = Fc;
    } else {
        b -= 36864; int e = b >> 12; b &= 4095;
        src = w2 + (size_t)e * Fc * Dc;
        dst = dstbase + 4 * (size_t)Dc * Dc + (size_t)Ec * Dc * Fc + (size_t)e * Fc * Dc;
        K = Fc; N = Dc;
    }
    const int ntx = N / 32;
    const int k0 = (b / ntx) * 32, n0 = (b % ntx) * 32;
    const int x = threadIdx.x, y = threadIdx.y;
#pragma unroll
    for (int i = 0; i < 32; i += 8)
        t[y + i][x] = src[(size_t)(k0 + y + i) * N + n0 + x];
    __syncthreads();
#pragma unroll
    for (int i = 0; i < 32; i += 8)
        dst[(size_t)(n0 + y + i) * K + k0 + x] = __float2half(t[x][y + i]);
}

__global__ void ln_residual(const float* __restrict__ x, const float* __restrict__ r,
                            const float* __restrict__ g, const float* __restrict__ b,
                            float* __restrict__ out, __half* __restrict__ out16)
{
    __shared__ float red[256];
    const size_t base = (size_t)blockIdx.x * Dc;
    const int tid = threadIdx.x;
    float v[4]; float s = 0.f;
#pragma unroll
    for (int i = 0; i < 4; i++) { const int c = tid + i * 256; v[i] = x[base + c] + r[base + c]; s += v[i]; }
    red[tid] = s; __syncthreads();
    for (int st = 128; st > 0; st >>= 1) { if (tid < st) red[tid] += red[tid + st]; __syncthreads(); }
    const float mean = red[0] * (1.0f / Dc); __syncthreads();
    float ss = 0.f;
#pragma unroll
    for (int i = 0; i < 4; i++) { const float d = v[i] - mean; ss += d * d; }
    red[tid] = ss; __syncthreads();
    for (int st = 128; st > 0; st >>= 1) { if (tid < st) red[tid] += red[tid + st]; __syncthreads(); }
    const float rstd = rsqrtf(red[0] * (1.0f / Dc) + LN_EPS);
#pragma unroll
    for (int i = 0; i < 4; i++) {
        const int c = tid + i * 256;
        const float o = (v[i] - mean) * rstd * g[c] + b[c];
        out[base + c] = o;
        if (out16) out16[base + c] = __float2half(o);
    }
}

__global__ void gate_kernel(const float* __restrict__ x, const float* __restrict__ gw,
                            const float* __restrict__ gb,
                            float* __restrict__ gate, float* __restrict__ gate_out)
{
    const int m = blockIdx.x;
    const int tid = threadIdx.x;
    const int wid = tid >> 5, lane = tid & 31;
    __shared__ float logits[Ec];
    float s = 0.f;
    const float* xr = x + (size_t)m * Dc;
    for (int d = lane; d < Dc; d += 32) s += xr[d] * gw[d * Ec + wid];
#pragma unroll
    for (int o = 16; o > 0; o >>= 1) s += __shfl_down_sync(0xffffffffu, s, o);
    if (lane == 0) logits[wid] = s + gb[wid];
    __syncthreads();
    if (tid == 0) {
        float mx = logits[0];
#pragma unroll
        for (int e = 1; e < Ec; e++) mx = fmaxf(mx, logits[e]);
        float p[Ec]; float sum = 0.f;
#pragma unroll
        for (int e = 0; e < Ec; e++) { p[e] = expf(logits[e] - mx); sum += p[e]; }
        const float inv = 1.0f / sum;
#pragma unroll
        for (int e = 0; e < Ec; e++) {
            const float pv = p[e] * inv;
            gate[(size_t)m * Ec + e] = pv;
            if (gate_out) gate_out[(size_t)m * Ec + e] = pv;
        }
    }
}

__global__ void moe_reduce(const __half* __restrict__ part, const float* __restrict__ gate,
                           float* __restrict__ outm)
{
    const int i = blockIdx.x * blockDim.x + threadIdx.x;
    const int m = i / (Dc / 2);
    const float* gm = gate + (size_t)m * Ec;
    float2 s = make_float2(0.f, 0.f);
#pragma unroll
    for (int e = 0; e < Ec; e++) {
        float2 f = __half22float2(((const __half2*)part)[(size_t)e * (NTOK * Dc / 2) + i]);
        const float g = gm[e];
        s.x += g * f.x; s.y += g * f.y;
    }
    ((float2*)outm)[i] = s;
}

// ---------------- launch ----------------------------------------------------
extern "C" void kernel_launch(void* const* d_in, const int* in_sizes, int n_in,
                              void* d_out, int out_size)
{
    const float* hidden = (const float*)d_in[0];
    const float* mask   = (const float*)d_in[1];
    const float* wq = (const float*)d_in[2];  const float* bq = (const float*)d_in[3];
    const float* wk = (const float*)d_in[4];  const float* bk = (const float*)d_in[5];
    const float* wv = (const float*)d_in[6];  const float* bv = (const float*)d_in[7];
    const float* wo = (const float*)d_in[8];  const float* bo = (const float*)d_in[9];
    const float* ln1_g = (const float*)d_in[10]; const float* ln1_b = (const float*)d_in[11];
    const float* gate_w = (const float*)d_in[12]; const float* gate_b = (const float*)d_in[13];
    const float* w1 = (const float*)d_in[14]; const float* b1 = (const float*)d_in[15];
    const float* w2 = (const float*)d_in[16]; const float* b2 = (const float*)d_in[17];
    const float* ln2_g = (const float*)d_in[18]; const float* ln2_b = (const float*)d_in[19];

    float* f32 = nullptr;  __half* f16 = nullptr;
    cudaGetSymbolAddress((void**)&f32, g_f32);
    cudaGetSymbolAddress((void**)&f16, g_f16);

    float*  attn   = f32 + F_ATTN;
    float*  inter  = f32 + F_INT;
    float*  moe    = f32 + F_MOE;
    float*  gate   = f32 + F_GATE;
    float*  qkvb   = f32 + F_QKVB;
    __half* hid16  = f16 + H_HID;
    __half* q16    = f16 + H_Q;
    __half* k16    = f16 + H_K;
    __half* vT16   = f16 + H_VT;
    __half* ctx16  = f16 + H_CTX;
    __half* int16_ = f16 + H_INT;
    __half* msk16  = f16 + H_MSK;
    __half* h16    = f16 + H_HB;
    __half* p2     = f16 + H_P2;
    __half* wqT = f16 + H_WQ;
    __half* woT = f16 + H_WQ + 3 * (size_t)Dc * Dc;
    __half* w1T = f16 + H_W1; __half* w2T = f16 + H_W2;

    float* out = (float*)d_out;
    float* gate_out = nullptr;
    if ((size_t)out_size >= (size_t)NTOK * Dc + (size_t)NTOK * Ec)
        gate_out = out + (size_t)NTOK * Dc;

    cudaFuncSetAttribute(hgemm<128,128,0>, cudaFuncAttributeMaxDynamicSharedMemorySize, SMEM_128);
    cudaFuncSetAttribute(hgemm<128,128,9>, cudaFuncAttributeMaxDynamicSharedMemorySize, SMEM_128);
    cudaFuncSetAttribute(hgemm<256,128,1>, cudaFuncAttributeMaxDynamicSharedMemorySize, SMEM_256);
    cudaFuncSetAttribute(hgemm<256,128,6>, cudaFuncAttributeMaxDynamicSharedMemorySize, SMEM_256);
    cudaFuncSetAttribute(flash_attn,       cudaFuncAttributeMaxDynamicSharedMemorySize, SMEM_FA);

    const dim3 blk(256);
    const dim3 blk5(512);
    const dim3 tblk(32, 8);

    // 0) hidden conversion + bias pack
    convpack<<<NTOK * Dc / 4 / 256, 256>>>(hidden, hid16, bq, bk, bv, qkvb);
    // 1) mask -> fp16
    maskconv<<<(int)((size_t)Bc * Sc * Sc / 4 / 256), 256>>>(mask, msk16);
    // 2) all weight transposes
    tconv_all<<<69632, tblk>>>(wq, wk, wv, wo, w1, w2, wqT);

    // 3) fused Q/K/V projection (z = 0,1,2 -> q16, k16, vT scatter)
    {
        dim3 grid(Dc / 128, NTOK / 128, 3);
        hgemm<128,128,9><<<grid, blk, SMEM_128>>>(hid16, wqT, nullptr, q16, qkvb,
            Dc, Dc, Dc, Dc, 3,
            0, 0,
            0, (long long)Dc * Dc,
            0, (long long)NTOK * Dc,
            (long long)Dc);
    }

    // 4) fused attention -> ctx16
    {
        dim3 grid(Sc / 128, Bc * Hc);
        flash_attn<<<grid, 256, SMEM_FA>>>(q16, k16, vT16, msk16, ctx16);
    }

    // 5) output projection -> fp32 attn
    {
        dim3 grid(Dc / 128, NTOK / 128, 1);
        hgemm<128,128,0><<<grid, blk, SMEM_128>>>(ctx16, woT, attn, nullptr, bo,
            Dc, Dc, Dc, Dc, 1, 0,0,0,0,0,0,0);
    }

    // 6) inter = LN1(attn + hidden)
    ln_residual<<<NTOK, 256>>>(attn, hidden, ln1_g, ln1_b, inter, int16_);

    // 7) gate
    gate_kernel<<<NTOK, 256>>>(inter, gate_w, gate_b, gate, gate_out);

    // 8-9) MoE batched across experts (z = expert), 256x128 tiles
    {
        dim3 gh(Fc / 128, NTOK / 256, Ec);
        hgemm<256,128,1><<<gh, blk5, SMEM_256>>>(int16_, w1T, nullptr, h16, b1,
            Dc, Dc, Dc, Fc, Ec,
            0, 0,
            0, (long long)Dc * Fc,
            0, (long long)NTOK * Fc,
            (long long)Fc);

        dim3 gy(Dc / 128, NTOK / 256, Ec);
        hgemm<256,128,6><<<gy, blk5, SMEM_256>>>(h16, w2T, nullptr, p2, b2,
            Fc, Fc, Fc, Dc, Ec,
            0, (long long)NTOK * Fc,
            0, (long long)Fc * Dc,
            0, (long long)NTOK * Dc,
            (long long)Dc);
    }

    // 10) gate-weighted reduce
    moe_reduce<<<NTOK * Dc / 2 / 256, 256>>>(p2, gate, moe);

    // 11) output = LN2(moe + inter)
    ln_residual<<<NTOK, 256>>>(moe, inter, ln2_g, ln2_b, out, nullptr);
}

// round 10
// speedup vs baseline: 1.0231x; 1.0231x over previous
#include <cuda_runtime.h>
#include <cuda_fp16.h>
#include <math.h>
#include <stdint.h>

// ---------------- problem constants ----------------
#define Bc 2
#define Sc 2048
#define Dc 1024
#define Hc 16
#define DHc 64
#define Fc 4096
#define Ec 8
#define NTOK (Bc * Sc)
#define LN_EPS 1e-6f

// ---------------- fp32 scratch ----------------
static const size_t F_ATTN  = 0;
static const size_t F_INT   = F_ATTN + (size_t)NTOK * Dc;
static const size_t F_MOE   = F_INT  + (size_t)NTOK * Dc;
static const size_t F_GATE  = F_MOE  + (size_t)NTOK * Dc;
static const size_t F_QKVB  = F_GATE + (size_t)NTOK * Ec;
static const size_t F_TOTAL = F_QKVB + 3 * (size_t)Dc;
__device__ float g_f32[F_TOTAL];

// ---------------- fp16 scratch ----------------
static const size_t H_HID  = 0;
static const size_t H_Q    = H_HID + (size_t)NTOK * Dc;
static const size_t H_K    = H_Q   + (size_t)NTOK * Dc;     // contiguous with Q
static const size_t H_VT   = H_K   + (size_t)NTOK * Dc;     // [B,H,DH,S]
static const size_t H_CTX  = H_VT  + (size_t)NTOK * Dc;
static const size_t H_INT  = H_CTX + (size_t)NTOK * Dc;
static const size_t H_MSK  = H_INT + (size_t)NTOK * Dc;                 // fp16 mask [B,S,S]
static const size_t H_HB   = H_MSK + (size_t)Bc * Sc * Sc;
static const size_t H_P2   = H_HB  + (size_t)Ec * NTOK * Fc;
static const size_t H_WQ   = H_P2  + (size_t)Ec * NTOK * Dc;
static const size_t H_W1   = H_WQ  + 4 * (size_t)Dc * Dc;   // [E][N=F,K=D]
static const size_t H_W2   = H_W1  + (size_t)Ec * Dc * Fc;  // [E][N=D,K=F]
static const size_t H_TOTAL= H_W2  + (size_t)Ec * Fc * Dc;
__device__ __half g_f16[H_TOTAL];

// ---------------- PTX helpers ----------------
__device__ __forceinline__ uint32_t smem_u32(const void* p) {
    uint32_t a;
    asm("{ .reg .u64 t; cvta.to.shared.u64 t, %1; cvt.u32.u64 %0, t; }" : "=r"(a) : "l"(p));
    return a;
}
__device__ __forceinline__ void cp16(uint32_t s, const void* g) {
    asm volatile("cp.async.cg.shared.global [%0], [%1], 16;" :: "r"(s), "l"(g));
}
#define CP_COMMIT() asm volatile("cp.async.commit_group;" ::: "memory")
#define CP_WAIT(n)  asm volatile("cp.async.wait_group %0;" :: "n"(n) : "memory")

__device__ __forceinline__ void ldm_x4(uint32_t* r, uint32_t addr) {
    asm volatile("ldmatrix.sync.aligned.m8n8.x4.shared.b16 {%0,%1,%2,%3}, [%4];"
        : "=r"(r[0]), "=r"(r[1]), "=r"(r[2]), "=r"(r[3]) : "r"(addr));
}
__device__ __forceinline__ void mma16816(float* c, const uint32_t* a, const uint32_t* b) {
    asm volatile(
        "mma.sync.aligned.m16n8k16.row.col.f32.f16.f16.f32 "
        "{%0,%1,%2,%3}, {%4,%5,%6,%7}, {%8,%9}, {%0,%1,%2,%3};"
        : "+f"(c[0]), "+f"(c[1]), "+f"(c[2]), "+f"(c[3])
        : "r"(a[0]), "r"(a[1]), "r"(a[2]), "r"(a[3]), "r"(b[0]), "r"(b[1]));
}

__device__ __forceinline__ float gelu_tanh(float x) {
    float x3 = x * x * x;
    float t  = tanhf(0.7978845608028654f * (x + 0.044715f * x3));
    return 0.5f * x * (1.0f + t);
}
__device__ __forceinline__ uint32_t pack_h2(float a, float b) {
    __half2 h = __floats2half2_rn(a, b);
    return *reinterpret_cast<uint32_t*>(&h);
}

// ============================================================================
// HMMA GEMM: C[128,NT tiles] = A[M,K] * B[N,K]^T   (fp16 K-major operands)
// 256 threads = 8 warps (4M x 2N), warp tile 32 x NT/2.
// BK=64 (4 ks steps), ST-stage cp.async pipeline (loop overlaps load(c+ST-1)
// with compute(c)), ONE __syncthreads per chunk.
// MINB = min blocks/SM hint: 3 for the slim NT=64 kernels (forces <=85 regs),
// 2 for NT=128 (forces <=128 regs).
// EPI: 0 = fp32 C = acc + bias?
//      1 = fp16 C16 = gelu(acc + bias)
//      6 = fp16 C16 = acc + bias?
//      9 = QKV route: hh<2 plain fp16; hh==2 V^T scatter
// ============================================================================
#define SPAD 72

template <int NT, int ST, int MINB, int EPI>
__global__ __launch_bounds__(256, MINB)
void hgemm(const __half* __restrict__ A, const __half* __restrict__ B,
           float* __restrict__ C, __half* __restrict__ C16,
           const float* __restrict__ bias,
           int K, int lda, int ldb, int ldc, int Hdim,
           long long aOB, long long aOH, long long bOB, long long bOH,
           long long cOB, long long cOH, long long biasOH)
{
    extern __shared__ __half smem[];

    const int tid = threadIdx.x, wid = tid >> 5, lane = tid & 31;
    const int wm = wid & 3, wn = wid >> 2;
    constexpr int WN = NT / 2;
    constexpr int NF = WN / 8;

    const int m0 = blockIdx.y * 128, n0 = blockIdx.x * NT;
    const int z = blockIdx.z, bb = z / Hdim, hh = z - bb * Hdim;
    A += (size_t)bb * aOB + (size_t)hh * aOH;
    B += (size_t)bb * bOB + (size_t)hh * bOH;
    if (bias) bias += (size_t)hh * biasOH;
    const long long coff = (long long)bb * cOB + (long long)hh * cOH;

    const uint32_t ABUF = 128 * SPAD * 2;
    const uint32_t BBUF = (uint32_t)NT * SPAD * 2;
    const uint32_t abase = smem_u32(smem);
    const uint32_t bbase = abase + ST * ABUF;

    const uint32_t a_off = (uint32_t)((wm * 32 + (lane & 15)) * (SPAD * 2) + ((lane >> 4) * 8) * 2);
    const uint32_t b_off = (uint32_t)((wn * WN + (lane & 7) + ((lane >> 4) << 3)) * (SPAD * 2)
                                      + (((lane >> 3) & 1) * 8) * 2);

    float acc[2][NF][4];
#pragma unroll
    for (int i = 0; i < 2; i++)
#pragma unroll
        for (int j = 0; j < NF; j++)
#pragma unroll
            for (int r = 0; r < 4; r++) acc[i][j][r] = 0.0f;

    const int nc = K >> 6;

    auto load_tile = [&](int c, int buf) {
        const __half* Ab = A + (size_t)m0 * lda + (size_t)c * 64;
#pragma unroll
        for (int it = 0; it < 4; it++) {
            int lin = it * 256 + tid;
            int row = lin >> 3, seg = lin & 7;
            cp16(abase + buf * ABUF + row * (SPAD * 2) + seg * 16,
                 Ab + (size_t)row * lda + seg * 8);
        }
        const __half* Bb = B + (size_t)n0 * ldb + (size_t)c * 64;
#pragma unroll
        for (int it = 0; it < NT / 32; it++) {
            int lin = it * 256 + tid;
            int row = lin >> 3, seg = lin & 7;
            cp16(bbase + buf * BBUF + row * (SPAD * 2) + seg * 16,
                 Bb + (size_t)row * ldb + seg * 8);
        }
    };

#pragma unroll
    for (int s = 0; s < ST - 1; s++) {
        if (s < nc) load_tile(s, s);
        CP_COMMIT();
    }

    for (int c = 0; c < nc; c++) {
        CP_WAIT(ST - 2);
        __syncthreads();
        const int nxt = c + ST - 1;
        if (nxt < nc) load_tile(nxt, nxt % ST);
        CP_COMMIT();

        const int buf = c % ST;
        const uint32_t ab = abase + buf * ABUF + a_off;
        const uint32_t bbf = bbase + buf * BBUF + b_off;

#pragma unroll
        for (int ks = 0; ks < 4; ks++) {
            uint32_t af[2][4];
#pragma unroll
            for (int mi = 0; mi < 2; mi++)
                ldm_x4(af[mi], ab + mi * 16 * (SPAD * 2) + ks * 32);
            uint32_t bf[NF][2];
#pragma unroll
            for (int p = 0; p < NF / 2; p++) {
                uint32_t t[4];
                ldm_x4(t, bbf + p * 16 * (SPAD * 2) + ks * 32);
                bf[2 * p][0] = t[0]; bf[2 * p][1] = t[1];
                bf[2 * p + 1][0] = t[2]; bf[2 * p + 1][1] = t[3];
            }
#pragma unroll
            for (int mi = 0; mi < 2; mi++)
#pragma unroll
                for (int nj = 0; nj < NF; nj++)
                    mma16816(acc[mi][nj], af[mi], bf[nj]);
        }
    }

#pragma unroll
    for (int mi = 0; mi < 2; mi++) {
#pragma unroll
        for (int nj = 0; nj < NF; nj++) {
            const int r0 = m0 + wm * 32 + mi * 16 + (lane >> 2);
            const int cc = n0 + wn * WN + nj * 8 + (lane & 3) * 2;
#pragma unroll
            for (int h = 0; h < 2; h++) {
                const int row = r0 + h * 8;
                const float v0 = acc[mi][nj][2 * h + 0];
                const float v1 = acc[mi][nj][2 * h + 1];
                if (EPI == 0) {
                    float b0 = bias ? bias[cc] : 0.f, b1 = bias ? bias[cc + 1] : 0.f;
                    float2 o = make_float2(v0 + b0, v1 + b1);
                    *(float2*)(C + coff + (size_t)row * ldc + cc) = o;
                } else if (EPI == 1 || EPI == 6) {
                    float o0 = v0 + (bias ? bias[cc] : 0.f);
                    float o1 = v1 + (bias ? bias[cc + 1] : 0.f);
                    if (EPI == 1) { o0 = gelu_tanh(o0); o1 = gelu_tanh(o1); }
                    *(uint32_t*)(C16 + coff + (size_t)row * ldc + cc) = pack_h2(o0, o1);
                } else if (EPI == 9) {
                    float o0 = v0 + bias[cc];
                    float o1 = v1 + bias[cc + 1];
                    if (hh < 2) {
                        *(uint32_t*)(C16 + coff + (size_t)row * ldc + cc) = pack_h2(o0, o1);
                    } else {
                        const int b_ = row >> 11, s_ = row & 2047;
                        const int h0 = cc >> 6, d0 = cc & 63;
                        const int h1 = (cc + 1) >> 6, d1 = (cc + 1) & 63;
                        C16[coff + ((size_t)((b_ * Hc + h0) * DHc + d0)) * Sc + s_] = __float2half(o0);
                        C16[coff + ((size_t)((b_ * Hc + h1) * DHc + d1)) * Sc + s_] = __float2half(o1);
                    }
                }
            }
        }
    }
}

static const int SMEM_128_S3 = 3 * (128 + 128) * SPAD * 2;  // 110592
static const int SMEM_64_S2  = 2 * (128 + 64) * SPAD * 2;   // 55296

// ============================================================================
// FlashAttention-2 fused attention (R8 version, unchanged).
// Grid: (S/64 q-tiles, B*H). 128 threads = 4 warps; warp = 16 q rows.
// ============================================================================
#define SP1 72     // K/Q smem row stride (halves)
#define SP2 136    // V^T smem row stride (halves)
static const int SMEM_FA = 64 * SP1 * 2 + 2 * 128 * SP1 * 2 + 2 * 64 * SP2 * 2; // 80896

__global__ __launch_bounds__(128)
void flash_attn(const __half* __restrict__ Qg, const __half* __restrict__ Kg,
                const __half* __restrict__ Vt, const __half* __restrict__ Mk,
                __half* __restrict__ Og)
{
    extern __shared__ __half sm[];
    const int tid = threadIdx.x, wid = tid >> 5, lane = tid & 31;
    const int q0 = blockIdx.x * 64;
    const int z = blockIdx.y, bb = z >> 4, hh = z & 15;

    const uint32_t qs  = smem_u32(sm);
    const uint32_t ks0 = qs + 64 * SP1 * 2;
    const uint32_t KBUF = 128 * SP1 * 2;
    const uint32_t vs0 = ks0 + 2 * KBUF;
    const uint32_t VBUF = 64 * SP2 * 2;

    const __half* Qb = Qg + ((size_t)bb * Sc + q0) * Dc + hh * DHc;
    const __half* Kb = Kg + (size_t)bb * Sc * Dc + hh * DHc;
    const __half* Vb = Vt + ((size_t)(bb * Hc + hh)) * DHc * Sc;
    const __half* Mb = Mk + (size_t)bb * Sc * Sc;

    auto loadKV = [&](int t, int buf) {
        const __half* ksrc = Kb + (size_t)(t * 128) * Dc;
#pragma unroll
        for (int it = 0; it < 8; it++) {
            int lin = it * 128 + tid, row = lin >> 3, seg = lin & 7;
            cp16(ks0 + buf * KBUF + row * (SP1 * 2) + seg * 16, ksrc + (size_t)row * Dc + seg * 8);
        }
#pragma unroll
        for (int it = 0; it < 8; it++) {
            int lin = it * 128 + tid, row = lin >> 4, seg = lin & 15;
            cp16(vs0 + buf * VBUF + row * (SP2 * 2) + seg * 16,
                 Vb + (size_t)row * Sc + t * 128 + seg * 8);
        }
    };

    // prologue: Q + KV(0)
#pragma unroll
    for (int it = 0; it < 4; it++) {
        int lin = it * 128 + tid, row = lin >> 3, seg = lin & 7;
        cp16(qs + row * (SP1 * 2) + seg * 16, Qb + (size_t)row * Dc + seg * 8);
    }
    loadKV(0, 0);
    CP_COMMIT();

    const uint32_t a_q = qs + (wid * 16 + (lane & 15)) * (SP1 * 2) + ((lane >> 4) * 8) * 2;
    const uint32_t b_k = (uint32_t)(((lane & 7) + ((lane >> 4) << 3)) * (SP1 * 2) + (((lane >> 3) & 1) * 8) * 2);
    const uint32_t b_v = (uint32_t)(((lane & 7) + ((lane >> 4) << 3)) * (SP2 * 2) + (((lane >> 3) & 1) * 8) * 2);

    const int r = lane >> 2;
    const int qrow = q0 + wid * 16 + r;

    float o[8][4];
#pragma unroll
    for (int j = 0; j < 8; j++) { o[j][0] = o[j][1] = o[j][2] = o[j][3] = 0.f; }
    float rm0 = -1e30f, rm1 = -1e30f, rl0 = 0.f, rl1 = 0.f;

    for (int t = 0; t < Sc / 128; t++) {
        __syncthreads();
        if (t + 1 < Sc / 128) loadKV(t + 1, (t + 1) & 1);
        CP_COMMIT();
        CP_WAIT(1);
        __syncthreads();

        const uint32_t kb = ks0 + (t & 1) * KBUF + b_k;
        const uint32_t vb = vs0 + (t & 1) * VBUF + b_v;

        // ---- S = Q K^T
        float s[16][4];
#pragma unroll
        for (int j = 0; j < 16; j++) { s[j][0] = s[j][1] = s[j][2] = s[j][3] = 0.f; }
#pragma unroll
        for (int ks = 0; ks < 4; ks++) {
            uint32_t af[4];
            ldm_x4(af, a_q + ks * 32);
#pragma unroll
            for (int p = 0; p < 8; p++) {
                uint32_t tt[4];
                ldm_x4(tt, kb + p * 16 * (SP1 * 2) + ks * 32);
                mma16816(s[2 * p], af, tt);
                mma16816(s[2 * p + 1], af, tt + 2);
            }
        }

        // ---- scale + mask + row max
        const __half* mr0 = Mb + (size_t)qrow * Sc + t * 128 + (lane & 3) * 2;
        const __half* mr1 = mr0 + 8 * Sc;
        float tm0 = -1e30f, tm1 = -1e30f;
#pragma unroll
        for (int j = 0; j < 16; j++) {
            float2 m0 = __half22float2(*(const __half2*)(mr0 + j * 8));
            float2 m1 = __half22float2(*(const __half2*)(mr1 + j * 8));
            s[j][0] = s[j][0] * 0.125f + m0.x;
            s[j][1] = s[j][1] * 0.125f + m0.y;
            s[j][2] = s[j][2] * 0.125f + m1.x;
            s[j][3] = s[j][3] * 0.125f + m1.y;
            tm0 = fmaxf(tm0, fmaxf(s[j][0], s[j][1]));
            tm1 = fmaxf(tm1, fmaxf(s[j][2], s[j][3]));
        }
#pragma unroll
        for (int off = 1; off <= 2; off <<= 1) {
            tm0 = fmaxf(tm0, __shfl_xor_sync(0xffffffffu, tm0, off));
            tm1 = fmaxf(tm1, __shfl_xor_sync(0xffffffffu, tm1, off));
        }
        const float mn0 = fmaxf(rm0, tm0), mn1 = fmaxf(rm1, tm1);
        const float cr0 = __expf(rm0 - mn0), cr1 = __expf(rm1 - mn1);
        rm0 = mn0; rm1 = mn1;

        // ---- exp + pack P
        uint32_t pk[16][2];
        float ps0 = 0.f, ps1 = 0.f;
#pragma unroll
        for (int j = 0; j < 16; j++) {
            float p0 = __expf(s[j][0] - mn0), p1 = __expf(s[j][1] - mn0);
            float p2 = __expf(s[j][2] - mn1), p3 = __expf(s[j][3] - mn1);
            ps0 += p0 + p1; ps1 += p2 + p3;
            pk[j][0] = pack_h2(p0, p1);
            pk[j][1] = pack_h2(p2, p3);
        }
#pragma unroll
        for (int off = 1; off <= 2; off <<= 1) {
            ps0 += __shfl_xor_sync(0xffffffffu, ps0, off);
            ps1 += __shfl_xor_sync(0xffffffffu, ps1, off);
        }
        rl0 = rl0 * cr0 + ps0;
        rl1 = rl1 * cr1 + ps1;

        // ---- rescale O
#pragma unroll
        for (int j = 0; j < 8; j++) {
            o[j][0] *= cr0; o[j][1] *= cr0;
            o[j][2] *= cr1; o[j][3] *= cr1;
        }

        // ---- O += P @ V
#pragma unroll
        for (int ks = 0; ks < 8; ks++) {
            uint32_t af[4] = { pk[2 * ks][0], pk[2 * ks][1], pk[2 * ks + 1][0], pk[2 * ks + 1][1] };
#pragma unroll
            for (int p = 0; p < 4; p++) {
                uint32_t tt[4];
                ldm_x4(tt, vb + p * 16 * (SP2 * 2) + ks * 32);
                mma16816(o[2 * p], af, tt);
                mma16816(o[2 * p + 1], af, tt + 2);
            }
        }
    }

    // ---- write O
    const float i0 = 1.0f / rl0, i1 = 1.0f / rl1;
    __half* or0 = Og + ((size_t)bb * Sc + qrow) * Dc + hh * DHc + (lane & 3) * 2;
    __half* or1 = or0 + 8 * Dc;
#pragma unroll
    for (int j = 0; j < 8; j++) {
        *(uint32_t*)(or0 + j * 8) = pack_h2(o[j][0] * i0, o[j][1] * i0);
        *(uint32_t*)(or1 + j * 8) = pack_h2(o[j][2] * i1, o[j][3] * i1);
    }
}

// ---------------- small kernels ----------------
__global__ void convpack(const float* __restrict__ s, __half* __restrict__ d,
                         const float* __restrict__ bq, const float* __restrict__ bk,
                         const float* __restrict__ bv, float* __restrict__ qkvb)
{
    int i = blockIdx.x * blockDim.x + threadIdx.x;
    if (i < NTOK * Dc / 4) {
        float4 v = ((const float4*)s)[i];
        uint2 u;
        u.x = pack_h2(v.x, v.y); u.y = pack_h2(v.z, v.w);
        ((uint2*)d)[i] = u;
    }
    if (i < Dc) { qkvb[i] = bq[i]; qkvb[Dc + i] = bk[i]; qkvb[2 * Dc + i] = bv[i]; }
}

__global__ void maskconv(const float* __restrict__ s, __half* __restrict__ d)
{
    int i = blockIdx.x * blockDim.x + threadIdx.x;
    float4 v = ((const float4*)s)[i];
    uint2 u;
    u.x = pack_h2(v.x, v.y); u.y = pack_h2(v.z, v.w);
    ((uint2*)d)[i] = u;
}

__global__ void tconv_all(const float* __restrict__ wq, const float* __restrict__ wk,
                          const float* __restrict__ wv, const float* __restrict__ wo,
                          const float* __restrict__ w1, const float* __restrict__ w2,
                          __half* __restrict__ dstbase)
{
    __shared__ float t[32][33];
    int b = blockIdx.x;
    const float* src; __half* dst; int K, N;
    if (b < 4096) {
        int m = b >> 10; b &= 1023;
        src = (m == 0) ? wq : (m == 1) ? wk : (m == 2) ? wv : wo;
        dst = dstbase + (size_t)m * Dc * Dc; K = Dc; N = Dc;
    } else if (b < 4096 + 32768) {
        b -= 4096; int e = b >> 12; b &= 4095;
        src = w1 + (size_t)e * Dc * Fc;
        dst = dstbase + 4 * (size_t)Dc * Dc + (size_t)e * Dc * Fc; K = Dc; N = Fc;
    } else {
        b -= 36864; int e = b >> 12; b &= 4095;
        src = w2 + (size_t)e * Fc * Dc;
        dst = dstbase + 4 * (size_t)Dc * Dc + (size_t)Ec * Dc * Fc + (size_t)e * Fc * Dc;
        K = Fc; N = Dc;
    }
    const int ntx = N / 32;
    const int k0 = (b / ntx) * 32, n0 = (b % ntx) * 32;
    const int x = threadIdx.x, y = threadIdx.y;
#pragma unroll
    for (int i = 0; i < 32; i += 8)
        t[y + i][x] = src[(size_t)(k0 + y + i) * N + n0 + x];
    __syncthreads();
#pragma unroll
    for (int i = 0; i < 32; i += 8)
        dst[(size_t)(n0 + y + i) * K + k0 + x] = __float2half(t[x][y + i]);
}

__global__ void ln_residual(const float* __restrict__ x, const float* __restrict__ r,
                            const float* __restrict__ g, const float* __restrict__ b,
                            float* __restrict__ out, __half* __restrict__ out16)
{
    __shared__ float red[256];
    const size_t base = (size_t)blockIdx.x * Dc;
    const int tid = threadIdx.x;
    float v[4]; float s = 0.f;
#pragma unroll
    for (int i = 0; i < 4; i++) { const int c = tid + i * 256; v[i] = x[base + c] + r[base + c]; s += v[i]; }
    red[tid] = s; __syncthreads();
    for (int st = 128; st > 0; st >>= 1) { if (tid < st) red[tid] += red[tid + st]; __syncthreads(); }
    const float mean = red[0] * (1.0f / Dc); __syncthreads();
    float ss = 0.f;
#pragma unroll
    for (int i = 0; i < 4; i++) { const float d = v[i] - mean; ss += d * d; }
    red[tid] = ss; __syncthreads();
    for (int st = 128; st > 0; st >>= 1) { if (tid < st) red[tid] += red[tid + st]; __syncthreads(); }
    const float rstd = rsqrtf(red[0] * (1.0f / Dc) + LN_EPS);
#pragma unroll
    for (int i = 0; i < 4; i++) {
        const int c = tid + i * 256;
        const float o = (v[i] - mean) * rstd * g[c] + b[c];
        out[base + c] = o;
        if (out16) out16[base + c] = __float2half(o);
    }
}

__global__ void gate_kernel(const float* __restrict__ x, const float* __restrict__ gw,
                            const float* __restrict__ gb,
                            float* __restrict__ gate, float* __restrict__ gate_out)
{
    const int m = blockIdx.x;
    const int tid = threadIdx.x;
    const int wid = tid >> 5, lane = tid & 31;
    __shared__ float logits[Ec];
    float s = 0.f;
    const float* xr = x + (size_t)m * Dc;
    for (int d = lane; d < Dc; d += 32) s += xr[d] * gw[d * Ec + wid];
#pragma unroll
    for (int o = 16; o > 0; o >>= 1) s += __shfl_down_sync(0xffffffffu, s, o);
    if (lane == 0) logits[wid] = s + gb[wid];
    __syncthreads();
    if (tid == 0) {
        float mx = logits[0];
#pragma unroll
        for (int e = 1; e < Ec; e++) mx = fmaxf(mx, logits[e]);
        float p[Ec]; float sum = 0.f;
#pragma unroll
        for (int e = 0; e < Ec; e++) { p[e] = expf(logits[e] - mx); sum += p[e]; }
        const float inv = 1.0f / sum;
#pragma unroll
        for (int e = 0; e < Ec; e++) {
            const float pv = p[e] * inv;
            gate[(size_t)m * Ec + e] = pv;
            if (gate_out) gate_out[(size_t)m * Ec + e] = pv;
        }
    }
}

__global__ void moe_reduce(const __half* __restrict__ part, const float* __restrict__ gate,
                           float* __restrict__ outm)
{
    const int i = blockIdx.x * blockDim.x + threadIdx.x;
    const int m = i / (Dc / 2);
    const float* gm = gate + (size_t)m * Ec;
    float2 s = make_float2(0.f, 0.f);
#pragma unroll
    for (int e = 0; e < Ec; e++) {
        float2 f = __half22float2(((const __half2*)part)[(size_t)e * (NTOK * Dc / 2) + i]);
        const float g = gm[e];
        s.x += g * f.x; s.y += g * f.y;
    }
    ((float2*)outm)[i] = s;
}

// ---------------- launch ----------------------------------------------------
extern "C" void kernel_launch(void* const* d_in, const int* in_sizes, int n_in,
                              void* d_out, int out_size)
{
    const float* hidden = (const float*)d_in[0];
    const float* mask   = (const float*)d_in[1];
    const float* wq = (const float*)d_in[2];  const float* bq = (const float*)d_in[3];
    const float* wk = (const float*)d_in[4];  const float* bk = (const float*)d_in[5];
    const float* wv = (const float*)d_in[6];  const float* bv = (const float*)d_in[7];
    const float* wo = (const float*)d_in[8];  const float* bo = (const float*)d_in[9];
    const float* ln1_g = (const float*)d_in[10]; const float* ln1_b = (const float*)d_in[11];
    const float* gate_w = (const float*)d_in[12]; const float* gate_b = (const float*)d_in[13];
    const float* w1 = (const float*)d_in[14]; const float* b1 = (const float*)d_in[15];
    const float* w2 = (const float*)d_in[16]; const float* b2 = (const float*)d_in[17];
    const float* ln2_g = (const float*)d_in[18]; const float* ln2_b = (const float*)d_in[19];

    float* f32 = nullptr;  __half* f16 = nullptr;
    cudaGetSymbolAddress((void**)&f32, g_f32);
    cudaGetSymbolAddress((void**)&f16, g_f16);

    float*  attn   = f32 + F_ATTN;
    float*  inter  = f32 + F_INT;
    float*  moe    = f32 + F_MOE;
    float*  gate   = f32 + F_GATE;
    float*  qkvb   = f32 + F_QKVB;
    __half* hid16  = f16 + H_HID;
    __half* q16    = f16 + H_Q;
    __half* k16    = f16 + H_K;
    __half* vT16   = f16 + H_VT;
    __half* ctx16  = f16 + H_CTX;
    __half* int16_ = f16 + H_INT;
    __half* msk16  = f16 + H_MSK;
    __half* h16    = f16 + H_HB;
    __half* p2     = f16 + H_P2;
    __half* wqT = f16 + H_WQ;
    __half* woT = f16 + H_WQ + 3 * (size_t)Dc * Dc;
    __half* w1T = f16 + H_W1; __half* w2T = f16 + H_W2;

    float* out = (float*)d_out;
    float* gate_out = nullptr;
    if ((size_t)out_size >= (size_t)NTOK * Dc + (size_t)NTOK * Ec)
        gate_out = out + (size_t)NTOK * Dc;

    cudaFuncSetAttribute(hgemm<128,3,2,0>, cudaFuncAttributeMaxDynamicSharedMemorySize, SMEM_128_S3);
    cudaFuncSetAttribute(hgemm<128,3,2,9>, cudaFuncAttributeMaxDynamicSharedMemorySize, SMEM_128_S3);
    cudaFuncSetAttribute(hgemm<64,2,3,1>,  cudaFuncAttributeMaxDynamicSharedMemorySize, SMEM_64_S2);
    cudaFuncSetAttribute(hgemm<64,2,3,6>,  cudaFuncAttributeMaxDynamicSharedMemorySize, SMEM_64_S2);
    cudaFuncSetAttribute(flash_attn,       cudaFuncAttributeMaxDynamicSharedMemorySize, SMEM_FA);

    const dim3 blk(256);
    const dim3 tblk(32, 8);

    // 0) hidden conversion + bias pack
    convpack<<<NTOK * Dc / 4 / 256, 256>>>(hidden, hid16, bq, bk, bv, qkvb);
    // 1) mask -> fp16
    maskconv<<<(int)((size_t)Bc * Sc * Sc / 4 / 256), 256>>>(mask, msk16);
    // 2) all weight transposes
    tconv_all<<<69632, tblk>>>(wq, wk, wv, wo, w1, w2, wqT);

    // 3) fused Q/K/V projection (z = 0,1,2 -> q16, k16, vT scatter)
    {
        dim3 grid(Dc / 128, NTOK / 128, 3);
        hgemm<128,3,2,9><<<grid, blk, SMEM_128_S3>>>(hid16, wqT, nullptr, q16, qkvb,
            Dc, Dc, Dc, Dc, 3,
            0, 0,
            0, (long long)Dc * Dc,
            0, (long long)NTOK * Dc,
            (long long)Dc);
    }

    // 4) fused attention -> ctx16
    {
        dim3 grid(Sc / 64, Bc * Hc);
        flash_attn<<<grid, 128, SMEM_FA>>>(q16, k16, vT16, msk16, ctx16);
    }

    // 5) output projection -> fp32 attn
    {
        dim3 grid(Dc / 128, NTOK / 128, 1);
        hgemm<128,3,2,0><<<grid, blk, SMEM_128_S3>>>(ctx16, woT, attn, nullptr, bo,
            Dc, Dc, Dc, Dc, 1, 0,0,0,0,0,0,0);
    }

    // 6) inter = LN1(attn + hidden)
    ln_residual<<<NTOK, 256>>>(attn, hidden, ln1_g, ln1_b, inter, int16_);

    // 7) gate
    gate_kernel<<<NTOK, 256>>>(inter, gate_w, gate_b, gate, gate_out);

    // 8-9) MoE batched across experts (z = expert), slim 128x64 3-CTA kernel
    {
        dim3 gh(Fc / 64, NTOK / 128, Ec);
        hgemm<64,2,3,1><<<gh, blk, SMEM_64_S2>>>(int16_, w1T, nullptr, h16, b1,
            Dc, Dc, Dc, Fc, Ec,
            0, 0,
            0, (long long)Dc * Fc,
            0, (long long)NTOK * Fc,
            (long long)Fc);

        dim3 gy(Dc / 64, NTOK / 128, Ec);
        hgemm<64,2,3,6><<<gy, blk, SMEM_64_S2>>>(h16, w2T, nullptr, p2, b2,
            Fc, Fc, Fc, Dc, Ec,
            0, (long long)NTOK * Fc,
            0, (long long)Fc * Dc,
            0, (long long)NTOK * Dc,
            (long long)Dc);
    }

    // 10) gate-weighted reduce
    moe_reduce<<<NTOK * Dc / 2 / 256, 256>>>(p2, gate, moe);

    // 11) output = LN2(moe + inter)
    ln_residual<<<NTOK, 256>>>(moe, inter, ln2_g, ln2_b, out, nullptr);
}

// round 11
// speedup vs baseline: 1.0696x; 1.0455x over previous
#include <cuda_runtime.h>
#include <cuda_fp16.h>
#include <math.h>
#include <stdint.h>

// ---------------- problem constants ----------------
#define Bc 2
#define Sc 2048
#define Dc 1024
#define Hc 16
#define DHc 64
#define Fc 4096
#define Ec 8
#define NTOK (Bc * Sc)
#define LN_EPS 1e-6f

// ---------------- fp32 scratch ----------------
static const size_t F_ATTN  = 0;
static const size_t F_INT   = F_ATTN + (size_t)NTOK * Dc;
static const size_t F_GATE  = F_INT  + (size_t)NTOK * Dc;
static const size_t F_QKVB  = F_GATE + (size_t)NTOK * Ec;
static const size_t F_TOTAL = F_QKVB + 3 * (size_t)Dc;
__device__ float g_f32[F_TOTAL];

// ---------------- fp16 scratch ----------------
static const size_t H_HID  = 0;
static const size_t H_Q    = H_HID + (size_t)NTOK * Dc;
static const size_t H_K    = H_Q   + (size_t)NTOK * Dc;     // contiguous with Q
static const size_t H_VT   = H_K   + (size_t)NTOK * Dc;     // [B,H,DH,S]
static const size_t H_CTX  = H_VT  + (size_t)NTOK * Dc;
static const size_t H_INT  = H_CTX + (size_t)NTOK * Dc;
static const size_t H_MSK  = H_INT + (size_t)NTOK * Dc;                 // fp16 mask [B,S,S]
static const size_t H_HB   = H_MSK + (size_t)Bc * Sc * Sc;
static const size_t H_P2   = H_HB  + (size_t)Ec * NTOK * Fc;
static const size_t H_WQ   = H_P2  + (size_t)Ec * NTOK * Dc;
static const size_t H_W1   = H_WQ  + 4 * (size_t)Dc * Dc;   // [E][N=F,K=D]
static const size_t H_W2   = H_W1  + (size_t)Ec * Dc * Fc;  // [E][N=D,K=F]
static const size_t H_TOTAL= H_W2  + (size_t)Ec * Fc * Dc;
__device__ __half g_f16[H_TOTAL];

// ---------------- PTX helpers ----------------
__device__ __forceinline__ uint32_t smem_u32(const void* p) {
    uint32_t a;
    asm("{ .reg .u64 t; cvta.to.shared.u64 t, %1; cvt.u32.u64 %0, t; }" : "=r"(a) : "l"(p));
    return a;
}
__device__ __forceinline__ void cp16(uint32_t s, const void* g) {
    asm volatile("cp.async.cg.shared.global [%0], [%1], 16;" :: "r"(s), "l"(g));
}
#define CP_COMMIT() asm volatile("cp.async.commit_group;" ::: "memory")
#define CP_WAIT(n)  asm volatile("cp.async.wait_group %0;" :: "n"(n) : "memory")

__device__ __forceinline__ void ldm_x4(uint32_t* r, uint32_t addr) {
    asm volatile("ldmatrix.sync.aligned.m8n8.x4.shared.b16 {%0,%1,%2,%3}, [%4];"
        : "=r"(r[0]), "=r"(r[1]), "=r"(r[2]), "=r"(r[3]) : "r"(addr));
}
__device__ __forceinline__ void mma16816(float* c, const uint32_t* a, const uint32_t* b) {
    asm volatile(
        "mma.sync.aligned.m16n8k16.row.col.f32.f16.f16.f32 "
        "{%0,%1,%2,%3}, {%4,%5,%6,%7}, {%8,%9}, {%0,%1,%2,%3};"
        : "+f"(c[0]), "+f"(c[1]), "+f"(c[2]), "+f"(c[3])
        : "r"(a[0]), "r"(a[1]), "r"(a[2]), "r"(a[3]), "r"(b[0]), "r"(b[1]));
}

__device__ __forceinline__ float gelu_tanh(float x) {
    float x3 = x * x * x;
    float t  = tanhf(0.7978845608028654f * (x + 0.044715f * x3));
    return 0.5f * x * (1.0f + t);
}
__device__ __forceinline__ uint32_t pack_h2(float a, float b) {
    __half2 h = __floats2half2_rn(a, b);
    return *reinterpret_cast<uint32_t*>(&h);
}

// ============================================================================
// HMMA GEMM (R8 core, verbatim): C[128,NT] = A[M,K] * B[N,K]^T, BK=64, 3 stages
// EPI: 0 = fp32 C = acc + bias?
//      1 = fp16 C16 = gelu(acc + bias)
//      6 = fp16 C16 = acc + bias?
//      9 = QKV route: hh<2 plain fp16; hh==2 V^T scatter
// ============================================================================
#define SPAD 72
#define STAGES 3

template <int NT, int EPI>
__global__ __launch_bounds__(256)
void hgemm(const __half* __restrict__ A, const __half* __restrict__ B,
           float* __restrict__ C, __half* __restrict__ C16,
           const float* __restrict__ bias,
           int K, int lda, int ldb, int ldc, int Hdim,
           long long aOB, long long aOH, long long bOB, long long bOH,
           long long cOB, long long cOH, long long biasOH)
{
    extern __shared__ __half smem[];

    const int tid = threadIdx.x, wid = tid >> 5, lane = tid & 31;
    const int wm = wid & 3, wn = wid >> 2;
    constexpr int WN = NT / 2;
    constexpr int NF = WN / 8;

    const int m0 = blockIdx.y * 128, n0 = blockIdx.x * NT;
    const int z = blockIdx.z, bb = z / Hdim, hh = z - bb * Hdim;
    A += (size_t)bb * aOB + (size_t)hh * aOH;
    B += (size_t)bb * bOB + (size_t)hh * bOH;
    if (bias) bias += (size_t)hh * biasOH;
    const long long coff = (long long)bb * cOB + (long long)hh * cOH;

    const uint32_t ABUF = 128 * SPAD * 2;
    const uint32_t BBUF = (uint32_t)NT * SPAD * 2;
    const uint32_t abase = smem_u32(smem);
    const uint32_t bbase = abase + STAGES * ABUF;

    const uint32_t a_off = (uint32_t)((wm * 32 + (lane & 15)) * (SPAD * 2) + ((lane >> 4) * 8) * 2);
    const uint32_t b_off = (uint32_t)((wn * WN + (lane & 7) + ((lane >> 4) << 3)) * (SPAD * 2)
                                      + (((lane >> 3) & 1) * 8) * 2);

    float acc[2][NF][4];
#pragma unroll
    for (int i = 0; i < 2; i++)
#pragma unroll
        for (int j = 0; j < NF; j++)
#pragma unroll
            for (int r = 0; r < 4; r++) acc[i][j][r] = 0.0f;

    const int nc = K >> 6;

    auto load_tile = [&](int c, int buf) {
        const __half* Ab = A + (size_t)m0 * lda + (size_t)c * 64;
#pragma unroll
        for (int it = 0; it < 4; it++) {
            int lin = it * 256 + tid;
            int row = lin >> 3, seg = lin & 7;
            cp16(abase + buf * ABUF + row * (SPAD * 2) + seg * 16,
                 Ab + (size_t)row * lda + seg * 8);
        }
        const __half* Bb = B + (size_t)n0 * ldb + (size_t)c * 64;
#pragma unroll
        for (int it = 0; it < NT / 32; it++) {
            int lin = it * 256 + tid;
            int row = lin >> 3, seg = lin & 7;
            cp16(bbase + buf * BBUF + row * (SPAD * 2) + seg * 16,
                 Bb + (size_t)row * ldb + seg * 8);
        }
    };

#pragma unroll
    for (int s = 0; s < STAGES - 1; s++) {
        if (s < nc) load_tile(s, s);
        CP_COMMIT();
    }

    for (int c = 0; c < nc; c++) {
        CP_WAIT(STAGES - 2);
        __syncthreads();
        const int nxt = c + STAGES - 1;
        if (nxt < nc) load_tile(nxt, nxt % STAGES);
        CP_COMMIT();

        const int buf = c % STAGES;
        const uint32_t ab = abase + buf * ABUF + a_off;
        const uint32_t bbf = bbase + buf * BBUF + b_off;

#pragma unroll
        for (int ks = 0; ks < 4; ks++) {
            uint32_t af[2][4];
#pragma unroll
            for (int mi = 0; mi < 2; mi++)
                ldm_x4(af[mi], ab + mi * 16 * (SPAD * 2) + ks * 32);
            uint32_t bf[NF][2];
#pragma unroll
            for (int p = 0; p < NF / 2; p++) {
                uint32_t t[4];
                ldm_x4(t, bbf + p * 16 * (SPAD * 2) + ks * 32);
                bf[2 * p][0] = t[0]; bf[2 * p][1] = t[1];
                bf[2 * p + 1][0] = t[2]; bf[2 * p + 1][1] = t[3];
            }
#pragma unroll
            for (int mi = 0; mi < 2; mi++)
#pragma unroll
                for (int nj = 0; nj < NF; nj++)
                    mma16816(acc[mi][nj], af[mi], bf[nj]);
        }
    }

#pragma unroll
    for (int mi = 0; mi < 2; mi++) {
#pragma unroll
        for (int nj = 0; nj < NF; nj++) {
            const int r0 = m0 + wm * 32 + mi * 16 + (lane >> 2);
            const int cc = n0 + wn * WN + nj * 8 + (lane & 3) * 2;
#pragma unroll
            for (int h = 0; h < 2; h++) {
                const int row = r0 + h * 8;
                const float v0 = acc[mi][nj][2 * h + 0];
                const float v1 = acc[mi][nj][2 * h + 1];
                if (EPI == 0) {
                    float b0 = bias ? bias[cc] : 0.f, b1 = bias ? bias[cc + 1] : 0.f;
                    float2 o = make_float2(v0 + b0, v1 + b1);
                    *(float2*)(C + coff + (size_t)row * ldc + cc) = o;
                } else if (EPI == 1 || EPI == 6) {
                    float o0 = v0 + (bias ? bias[cc] : 0.f);
                    float o1 = v1 + (bias ? bias[cc + 1] : 0.f);
                    if (EPI == 1) { o0 = gelu_tanh(o0); o1 = gelu_tanh(o1); }
                    *(uint32_t*)(C16 + coff + (size_t)row * ldc + cc) = pack_h2(o0, o1);
                } else if (EPI == 9) {
                    float o0 = v0 + bias[cc];
                    float o1 = v1 + bias[cc + 1];
                    if (hh < 2) {
                        *(uint32_t*)(C16 + coff + (size_t)row * ldc + cc) = pack_h2(o0, o1);
                    } else {
                        const int b_ = row >> 11, s_ = row & 2047;
                        const int h0 = cc >> 6, d0 = cc & 63;
                        const int h1 = (cc + 1) >> 6, d1 = (cc + 1) & 63;
                        C16[coff + ((size_t)((b_ * Hc + h0) * DHc + d0)) * Sc + s_] = __float2half(o0);
                        C16[coff + ((size_t)((b_ * Hc + h1) * DHc + d1)) * Sc + s_] = __float2half(o1);
                    }
                }
            }
        }
    }
}

static const int SMEM_NT128 = STAGES * (128 + 128) * SPAD * 2;  // 110592

// ============================================================================
// FlashAttention-2 fused attention, q-tile 128 (R9 variant).
// Grid: (S/128, B*H). 256 threads = 8 warps; warp = 16 q rows.
// KV tiles of 128, double-buffered cp.async. Mask fp16 [B,S,S].
// ============================================================================
#define SP1 72     // K/Q smem row stride (halves)
#define SP2 136    // V^T smem row stride (halves)
static const int SMEM_FA = 128 * SP1 * 2 + 2 * 128 * SP1 * 2 + 2 * 64 * SP2 * 2; // 90112

__global__ __launch_bounds__(256)
void flash_attn(const __half* __restrict__ Qg, const __half* __restrict__ Kg,
                const __half* __restrict__ Vt, const __half* __restrict__ Mk,
                __half* __restrict__ Og)
{
    extern __shared__ __half sm[];
    const int tid = threadIdx.x, wid = tid >> 5, lane = tid & 31;
    const int q0 = blockIdx.x * 128;
    const int z = blockIdx.y, bb = z >> 4, hh = z & 15;

    const uint32_t qs  = smem_u32(sm);
    const uint32_t ks0 = qs + 128 * SP1 * 2;
    const uint32_t KBUF = 128 * SP1 * 2;
    const uint32_t vs0 = ks0 + 2 * KBUF;
    const uint32_t VBUF = 64 * SP2 * 2;

    const __half* Qb = Qg + ((size_t)bb * Sc + q0) * Dc + hh * DHc;
    const __half* Kb = Kg + (size_t)bb * Sc * Dc + hh * DHc;
    const __half* Vb = Vt + ((size_t)(bb * Hc + hh)) * DHc * Sc;
    const __half* Mb = Mk + (size_t)bb * Sc * Sc;

    auto loadKV = [&](int t, int buf) {
        const __half* ksrc = Kb + (size_t)(t * 128) * Dc;
#pragma unroll
        for (int it = 0; it < 4; it++) {
            int lin = it * 256 + tid, row = lin >> 3, seg = lin & 7;
            cp16(ks0 + buf * KBUF + row * (SP1 * 2) + seg * 16, ksrc + (size_t)row * Dc + seg * 8);
        }
#pragma unroll
        for (int it = 0; it < 4; it++) {
            int lin = it * 256 + tid, row = lin >> 4, seg = lin & 15;
            cp16(vs0 + buf * VBUF + row * (SP2 * 2) + seg * 16,
                 Vb + (size_t)row * Sc + t * 128 + seg * 8);
        }
    };

    // prologue: Q + KV(0)
#pragma unroll
    for (int it = 0; it < 4; it++) {
        int lin = it * 256 + tid, row = lin >> 3, seg = lin & 7;
        cp16(qs + row * (SP1 * 2) + seg * 16, Qb + (size_t)row * Dc + seg * 8);
    }
    loadKV(0, 0);
    CP_COMMIT();

    const uint32_t a_q = qs + (wid * 16 + (lane & 15)) * (SP1 * 2) + ((lane >> 4) * 8) * 2;
    const uint32_t b_k = (uint32_t)(((lane & 7) + ((lane >> 4) << 3)) * (SP1 * 2) + (((lane >> 3) & 1) * 8) * 2);
    const uint32_t b_v = (uint32_t)(((lane & 7) + ((lane >> 4) << 3)) * (SP2 * 2) + (((lane >> 3) & 1) * 8) * 2);

    const int r = lane >> 2;
    const int qrow = q0 + wid * 16 + r;

    float o[8][4];
#pragma unroll
    for (int j = 0; j < 8; j++) { o[j][0] = o[j][1] = o[j][2] = o[j][3] = 0.f; }
    float rm0 = -1e30f, rm1 = -1e30f, rl0 = 0.f, rl1 = 0.f;

    for (int t = 0; t < Sc / 128; t++) {
        __syncthreads();
        if (t + 1 < Sc / 128) loadKV(t + 1, (t + 1) & 1);
        CP_COMMIT();
        CP_WAIT(1);
        __syncthreads();

        const uint32_t kb = ks0 + (t & 1) * KBUF + b_k;
        const uint32_t vb = vs0 + (t & 1) * VBUF + b_v;

        // ---- S = Q K^T
        float s[16][4];
#pragma unroll
        for (int j = 0; j < 16; j++) { s[j][0] = s[j][1] = s[j][2] = s[j][3] = 0.f; }
#pragma unroll
        for (int ks = 0; ks < 4; ks++) {
            uint32_t af[4];
            ldm_x4(af, a_q + ks * 32);
#pragma unroll
            for (int p = 0; p < 8; p++) {
                uint32_t tt[4];
                ldm_x4(tt, kb + p * 16 * (SP1 * 2) + ks * 32);
                mma16816(s[2 * p], af, tt);
                mma16816(s[2 * p + 1], af, tt + 2);
            }
        }

        // ---- scale + mask + row max
        const __half* mr0 = Mb + (size_t)qrow * Sc + t * 128 + (lane & 3) * 2;
        const __half* mr1 = mr0 + 8 * Sc;
        float tm0 = -1e30f, tm1 = -1e30f;
#pragma unroll
        for (int j = 0; j < 16; j++) {
            float2 m0 = __half22float2(*(const __half2*)(mr0 + j * 8));
            float2 m1 = __half22float2(*(const __half2*)(mr1 + j * 8));
            s[j][0] = s[j][0] * 0.125f + m0.x;
            s[j][1] = s[j][1] * 0.125f + m0.y;
            s[j][2] = s[j][2] * 0.125f + m1.x;
            s[j][3] = s[j][3] * 0.125f + m1.y;
            tm0 = fmaxf(tm0, fmaxf(s[j][0], s[j][1]));
            tm1 = fmaxf(tm1, fmaxf(s[j][2], s[j][3]));
        }
#pragma unroll
        for (int off = 1; off <= 2; off <<= 1) {
            tm0 = fmaxf(tm0, __shfl_xor_sync(0xffffffffu, tm0, off));
            tm1 = fmaxf(tm1, __shfl_xor_sync(0xffffffffu, tm1, off));
        }
        const float mn0 = fmaxf(rm0, tm0), mn1 = fmaxf(rm1, tm1);
        const float cr0 = __expf(rm0 - mn0), cr1 = __expf(rm1 - mn1);
        rm0 = mn0; rm1 = mn1;

        // ---- exp + pack P
        uint32_t pk[16][2];
        float ps0 = 0.f, ps1 = 0.f;
#pragma unroll
        for (int j = 0; j < 16; j++) {
            float p0 = __expf(s[j][0] - mn0), p1 = __expf(s[j][1] - mn0);
            float p2 = __expf(s[j][2] - mn1), p3 = __expf(s[j][3] - mn1);
            ps0 += p0 + p1; ps1 += p2 + p3;
            pk[j][0] = pack_h2(p0, p1);
            pk[j][1] = pack_h2(p2, p3);
        }
#pragma unroll
        for (int off = 1; off <= 2; off <<= 1) {
            ps0 += __shfl_xor_sync(0xffffffffu, ps0, off);
            ps1 += __shfl_xor_sync(0xffffffffu, ps1, off);
        }
        rl0 = rl0 * cr0 + ps0;
        rl1 = rl1 * cr1 + ps1;

        // ---- rescale O
#pragma unroll
        for (int j = 0; j < 8; j++) {
            o[j][0] *= cr0; o[j][1] *= cr0;
            o[j][2] *= cr1; o[j][3] *= cr1;
        }

        // ---- O += P @ V
#pragma unroll
        for (int ks = 0; ks < 8; ks++) {
            uint32_t af[4] = { pk[2 * ks][0], pk[2 * ks][1], pk[2 * ks + 1][0], pk[2 * ks + 1][1] };
#pragma unroll
            for (int p = 0; p < 4; p++) {
                uint32_t tt[4];
                ldm_x4(tt, vb + p * 16 * (SP2 * 2) + ks * 32);
                mma16816(o[2 * p], af, tt);
                mma16816(o[2 * p + 1], af, tt + 2);
            }
        }
    }

    // ---- write O
    const float i0 = 1.0f / rl0, i1 = 1.0f / rl1;
    __half* or0 = Og + ((size_t)bb * Sc + qrow) * Dc + hh * DHc + (lane & 3) * 2;
    __half* or1 = or0 + 8 * Dc;
#pragma unroll
    for (int j = 0; j < 8; j++) {
        *(uint32_t*)(or0 + j * 8) = pack_h2(o[j][0] * i0, o[j][1] * i0);
        *(uint32_t*)(or1 + j * 8) = pack_h2(o[j][2] * i1, o[j][3] * i1);
    }
}

// ---------------- small kernels ----------------
__global__ void convpack(const float* __restrict__ s, __half* __restrict__ d,
                         const float* __restrict__ bq, const float* __restrict__ bk,
                         const float* __restrict__ bv, float* __restrict__ qkvb)
{
    int i = blockIdx.x * blockDim.x + threadIdx.x;
    if (i < NTOK * Dc / 4) {
        float4 v = ((const float4*)s)[i];
        uint2 u;
        u.x = pack_h2(v.x, v.y); u.y = pack_h2(v.z, v.w);
        ((uint2*)d)[i] = u;
    }
    if (i < Dc) { qkvb[i] = bq[i]; qkvb[Dc + i] = bk[i]; qkvb[2 * Dc + i] = bv[i]; }
}

__global__ void maskconv(const float* __restrict__ s, __half* __restrict__ d)
{
    int i = blockIdx.x * blockDim.x + threadIdx.x;
    float4 v = ((const float4*)s)[i];
    uint2 u;
    u.x = pack_h2(v.x, v.y); u.y = pack_h2(v.z, v.w);
    ((uint2*)d)[i] = u;
}

__global__ void tconv_all(const float* __restrict__ wq, const float* __restrict__ wk,
                          const float* __restrict__ wv, const float* __restrict__ wo,
                          const float* __restrict__ w1, const float* __restrict__ w2,
                          __half* __restrict__ dstbase)
{
    __shared__ float t[32][33];
    int b = blockIdx.x;
    const float* src; __half* dst; int K, N;
    if (b < 4096) {
        int m = b >> 10; b &= 1023;
        src = (m == 0) ? wq : (m == 1) ? wk : (m == 2) ? wv : wo;
        dst = dstbase + (size_t)m * Dc * Dc; K = Dc; N = Dc;
    } else if (b < 4096 + 32768) {
        b -= 4096; int e = b >> 12; b &= 4095;
        src = w1 + (size_t)e * Dc * Fc;
        dst = dstbase + 4 * (size_t)Dc * Dc + (size_t)e * Dc * Fc; K = Dc; N = Fc;
    } else {
        b -= 36864; int e = b >> 12; b &= 4095;
        src = w2 + (size_t)e * Fc * Dc;
        dst = dstbase + 4 * (size_t)Dc * Dc + (size_t)Ec * Dc * Fc + (size_t)e * Fc * Dc;
        K = Fc; N = Dc;
    }
    const int ntx = N / 32;
    const int k0 = (b / ntx) * 32, n0 = (b % ntx) * 32;
    const int x = threadIdx.x, y = threadIdx.y;
#pragma unroll
    for (int i = 0; i < 32; i += 8)
        t[y + i][x] = src[(size_t)(k0 + y + i) * N + n0 + x];
    __syncthreads();
#pragma unroll
    for (int i = 0; i < 32; i += 8)
        dst[(size_t)(n0 + y + i) * K + k0 + x] = __float2half(t[x][y + i]);
}

__global__ void ln_residual(const float* __restrict__ x, const float* __restrict__ r,
                            const float* __restrict__ g, const float* __restrict__ b,
                            float* __restrict__ out, __half* __restrict__ out16)
{
    __shared__ float red[256];
    const size_t base = (size_t)blockIdx.x * Dc;
    const int tid = threadIdx.x;
    float v[4]; float s = 0.f;
#pragma unroll
    for (int i = 0; i < 4; i++) { const int c = tid + i * 256; v[i] = x[base + c] + r[base + c]; s += v[i]; }
    red[tid] = s; __syncthreads();
    for (int st = 128; st > 0; st >>= 1) { if (tid < st) red[tid] += red[tid + st]; __syncthreads(); }
    const float mean = red[0] * (1.0f / Dc); __syncthreads();
    float ss = 0.f;
#pragma unroll
    for (int i = 0; i < 4; i++) { const float d = v[i] - mean; ss += d * d; }
    red[tid] = ss; __syncthreads();
    for (int st = 128; st > 0; st >>= 1) { if (tid < st) red[tid] += red[tid + st]; __syncthreads(); }
    const float rstd = rsqrtf(red[0] * (1.0f / Dc) + LN_EPS);
#pragma unroll
    for (int i = 0; i < 4; i++) {
        const int c = tid + i * 256;
        const float o = (v[i] - mean) * rstd * g[c] + b[c];
        out[base + c] = o;
        if (out16) out16[base + c] = __float2half(o);
    }
}

__global__ void gate_kernel(const float* __restrict__ x, const float* __restrict__ gw,
                            const float* __restrict__ gb,
                            float* __restrict__ gate, float* __restrict__ gate_out)
{
    const int m = blockIdx.x;
    const int tid = threadIdx.x;
    const int wid = tid >> 5, lane = tid & 31;
    __shared__ float logits[Ec];
    float s = 0.f;
    const float* xr = x + (size_t)m * Dc;
    for (int d = lane; d < Dc; d += 32) s += xr[d] * gw[d * Ec + wid];
#pragma unroll
    for (int o = 16; o > 0; o >>= 1) s += __shfl_down_sync(0xffffffffu, s, o);
    if (lane == 0) logits[wid] = s + gb[wid];
    __syncthreads();
    if (tid == 0) {
        float mx = logits[0];
#pragma unroll
        for (int e = 1; e < Ec; e++) mx = fmaxf(mx, logits[e]);
        float p[Ec]; float sum = 0.f;
#pragma unroll
        for (int e = 0; e < Ec; e++) { p[e] = expf(logits[e] - mx); sum += p[e]; }
        const float inv = 1.0f / sum;
#pragma unroll
        for (int e = 0; e < Ec; e++) {
            const float pv = p[e] * inv;
            gate[(size_t)m * Ec + e] = pv;
            if (gate_out) gate_out[(size_t)m * Ec + e] = pv;
        }
    }
}

// fused: out = LN2( sum_e gate[e]*p2[e] + inter )
__global__ void ln2_moe(const __half* __restrict__ part, const float* __restrict__ gate,
                        const float* __restrict__ inter,
                        const float* __restrict__ g, const float* __restrict__ b,
                        float* __restrict__ out)
{
    __shared__ float red[256];
    __shared__ float gs[Ec];
    const int m = blockIdx.x, tid = threadIdx.x;
    if (tid < Ec) gs[tid] = gate[(size_t)m * Ec + tid];
    __syncthreads();
    const size_t base = (size_t)m * Dc;

    float v[4]; float s = 0.f;
#pragma unroll
    for (int i = 0; i < 2; i++) {
        const int c = tid * 2 + i * 512;
        float2 acc = *(const float2*)(inter + base + c);
#pragma unroll
        for (int e = 0; e < Ec; e++) {
            float2 f = __half22float2(*(const __half2*)(part + (size_t)e * NTOK * Dc + base + c));
            acc.x += gs[e] * f.x;
            acc.y += gs[e] * f.y;
        }
        v[2 * i] = acc.x; v[2 * i + 1] = acc.y;
        s += acc.x + acc.y;
    }
    red[tid] = s; __syncthreads();
    for (int st = 128; st > 0; st >>= 1) { if (tid < st) red[tid] += red[tid + st]; __syncthreads(); }
    const float mean = red[0] * (1.0f / Dc); __syncthreads();
    float ss = 0.f;
#pragma unroll
    for (int j = 0; j < 4; j++) { const float d = v[j] - mean; ss += d * d; }
    red[tid] = ss; __syncthreads();
    for (int st = 128; st > 0; st >>= 1) { if (tid < st) red[tid] += red[tid + st]; __syncthreads(); }
    const float rstd = rsqrtf(red[0] * (1.0f / Dc) + LN_EPS);
#pragma unroll
    for (int i = 0; i < 2; i++) {
        const int c = tid * 2 + i * 512;
        float2 o;
        o.x = (v[2 * i]     - mean) * rstd * g[c]     + b[c];
        o.y = (v[2 * i + 1] - mean) * rstd * g[c + 1] + b[c + 1];
        *(float2*)(out + base + c) = o;
    }
}

// ---------------- launch ----------------------------------------------------
extern "C" void kernel_launch(void* const* d_in, const int* in_sizes, int n_in,
                              void* d_out, int out_size)
{
    const float* hidden = (const float*)d_in[0];
    const float* mask   = (const float*)d_in[1];
    const float* wq = (const float*)d_in[2];  const float* bq = (const float*)d_in[3];
    const float* wk = (const float*)d_in[4];  const float* bk = (const float*)d_in[5];
    const float* wv = (const float*)d_in[6];  const float* bv = (const float*)d_in[7];
    const float* wo = (const float*)d_in[8];  const float* bo = (const float*)d_in[9];
    const float* ln1_g = (const float*)d_in[10]; const float* ln1_b = (const float*)d_in[11];
    const float* gate_w = (const float*)d_in[12]; const float* gate_b = (const float*)d_in[13];
    const float* w1 = (const float*)d_in[14]; const float* b1 = (const float*)d_in[15];
    const float* w2 = (const float*)d_in[16]; const float* b2 = (const float*)d_in[17];
    const float* ln2_g = (const float*)d_in[18]; const float* ln2_b = (const float*)d_in[19];

    float* f32 = nullptr;  __half* f16 = nullptr;
    cudaGetSymbolAddress((void**)&f32, g_f32);
    cudaGetSymbolAddress((void**)&f16, g_f16);

    float*  attn   = f32 + F_ATTN;
    float*  inter  = f32 + F_INT;
    float*  gate   = f32 + F_GATE;
    float*  qkvb   = f32 + F_QKVB;
    __half* hid16  = f16 + H_HID;
    __half* q16    = f16 + H_Q;
    __half* k16    = f16 + H_K;
    __half* vT16   = f16 + H_VT;
    __half* ctx16  = f16 + H_CTX;
    __half* int16_ = f16 + H_INT;
    __half* msk16  = f16 + H_MSK;
    __half* h16    = f16 + H_HB;
    __half* p2     = f16 + H_P2;
    __half* wqT = f16 + H_WQ;
    __half* woT = f16 + H_WQ + 3 * (size_t)Dc * Dc;
    __half* w1T = f16 + H_W1; __half* w2T = f16 + H_W2;

    float* out = (float*)d_out;
    float* gate_out = nullptr;
    if ((size_t)out_size >= (size_t)NTOK * Dc + (size_t)NTOK * Ec)
        gate_out = out + (size_t)NTOK * Dc;

    cudaFuncSetAttribute(hgemm<128,0>, cudaFuncAttributeMaxDynamicSharedMemorySize, SMEM_NT128);
    cudaFuncSetAttribute(hgemm<128,1>, cudaFuncAttributeMaxDynamicSharedMemorySize, SMEM_NT128);
    cudaFuncSetAttribute(hgemm<128,6>, cudaFuncAttributeMaxDynamicSharedMemorySize, SMEM_NT128);
    cudaFuncSetAttribute(hgemm<128,9>, cudaFuncAttributeMaxDynamicSharedMemorySize, SMEM_NT128);
    cudaFuncSetAttribute(flash_attn,   cudaFuncAttributeMaxDynamicSharedMemorySize, SMEM_FA);

    const dim3 blk(256);
    const dim3 tblk(32, 8);

    // 0) hidden conversion + bias pack
    convpack<<<NTOK * Dc / 4 / 256, 256>>>(hidden, hid16, bq, bk, bv, qkvb);
    // 1) mask -> fp16
    maskconv<<<(int)((size_t)Bc * Sc * Sc / 4 / 256), 256>>>(mask, msk16);
    // 2) all weight transposes
    tconv_all<<<69632, tblk>>>(wq, wk, wv, wo, w1, w2, wqT);

    // 3) fused Q/K/V projection (z = 0,1,2 -> q16, k16, vT scatter)
    {
        dim3 grid(Dc / 128, NTOK / 128, 3);
        hgemm<128,9><<<grid, blk, SMEM_NT128>>>(hid16, wqT, nullptr, q16, qkvb,
            Dc, Dc, Dc, Dc, 3,
            0, 0,
            0, (long long)Dc * Dc,
            0, (long long)NTOK * Dc,
            (long long)Dc);
    }

    // 4) fused attention (q-tile 128) -> ctx16
    {
        dim3 grid(Sc / 128, Bc * Hc);
        flash_attn<<<grid, 256, SMEM_FA>>>(q16, k16, vT16, msk16, ctx16);
    }

    // 5) output projection -> fp32 attn
    {
        dim3 grid(Dc / 128, NTOK / 128, 1);
        hgemm<128,0><<<grid, blk, SMEM_NT128>>>(ctx16, woT, attn, nullptr, bo,
            Dc, Dc, Dc, Dc, 1, 0,0,0,0,0,0,0);
    }

    // 6) inter = LN1(attn + hidden)
    ln_residual<<<NTOK, 256>>>(attn, hidden, ln1_g, ln1_b, inter, int16_);

    // 7) gate
    gate_kernel<<<NTOK, 256>>>(inter, gate_w, gate_b, gate, gate_out);

    // 8-9) MoE batched across experts (z = expert) — R8 128x128 config
    {
        dim3 gh(Fc / 128, NTOK / 128, Ec);
        hgemm<128,1><<<gh, blk, SMEM_NT128>>>(int16_, w1T, nullptr, h16, b1,
            Dc, Dc, Dc, Fc, Ec,
            0, 0,
            0, (long long)Dc * Fc,
            0, (long long)NTOK * Fc,
            (long long)Fc);

        dim3 gy(Dc / 128, NTOK / 128, Ec);
        hgemm<128,6><<<gy, blk, SMEM_NT128>>>(h16, w2T, nullptr, p2, b2,
            Fc, Fc, Fc, Dc, Ec,
            0, (long long)NTOK * Fc,
            0, (long long)Fc * Dc,
            0, (long long)NTOK * Dc,
            (long long)Dc);
    }

    // 10) fused gate-weighted reduce + LN2 -> out
    ln2_moe<<<NTOK, 256>>>(p2, gate, inter, ln2_g, ln2_b, out);
}

// round 12
// speedup vs baseline: 1.1024x; 1.0306x over previous
#include <cuda_runtime.h>
#include <cuda_fp16.h>
#include <math.h>
#include <stdint.h>

// ---------------- problem constants ----------------
#define Bc 2
#define Sc 2048
#define Dc 1024
#define Hc 16
#define DHc 64
#define Fc 4096
#define Ec 8
#define NTOK (Bc * Sc)
#define LN_EPS 1e-6f

// ---------------- fp32 scratch ----------------
static const size_t F_ATTN  = 0;
static const size_t F_INT   = F_ATTN + (size_t)NTOK * Dc;
static const size_t F_GATE  = F_INT  + (size_t)NTOK * Dc;
static const size_t F_QKVB  = F_GATE + (size_t)NTOK * Ec;
static const size_t F_TOTAL = F_QKVB + 3 * (size_t)Dc;
__device__ float g_f32[F_TOTAL];

// ---------------- fp16 scratch ----------------
static const size_t H_HID  = 0;
static const size_t H_Q    = H_HID + (size_t)NTOK * Dc;
static const size_t H_K    = H_Q   + (size_t)NTOK * Dc;     // contiguous with Q
static const size_t H_VT   = H_K   + (size_t)NTOK * Dc;     // [B,H,DH,S]
static const size_t H_CTX  = H_VT  + (size_t)NTOK * Dc;
static const size_t H_INT  = H_CTX + (size_t)NTOK * Dc;
static const size_t H_MSK  = H_INT + (size_t)NTOK * Dc;                 // fp16 mask [B,S,S]
static const size_t H_HB   = H_MSK + (size_t)Bc * Sc * Sc;
static const size_t H_P2   = H_HB  + (size_t)Ec * NTOK * Fc;
static const size_t H_WQ   = H_P2  + (size_t)Ec * NTOK * Dc;
static const size_t H_W1   = H_WQ  + 4 * (size_t)Dc * Dc;   // [E][N=F,K=D]
static const size_t H_W2   = H_W1  + (size_t)Ec * Dc * Fc;  // [E][N=D,K=F]
static const size_t H_TOTAL= H_W2  + (size_t)Ec * Fc * Dc;
__device__ __half g_f16[H_TOTAL];

// ---------------- PTX helpers ----------------
__device__ __forceinline__ uint32_t smem_u32(const void* p) {
    uint32_t a;
    asm("{ .reg .u64 t; cvta.to.shared.u64 t, %1; cvt.u32.u64 %0, t; }" : "=r"(a) : "l"(p));
    return a;
}
__device__ __forceinline__ void cp16(uint32_t s, const void* g) {
    asm volatile("cp.async.cg.shared.global [%0], [%1], 16;" :: "r"(s), "l"(g));
}
#define CP_COMMIT() asm volatile("cp.async.commit_group;" ::: "memory")
#define CP_WAIT(n)  asm volatile("cp.async.wait_group %0;" :: "n"(n) : "memory")

__device__ __forceinline__ void ldm_x4(uint32_t* r, uint32_t addr) {
    asm volatile("ldmatrix.sync.aligned.m8n8.x4.shared.b16 {%0,%1,%2,%3}, [%4];"
        : "=r"(r[0]), "=r"(r[1]), "=r"(r[2]), "=r"(r[3]) : "r"(addr));
}
__device__ __forceinline__ void mma16816(float* c, const uint32_t* a, const uint32_t* b) {
    asm volatile(
        "mma.sync.aligned.m16n8k16.row.col.f32.f16.f16.f32 "
        "{%0,%1,%2,%3}, {%4,%5,%6,%7}, {%8,%9}, {%0,%1,%2,%3};"
        : "+f"(c[0]), "+f"(c[1]), "+f"(c[2]), "+f"(c[3])
        : "r"(a[0]), "r"(a[1]), "r"(a[2]), "r"(a[3]), "r"(b[0]), "r"(b[1]));
}

__device__ __forceinline__ float gelu_tanh(float x) {
    float x3 = x * x * x;
    float t  = tanhf(0.7978845608028654f * (x + 0.044715f * x3));
    return 0.5f * x * (1.0f + t);
}
__device__ __forceinline__ uint32_t pack_h2(float a, float b) {
    __half2 h = __floats2half2_rn(a, b);
    return *reinterpret_cast<uint32_t*>(&h);
}

// ============================================================================
// HMMA GEMM (R8 core, verbatim): C[128,NT] = A[M,K] * B[N,K]^T, BK=64, 3 stages
// EPI: 0 = fp32 C = acc + bias?
//      1 = fp16 C16 = gelu(acc + bias)
//      6 = fp16 C16 = acc + bias?
//      9 = QKV route: hh<2 plain fp16; hh==2 V^T scatter
// ============================================================================
#define SPAD 72
#define STAGES 3

template <int NT, int EPI>
__global__ __launch_bounds__(256)
void hgemm(const __half* __restrict__ A, const __half* __restrict__ B,
           float* __restrict__ C, __half* __restrict__ C16,
           const float* __restrict__ bias,
           int K, int lda, int ldb, int ldc, int Hdim,
           long long aOB, long long aOH, long long bOB, long long bOH,
           long long cOB, long long cOH, long long biasOH)
{
    extern __shared__ __half smem[];

    const int tid = threadIdx.x, wid = tid >> 5, lane = tid & 31;
    const int wm = wid & 3, wn = wid >> 2;
    constexpr int WN = NT / 2;
    constexpr int NF = WN / 8;

    const int m0 = blockIdx.y * 128, n0 = blockIdx.x * NT;
    const int z = blockIdx.z, bb = z / Hdim, hh = z - bb * Hdim;
    A += (size_t)bb * aOB + (size_t)hh * aOH;
    B += (size_t)bb * bOB + (size_t)hh * bOH;
    if (bias) bias += (size_t)hh * biasOH;
    const long long coff = (long long)bb * cOB + (long long)hh * cOH;

    const uint32_t ABUF = 128 * SPAD * 2;
    const uint32_t BBUF = (uint32_t)NT * SPAD * 2;
    const uint32_t abase = smem_u32(smem);
    const uint32_t bbase = abase + STAGES * ABUF;

    const uint32_t a_off = (uint32_t)((wm * 32 + (lane & 15)) * (SPAD * 2) + ((lane >> 4) * 8) * 2);
    const uint32_t b_off = (uint32_t)((wn * WN + (lane & 7) + ((lane >> 4) << 3)) * (SPAD * 2)
                                      + (((lane >> 3) & 1) * 8) * 2);

    float acc[2][NF][4];
#pragma unroll
    for (int i = 0; i < 2; i++)
#pragma unroll
        for (int j = 0; j < NF; j++)
#pragma unroll
            for (int r = 0; r < 4; r++) acc[i][j][r] = 0.0f;

    const int nc = K >> 6;

    auto load_tile = [&](int c, int buf) {
        const __half* Ab = A + (size_t)m0 * lda + (size_t)c * 64;
#pragma unroll
        for (int it = 0; it < 4; it++) {
            int lin = it * 256 + tid;
            int row = lin >> 3, seg = lin & 7;
            cp16(abase + buf * ABUF + row * (SPAD * 2) + seg * 16,
                 Ab + (size_t)row * lda + seg * 8);
        }
        const __half* Bb = B + (size_t)n0 * ldb + (size_t)c * 64;
#pragma unroll
        for (int it = 0; it < NT / 32; it++) {
            int lin = it * 256 + tid;
            int row = lin >> 3, seg = lin & 7;
            cp16(bbase + buf * BBUF + row * (SPAD * 2) + seg * 16,
                 Bb + (size_t)row * ldb + seg * 8);
        }
    };

#pragma unroll
    for (int s = 0; s < STAGES - 1; s++) {
        if (s < nc) load_tile(s, s);
        CP_COMMIT();
    }

    for (int c = 0; c < nc; c++) {
        CP_WAIT(STAGES - 2);
        __syncthreads();
        const int nxt = c + STAGES - 1;
        if (nxt < nc) load_tile(nxt, nxt % STAGES);
        CP_COMMIT();

        const int buf = c % STAGES;
        const uint32_t ab = abase + buf * ABUF + a_off;
        const uint32_t bbf = bbase + buf * BBUF + b_off;

#pragma unroll
        for (int ks = 0; ks < 4; ks++) {
            uint32_t af[2][4];
#pragma unroll
            for (int mi = 0; mi < 2; mi++)
                ldm_x4(af[mi], ab + mi * 16 * (SPAD * 2) + ks * 32);
            uint32_t bf[NF][2];
#pragma unroll
            for (int p = 0; p < NF / 2; p++) {
                uint32_t t[4];
                ldm_x4(t, bbf + p * 16 * (SPAD * 2) + ks * 32);
                bf[2 * p][0] = t[0]; bf[2 * p][1] = t[1];
                bf[2 * p + 1][0] = t[2]; bf[2 * p + 1][1] = t[3];
            }
#pragma unroll
            for (int mi = 0; mi < 2; mi++)
#pragma unroll
                for (int nj = 0; nj < NF; nj++)
                    mma16816(acc[mi][nj], af[mi], bf[nj]);
        }
    }

#pragma unroll
    for (int mi = 0; mi < 2; mi++) {
#pragma unroll
        for (int nj = 0; nj < NF; nj++) {
            const int r0 = m0 + wm * 32 + mi * 16 + (lane >> 2);
            const int cc = n0 + wn * WN + nj * 8 + (lane & 3) * 2;
#pragma unroll
            for (int h = 0; h < 2; h++) {
                const int row = r0 + h * 8;
                const float v0 = acc[mi][nj][2 * h + 0];
                const float v1 = acc[mi][nj][2 * h + 1];
                if (EPI == 0) {
                    float b0 = bias ? bias[cc] : 0.f, b1 = bias ? bias[cc + 1] : 0.f;
                    float2 o = make_float2(v0 + b0, v1 + b1);
                    *(float2*)(C + coff + (size_t)row * ldc + cc) = o;
                } else if (EPI == 1 || EPI == 6) {
                    float o0 = v0 + (bias ? bias[cc] : 0.f);
                    float o1 = v1 + (bias ? bias[cc + 1] : 0.f);
                    if (EPI == 1) { o0 = gelu_tanh(o0); o1 = gelu_tanh(o1); }
                    *(uint32_t*)(C16 + coff + (size_t)row * ldc + cc) = pack_h2(o0, o1);
                } else if (EPI == 9) {
                    float o0 = v0 + bias[cc];
                    float o1 = v1 + bias[cc + 1];
                    if (hh < 2) {
                        *(uint32_t*)(C16 + coff + (size_t)row * ldc + cc) = pack_h2(o0, o1);
                    } else {
                        const int b_ = row >> 11, s_ = row & 2047;
                        const int h0 = cc >> 6, d0 = cc & 63;
                        const int h1 = (cc + 1) >> 6, d1 = (cc + 1) & 63;
                        C16[coff + ((size_t)((b_ * Hc + h0) * DHc + d0)) * Sc + s_] = __float2half(o0);
                        C16[coff + ((size_t)((b_ * Hc + h1) * DHc + d1)) * Sc + s_] = __float2half(o1);
                    }
                }
            }
        }
    }
}

static const int SMEM_NT128 = STAGES * (128 + 128) * SPAD * 2;  // 110592

// ============================================================================
// FlashAttention-2 fused attention (R8 version, q-tile 64 — the proven one).
// Grid: (S/64 q-tiles, B*H). 128 threads = 4 warps; warp = 16 q rows.
// ============================================================================
#define SP1 72     // K/Q smem row stride (halves)
#define SP2 136    // V^T smem row stride (halves)
static const int SMEM_FA = 64 * SP1 * 2 + 2 * 128 * SP1 * 2 + 2 * 64 * SP2 * 2; // 80896

__global__ __launch_bounds__(128)
void flash_attn(const __half* __restrict__ Qg, const __half* __restrict__ Kg,
                const __half* __restrict__ Vt, const __half* __restrict__ Mk,
                __half* __restrict__ Og)
{
    extern __shared__ __half sm[];
    const int tid = threadIdx.x, wid = tid >> 5, lane = tid & 31;
    const int q0 = blockIdx.x * 64;
    const int z = blockIdx.y, bb = z >> 4, hh = z & 15;

    const uint32_t qs  = smem_u32(sm);
    const uint32_t ks0 = qs + 64 * SP1 * 2;
    const uint32_t KBUF = 128 * SP1 * 2;
    const uint32_t vs0 = ks0 + 2 * KBUF;
    const uint32_t VBUF = 64 * SP2 * 2;

    const __half* Qb = Qg + ((size_t)bb * Sc + q0) * Dc + hh * DHc;
    const __half* Kb = Kg + (size_t)bb * Sc * Dc + hh * DHc;
    const __half* Vb = Vt + ((size_t)(bb * Hc + hh)) * DHc * Sc;
    const __half* Mb = Mk + (size_t)bb * Sc * Sc;

    auto loadKV = [&](int t, int buf) {
        const __half* ksrc = Kb + (size_t)(t * 128) * Dc;
#pragma unroll
        for (int it = 0; it < 8; it++) {
            int lin = it * 128 + tid, row = lin >> 3, seg = lin & 7;
            cp16(ks0 + buf * KBUF + row * (SP1 * 2) + seg * 16, ksrc + (size_t)row * Dc + seg * 8);
        }
#pragma unroll
        for (int it = 0; it < 8; it++) {
            int lin = it * 128 + tid, row = lin >> 4, seg = lin & 15;
            cp16(vs0 + buf * VBUF + row * (SP2 * 2) + seg * 16,
                 Vb + (size_t)row * Sc + t * 128 + seg * 8);
        }
    };

    // prologue: Q + KV(0)
#pragma unroll
    for (int it = 0; it < 4; it++) {
        int lin = it * 128 + tid, row = lin >> 3, seg = lin & 7;
        cp16(qs + row * (SP1 * 2) + seg * 16, Qb + (size_t)row * Dc + seg * 8);
    }
    loadKV(0, 0);
    CP_COMMIT();

    const uint32_t a_q = qs + (wid * 16 + (lane & 15)) * (SP1 * 2) + ((lane >> 4) * 8) * 2;
    const uint32_t b_k = (uint32_t)(((lane & 7) + ((lane >> 4) << 3)) * (SP1 * 2) + (((lane >> 3) & 1) * 8) * 2);
    const uint32_t b_v = (uint32_t)(((lane & 7) + ((lane >> 4) << 3)) * (SP2 * 2) + (((lane >> 3) & 1) * 8) * 2);

    const int r = lane >> 2;
    const int qrow = q0 + wid * 16 + r;

    float o[8][4];
#pragma unroll
    for (int j = 0; j < 8; j++) { o[j][0] = o[j][1] = o[j][2] = o[j][3] = 0.f; }
    float rm0 = -1e30f, rm1 = -1e30f, rl0 = 0.f, rl1 = 0.f;

    for (int t = 0; t < Sc / 128; t++) {
        __syncthreads();
        if (t + 1 < Sc / 128) loadKV(t + 1, (t + 1) & 1);
        CP_COMMIT();
        CP_WAIT(1);
        __syncthreads();

        const uint32_t kb = ks0 + (t & 1) * KBUF + b_k;
        const uint32_t vb = vs0 + (t & 1) * VBUF + b_v;

        // ---- S = Q K^T
        float s[16][4];
#pragma unroll
        for (int j = 0; j < 16; j++) { s[j][0] = s[j][1] = s[j][2] = s[j][3] = 0.f; }
#pragma unroll
        for (int ks = 0; ks < 4; ks++) {
            uint32_t af[4];
            ldm_x4(af, a_q + ks * 32);
#pragma unroll
            for (int p = 0; p < 8; p++) {
                uint32_t tt[4];
                ldm_x4(tt, kb + p * 16 * (SP1 * 2) + ks * 32);
                mma16816(s[2 * p], af, tt);
                mma16816(s[2 * p + 1], af, tt + 2);
            }
        }

        // ---- scale + mask + row max
        const __half* mr0 = Mb + (size_t)qrow * Sc + t * 128 + (lane & 3) * 2;
        const __half* mr1 = mr0 + 8 * Sc;
        float tm0 = -1e30f, tm1 = -1e30f;
#pragma unroll
        for (int j = 0; j < 16; j++) {
            float2 m0 = __half22float2(*(const __half2*)(mr0 + j * 8));
            float2 m1 = __half22float2(*(const __half2*)(mr1 + j * 8));
            s[j][0] = s[j][0] * 0.125f + m0.x;
            s[j][1] = s[j][1] * 0.125f + m0.y;
            s[j][2] = s[j][2] * 0.125f + m1.x;
            s[j][3] = s[j][3] * 0.125f + m1.y;
            tm0 = fmaxf(tm0, fmaxf(s[j][0], s[j][1]));
            tm1 = fmaxf(tm1, fmaxf(s[j][2], s[j][3]));
        }
#pragma unroll
        for (int off = 1; off <= 2; off <<= 1) {
            tm0 = fmaxf(tm0, __shfl_xor_sync(0xffffffffu, tm0, off));
            tm1 = fmaxf(tm1, __shfl_xor_sync(0xffffffffu, tm1, off));
        }
        const float mn0 = fmaxf(rm0, tm0), mn1 = fmaxf(rm1, tm1);
        const float cr0 = __expf(rm0 - mn0), cr1 = __expf(rm1 - mn1);
        rm0 = mn0; rm1 = mn1;

        // ---- exp + pack P
        uint32_t pk[16][2];
        float ps0 = 0.f, ps1 = 0.f;
#pragma unroll
        for (int j = 0; j < 16; j++) {
            float p0 = __expf(s[j][0] - mn0), p1 = __expf(s[j][1] - mn0);
            float p2 = __expf(s[j][2] - mn1), p3 = __expf(s[j][3] - mn1);
            ps0 += p0 + p1; ps1 += p2 + p3;
            pk[j][0] = pack_h2(p0, p1);
            pk[j][1] = pack_h2(p2, p3);
        }
#pragma unroll
        for (int off = 1; off <= 2; off <<= 1) {
            ps0 += __shfl_xor_sync(0xffffffffu, ps0, off);
            ps1 += __shfl_xor_sync(0xffffffffu, ps1, off);
        }
        rl0 = rl0 * cr0 + ps0;
        rl1 = rl1 * cr1 + ps1;

        // ---- rescale O
#pragma unroll
        for (int j = 0; j < 8; j++) {
            o[j][0] *= cr0; o[j][1] *= cr0;
            o[j][2] *= cr1; o[j][3] *= cr1;
        }

        // ---- O += P @ V
#pragma unroll
        for (int ks = 0; ks < 8; ks++) {
            uint32_t af[4] = { pk[2 * ks][0], pk[2 * ks][1], pk[2 * ks + 1][0], pk[2 * ks + 1][1] };
#pragma unroll
            for (int p = 0; p < 4; p++) {
                uint32_t tt[4];
                ldm_x4(tt, vb + p * 16 * (SP2 * 2) + ks * 32);
                mma16816(o[2 * p], af, tt);
                mma16816(o[2 * p + 1], af, tt + 2);
            }
        }
    }

    // ---- write O
    const float i0 = 1.0f / rl0, i1 = 1.0f / rl1;
    __half* or0 = Og + ((size_t)bb * Sc + qrow) * Dc + hh * DHc + (lane & 3) * 2;
    __half* or1 = or0 + 8 * Dc;
#pragma unroll
    for (int j = 0; j < 8; j++) {
        *(uint32_t*)(or0 + j * 8) = pack_h2(o[j][0] * i0, o[j][1] * i0);
        *(uint32_t*)(or1 + j * 8) = pack_h2(o[j][2] * i1, o[j][3] * i1);
    }
}

// ---------------- small kernels ----------------
__global__ void convpack(const float* __restrict__ s, __half* __restrict__ d,
                         const float* __restrict__ bq, const float* __restrict__ bk,
                         const float* __restrict__ bv, float* __restrict__ qkvb)
{
    int i = blockIdx.x * blockDim.x + threadIdx.x;
    if (i < NTOK * Dc / 4) {
        float4 v = ((const float4*)s)[i];
        uint2 u;
        u.x = pack_h2(v.x, v.y); u.y = pack_h2(v.z, v.w);
        ((uint2*)d)[i] = u;
    }
    if (i < Dc) { qkvb[i] = bq[i]; qkvb[Dc + i] = bk[i]; qkvb[2 * Dc + i] = bv[i]; }
}

__global__ void maskconv(const float* __restrict__ s, __half* __restrict__ d)
{
    int i = blockIdx.x * blockDim.x + threadIdx.x;
    float4 v = ((const float4*)s)[i];
    uint2 u;
    u.x = pack_h2(v.x, v.y); u.y = pack_h2(v.z, v.w);
    ((uint2*)d)[i] = u;
}

__global__ void tconv_all(const float* __restrict__ wq, const float* __restrict__ wk,
                          const float* __restrict__ wv, const float* __restrict__ wo,
                          const float* __restrict__ w1, const float* __restrict__ w2,
                          __half* __restrict__ dstbase)
{
    __shared__ float t[32][33];
    int b = blockIdx.x;
    const float* src; __half* dst; int K, N;
    if (b < 4096) {
        int m = b >> 10; b &= 1023;
        src = (m == 0) ? wq : (m == 1) ? wk : (m == 2) ? wv : wo;
        dst = dstbase + (size_t)m * Dc * Dc; K = Dc; N = Dc;
    } else if (b < 4096 + 32768) {
        b -= 4096; int e = b >> 12; b &= 4095;
        src = w1 + (size_t)e * Dc * Fc;
        dst = dstbase + 4 * (size_t)Dc * Dc + (size_t)e * Dc * Fc; K = Dc; N = Fc;
    } else {
        b -= 36864; int e = b >> 12; b &= 4095;
        src = w2 + (size_t)e * Fc * Dc;
        dst = dstbase + 4 * (size_t)Dc * Dc + (size_t)Ec * Dc * Fc + (size_t)e * Fc * Dc;
        K = Fc; N = Dc;
    }
    const int ntx = N / 32;
    const int k0 = (b / ntx) * 32, n0 = (b % ntx) * 32;
    const int x = threadIdx.x, y = threadIdx.y;
#pragma unroll
    for (int i = 0; i < 32; i += 8)
        t[y + i][x] = src[(size_t)(k0 + y + i) * N + n0 + x];
    __syncthreads();
#pragma unroll
    for (int i = 0; i < 32; i += 8)
        dst[(size_t)(n0 + y + i) * K + k0 + x] = __float2half(t[x][y + i]);
}

__global__ void ln_residual(const float* __restrict__ x, const float* __restrict__ r,
                            const float* __restrict__ g, const float* __restrict__ b,
                            float* __restrict__ out, __half* __restrict__ out16)
{
    __shared__ float red[256];
    const size_t base = (size_t)blockIdx.x * Dc;
    const int tid = threadIdx.x;
    float v[4]; float s = 0.f;
#pragma unroll
    for (int i = 0; i < 4; i++) { const int c = tid + i * 256; v[i] = x[base + c] + r[base + c]; s += v[i]; }
    red[tid] = s; __syncthreads();
    for (int st = 128; st > 0; st >>= 1) { if (tid < st) red[tid] += red[tid + st]; __syncthreads(); }
    const float mean = red[0] * (1.0f / Dc); __syncthreads();
    float ss = 0.f;
#pragma unroll
    for (int i = 0; i < 4; i++) { const float d = v[i] - mean; ss += d * d; }
    red[tid] = ss; __syncthreads();
    for (int st = 128; st > 0; st >>= 1) { if (tid < st) red[tid] += red[tid + st]; __syncthreads(); }
    const float rstd = rsqrtf(red[0] * (1.0f / Dc) + LN_EPS);
#pragma unroll
    for (int i = 0; i < 4; i++) {
        const int c = tid + i * 256;
        const float o = (v[i] - mean) * rstd * g[c] + b[c];
        out[base + c] = o;
        if (out16) out16[base + c] = __float2half(o);
    }
}

__global__ void gate_kernel(const float* __restrict__ x, const float* __restrict__ gw,
                            const float* __restrict__ gb,
                            float* __restrict__ gate, float* __restrict__ gate_out)
{
    const int m = blockIdx.x;
    const int tid = threadIdx.x;
    const int wid = tid >> 5, lane = tid & 31;
    __shared__ float logits[Ec];
    float s = 0.f;
    const float* xr = x + (size_t)m * Dc;
    for (int d = lane; d < Dc; d += 32) s += xr[d] * gw[d * Ec + wid];
#pragma unroll
    for (int o = 16; o > 0; o >>= 1) s += __shfl_down_sync(0xffffffffu, s, o);
    if (lane == 0) logits[wid] = s + gb[wid];
    __syncthreads();
    if (tid == 0) {
        float mx = logits[0];
#pragma unroll
        for (int e = 1; e < Ec; e++) mx = fmaxf(mx, logits[e]);
        float p[Ec]; float sum = 0.f;
#pragma unroll
        for (int e = 0; e < Ec; e++) { p[e] = expf(logits[e] - mx); sum += p[e]; }
        const float inv = 1.0f / sum;
#pragma unroll
        for (int e = 0; e < Ec; e++) {
            const float pv = p[e] * inv;
            gate[(size_t)m * Ec + e] = pv;
            if (gate_out) gate_out[(size_t)m * Ec + e] = pv;
        }
    }
}

// fused: out = LN2( sum_e gate[e]*p2[e] + inter )
__global__ void ln2_moe(const __half* __restrict__ part, const float* __restrict__ gate,
                        const float* __restrict__ inter,
                        const float* __restrict__ g, const float* __restrict__ b,
                        float* __restrict__ out)
{
    __shared__ float red[256];
    __shared__ float gs[Ec];
    const int m = blockIdx.x, tid = threadIdx.x;
    if (tid < Ec) gs[tid] = gate[(size_t)m * Ec + tid];
    __syncthreads();
    const size_t base = (size_t)m * Dc;

    float v[4]; float s = 0.f;
#pragma unroll
    for (int i = 0; i < 2; i++) {
        const int c = tid * 2 + i * 512;
        float2 acc = *(const float2*)(inter + base + c);
#pragma unroll
        for (int e = 0; e < Ec; e++) {
            float2 f = __half22float2(*(const __half2*)(part + (size_t)e * NTOK * Dc + base + c));
            acc.x += gs[e] * f.x;
            acc.y += gs[e] * f.y;
        }
        v[2 * i] = acc.x; v[2 * i + 1] = acc.y;
        s += acc.x + acc.y;
    }
    red[tid] = s; __syncthreads();
    for (int st = 128; st > 0; st >>= 1) { if (tid < st) red[tid] += red[tid + st]; __syncthreads(); }
    const float mean = red[0] * (1.0f / Dc); __syncthreads();
    float ss = 0.f;
#pragma unroll
    for (int j = 0; j < 4; j++) { const float d = v[j] - mean; ss += d * d; }
    red[tid] = ss; __syncthreads();
    for (int st = 128; st > 0; st >>= 1) { if (tid < st) red[tid] += red[tid + st]; __syncthreads(); }
    const float rstd = rsqrtf(red[0] * (1.0f / Dc) + LN_EPS);
#pragma unroll
    for (int i = 0; i < 2; i++) {
        const int c = tid * 2 + i * 512;
        float2 o;
        o.x = (v[2 * i]     - mean) * rstd * g[c]     + b[c];
        o.y = (v[2 * i + 1] - mean) * rstd * g[c + 1] + b[c + 1];
        *(float2*)(out + base + c) = o;
    }
}

// ---------------- launch ----------------------------------------------------
extern "C" void kernel_launch(void* const* d_in, const int* in_sizes, int n_in,
                              void* d_out, int out_size)
{
    const float* hidden = (const float*)d_in[0];
    const float* mask   = (const float*)d_in[1];
    const float* wq = (const float*)d_in[2];  const float* bq = (const float*)d_in[3];
    const float* wk = (const float*)d_in[4];  const float* bk = (const float*)d_in[5];
    const float* wv = (const float*)d_in[6];  const float* bv = (const float*)d_in[7];
    const float* wo = (const float*)d_in[8];  const float* bo = (const float*)d_in[9];
    const float* ln1_g = (const float*)d_in[10]; const float* ln1_b = (const float*)d_in[11];
    const float* gate_w = (const float*)d_in[12]; const float* gate_b = (const float*)d_in[13];
    const float* w1 = (const float*)d_in[14]; const float* b1 = (const float*)d_in[15];
    const float* w2 = (const float*)d_in[16]; const float* b2 = (const float*)d_in[17];
    const float* ln2_g = (const float*)d_in[18]; const float* ln2_b = (const float*)d_in[19];

    float* f32 = nullptr;  __half* f16 = nullptr;
    cudaGetSymbolAddress((void**)&f32, g_f32);
    cudaGetSymbolAddress((void**)&f16, g_f16);

    float*  attn   = f32 + F_ATTN;
    float*  inter  = f32 + F_INT;
    float*  gate   = f32 + F_GATE;
    float*  qkvb   = f32 + F_QKVB;
    __half* hid16  = f16 + H_HID;
    __half* q16    = f16 + H_Q;
    __half* k16    = f16 + H_K;
    __half* vT16   = f16 + H_VT;
    __half* ctx16  = f16 + H_CTX;
    __half* int16_ = f16 + H_INT;
    __half* msk16  = f16 + H_MSK;
    __half* h16    = f16 + H_HB;
    __half* p2     = f16 + H_P2;
    __half* wqT = f16 + H_WQ;
    __half* woT = f16 + H_WQ + 3 * (size_t)Dc * Dc;
    __half* w1T = f16 + H_W1; __half* w2T = f16 + H_W2;

    float* out = (float*)d_out;
    float* gate_out = nullptr;
    if ((size_t)out_size >= (size_t)NTOK * Dc + (size_t)NTOK * Ec)
        gate_out = out + (size_t)NTOK * Dc;

    cudaFuncSetAttribute(hgemm<128,0>, cudaFuncAttributeMaxDynamicSharedMemorySize, SMEM_NT128);
    cudaFuncSetAttribute(hgemm<128,1>, cudaFuncAttributeMaxDynamicSharedMemorySize, SMEM_NT128);
    cudaFuncSetAttribute(hgemm<128,6>, cudaFuncAttributeMaxDynamicSharedMemorySize, SMEM_NT128);
    cudaFuncSetAttribute(hgemm<128,9>, cudaFuncAttributeMaxDynamicSharedMemorySize, SMEM_NT128);
    cudaFuncSetAttribute(flash_attn,   cudaFuncAttributeMaxDynamicSharedMemorySize, SMEM_FA);

    const dim3 blk(256);
    const dim3 tblk(32, 8);

    // 0) hidden conversion + bias pack
    convpack<<<NTOK * Dc / 4 / 256, 256>>>(hidden, hid16, bq, bk, bv, qkvb);
    // 1) mask -> fp16
    maskconv<<<(int)((size_t)Bc * Sc * Sc / 4 / 256), 256>>>(mask, msk16);
    // 2) all weight transposes
    tconv_all<<<69632, tblk>>>(wq, wk, wv, wo, w1, w2, wqT);

    // 3) fused Q/K/V projection (z = 0,1,2 -> q16, k16, vT scatter)
    {
        dim3 grid(Dc / 128, NTOK / 128, 3);
        hgemm<128,9><<<grid, blk, SMEM_NT128>>>(hid16, wqT, nullptr, q16, qkvb,
            Dc, Dc, Dc, Dc, 3,
            0, 0,
            0, (long long)Dc * Dc,
            0, (long long)NTOK * Dc,
            (long long)Dc);
    }

    // 4) fused attention (q-tile 64) -> ctx16
    {
        dim3 grid(Sc / 64, Bc * Hc);
        flash_attn<<<grid, 128, SMEM_FA>>>(q16, k16, vT16, msk16, ctx16);
    }

    // 5) output projection -> fp32 attn
    {
        dim3 grid(Dc / 128, NTOK / 128, 1);
        hgemm<128,0><<<grid, blk, SMEM_NT128>>>(ctx16, woT, attn, nullptr, bo,
            Dc, Dc, Dc, Dc, 1, 0,0,0,0,0,0,0);
    }

    // 6) inter = LN1(attn + hidden)
    ln_residual<<<NTOK, 256>>>(attn, hidden, ln1_g, ln1_b, inter, int16_);

    // 7) gate
    gate_kernel<<<NTOK, 256>>>(inter, gate_w, gate_b, gate, gate_out);

    // 8-9) MoE batched across experts (z = expert) — R8 128x128 config
    {
        dim3 gh(Fc / 128, NTOK / 128, Ec);
        hgemm<128,1><<<gh, blk, SMEM_NT128>>>(int16_, w1T, nullptr, h16, b1,
            Dc, Dc, Dc, Fc, Ec,
            0, 0,
            0, (long long)Dc * Fc,
            0, (long long)NTOK * Fc,
            (long long)Fc);

        dim3 gy(Dc / 128, NTOK / 128, Ec);
        hgemm<128,6><<<gy, blk, SMEM_NT128>>>(h16, w2T, nullptr, p2, b2,
            Fc, Fc, Fc, Dc, Ec,
            0, (long long)NTOK * Fc,
            0, (long long)Fc * Dc,
            0, (long long)NTOK * Dc,
            (long long)Dc);
    }

    // 10) fused gate-weighted reduce + LN2 -> out
    ln2_moe<<<NTOK, 256>>>(p2, gate, inter, ln2_g, ln2_b, out);
}

// round 13
// speedup vs baseline: 1.1124x; 1.0091x over previous
#include <cuda_runtime.h>
#include <cuda_fp16.h>
#include <math.h>
#include <stdint.h>

// ---------------- problem constants ----------------
#define Bc 2
#define Sc 2048
#define Dc 1024
#define Hc 16
#define DHc 64
#define Fc 4096
#define Ec 8
#define NTOK (Bc * Sc)
#define LN_EPS 1e-6f

// ---------------- fp32 scratch ----------------
static const size_t F_ATTN  = 0;
static const size_t F_INT   = F_ATTN + (size_t)NTOK * Dc;
static const size_t F_GATE  = F_INT  + (size_t)NTOK * Dc;
static const size_t F_QKVB  = F_GATE + (size_t)NTOK * Ec;
static const size_t F_TOTAL = F_QKVB + 3 * (size_t)Dc;
__device__ float g_f32[F_TOTAL];

// ---------------- fp16 scratch ----------------
static const size_t H_HID  = 0;
static const size_t H_Q    = H_HID + (size_t)NTOK * Dc;
static const size_t H_K    = H_Q   + (size_t)NTOK * Dc;     // contiguous with Q
static const size_t H_VT   = H_K   + (size_t)NTOK * Dc;     // [B,H,DH,S]
static const size_t H_CTX  = H_VT  + (size_t)NTOK * Dc;
static const size_t H_INT  = H_CTX + (size_t)NTOK * Dc;
static const size_t H_MSK  = H_INT + (size_t)NTOK * Dc;                 // fp16 mask [B,S,S]
static const size_t H_HB   = H_MSK + (size_t)Bc * Sc * Sc;
static const size_t H_P2   = H_HB  + (size_t)Ec * NTOK * Fc;
static const size_t H_WQ   = H_P2  + (size_t)Ec * NTOK * Dc;
static const size_t H_W1   = H_WQ  + 4 * (size_t)Dc * Dc;   // [E][N=F,K=D]
static const size_t H_W2   = H_W1  + (size_t)Ec * Dc * Fc;  // [E][N=D,K=F]
static const size_t H_TOTAL= H_W2  + (size_t)Ec * Fc * Dc;
__device__ __half g_f16[H_TOTAL];

// ---------------- PTX helpers ----------------
__device__ __forceinline__ uint32_t smem_u32(const void* p) {
    uint32_t a;
    asm("{ .reg .u64 t; cvta.to.shared.u64 t, %1; cvt.u32.u64 %0, t; }" : "=r"(a) : "l"(p));
    return a;
}
__device__ __forceinline__ void cp16(uint32_t s, const void* g) {
    asm volatile("cp.async.cg.shared.global [%0], [%1], 16;" :: "r"(s), "l"(g));
}
#define CP_COMMIT() asm volatile("cp.async.commit_group;" ::: "memory")
#define CP_WAIT(n)  asm volatile("cp.async.wait_group %0;" :: "n"(n) : "memory")

__device__ __forceinline__ void ldm_x4(uint32_t* r, uint32_t addr) {
    asm volatile("ldmatrix.sync.aligned.m8n8.x4.shared.b16 {%0,%1,%2,%3}, [%4];"
        : "=r"(r[0]), "=r"(r[1]), "=r"(r[2]), "=r"(r[3]) : "r"(addr));
}
__device__ __forceinline__ void mma16816(float* c, const uint32_t* a, const uint32_t* b) {
    asm volatile(
        "mma.sync.aligned.m16n8k16.row.col.f32.f16.f16.f32 "
        "{%0,%1,%2,%3}, {%4,%5,%6,%7}, {%8,%9}, {%0,%1,%2,%3};"
        : "+f"(c[0]), "+f"(c[1]), "+f"(c[2]), "+f"(c[3])
        : "r"(a[0]), "r"(a[1]), "r"(a[2]), "r"(a[3]), "r"(b[0]), "r"(b[1]));
}

__device__ __forceinline__ float gelu_tanh(float x) {
    float x3 = x * x * x;
    float t  = tanhf(0.7978845608028654f * (x + 0.044715f * x3));
    return 0.5f * x * (1.0f + t);
}
__device__ __forceinline__ uint32_t pack_h2(float a, float b) {
    __half2 h = __floats2half2_rn(a, b);
    return *reinterpret_cast<uint32_t*>(&h);
}

// ============================================================================
// HMMA GEMM (R8 core, verbatim): C[128,NT] = A[M,K] * B[N,K]^T, BK=64, 3 stages
// EPI: 0 = fp32 C = acc + bias?
//      1 = fp16 C16 = gelu(acc + bias)
//      6 = fp16 C16 = acc + bias?
//      9 = QKV route: hh<2 plain fp16; hh==2 V^T scatter
// ============================================================================
#define SPAD 72
#define STAGES 3

template <int NT, int EPI>
__global__ __launch_bounds__(256)
void hgemm(const __half* __restrict__ A, const __half* __restrict__ B,
           float* __restrict__ C, __half* __restrict__ C16,
           const float* __restrict__ bias,
           int K, int lda, int ldb, int ldc, int Hdim,
           long long aOB, long long aOH, long long bOB, long long bOH,
           long long cOB, long long cOH, long long biasOH)
{
    extern __shared__ __half smem[];

    const int tid = threadIdx.x, wid = tid >> 5, lane = tid & 31;
    const int wm = wid & 3, wn = wid >> 2;
    constexpr int WN = NT / 2;
    constexpr int NF = WN / 8;

    const int m0 = blockIdx.y * 128, n0 = blockIdx.x * NT;
    const int z = blockIdx.z, bb = z / Hdim, hh = z - bb * Hdim;
    A += (size_t)bb * aOB + (size_t)hh * aOH;
    B += (size_t)bb * bOB + (size_t)hh * bOH;
    if (bias) bias += (size_t)hh * biasOH;
    const long long coff = (long long)bb * cOB + (long long)hh * cOH;

    const uint32_t ABUF = 128 * SPAD * 2;
    const uint32_t BBUF = (uint32_t)NT * SPAD * 2;
    const uint32_t abase = smem_u32(smem);
    const uint32_t bbase = abase + STAGES * ABUF;

    const uint32_t a_off = (uint32_t)((wm * 32 + (lane & 15)) * (SPAD * 2) + ((lane >> 4) * 8) * 2);
    const uint32_t b_off = (uint32_t)((wn * WN + (lane & 7) + ((lane >> 4) << 3)) * (SPAD * 2)
                                      + (((lane >> 3) & 1) * 8) * 2);

    float acc[2][NF][4];
#pragma unroll
    for (int i = 0; i < 2; i++)
#pragma unroll
        for (int j = 0; j < NF; j++)
#pragma unroll
            for (int r = 0; r < 4; r++) acc[i][j][r] = 0.0f;

    const int nc = K >> 6;

    auto load_tile = [&](int c, int buf) {
        const __half* Ab = A + (size_t)m0 * lda + (size_t)c * 64;
#pragma unroll
        for (int it = 0; it < 4; it++) {
            int lin = it * 256 + tid;
            int row = lin >> 3, seg = lin & 7;
            cp16(abase + buf * ABUF + row * (SPAD * 2) + seg * 16,
                 Ab + (size_t)row * lda + seg * 8);
        }
        const __half* Bb = B + (size_t)n0 * ldb + (size_t)c * 64;
#pragma unroll
        for (int it = 0; it < NT / 32; it++) {
            int lin = it * 256 + tid;
            int row = lin >> 3, seg = lin & 7;
            cp16(bbase + buf * BBUF + row * (SPAD * 2) + seg * 16,
                 Bb + (size_t)row * ldb + seg * 8);
        }
    };

#pragma unroll
    for (int s = 0; s < STAGES - 1; s++) {
        if (s < nc) load_tile(s, s);
        CP_COMMIT();
    }

    for (int c = 0; c < nc; c++) {
        CP_WAIT(STAGES - 2);
        __syncthreads();
        const int nxt = c + STAGES - 1;
        if (nxt < nc) load_tile(nxt, nxt % STAGES);
        CP_COMMIT();

        const int buf = c % STAGES;
        const uint32_t ab = abase + buf * ABUF + a_off;
        const uint32_t bbf = bbase + buf * BBUF + b_off;

#pragma unroll
        for (int ks = 0; ks < 4; ks++) {
            uint32_t af[2][4];
#pragma unroll
            for (int mi = 0; mi < 2; mi++)
                ldm_x4(af[mi], ab + mi * 16 * (SPAD * 2) + ks * 32);
            uint32_t bf[NF][2];
#pragma unroll
            for (int p = 0; p < NF / 2; p++) {
                uint32_t t[4];
                ldm_x4(t, bbf + p * 16 * (SPAD * 2) + ks * 32);
                bf[2 * p][0] = t[0]; bf[2 * p][1] = t[1];
                bf[2 * p + 1][0] = t[2]; bf[2 * p + 1][1] = t[3];
            }
#pragma unroll
            for (int mi = 0; mi < 2; mi++)
#pragma unroll
                for (int nj = 0; nj < NF; nj++)
                    mma16816(acc[mi][nj], af[mi], bf[nj]);
        }
    }

#pragma unroll
    for (int mi = 0; mi < 2; mi++) {
#pragma unroll
        for (int nj = 0; nj < NF; nj++) {
            const int r0 = m0 + wm * 32 + mi * 16 + (lane >> 2);
            const int cc = n0 + wn * WN + nj * 8 + (lane & 3) * 2;
#pragma unroll
            for (int h = 0; h < 2; h++) {
                const int row = r0 + h * 8;
                const float v0 = acc[mi][nj][2 * h + 0];
                const float v1 = acc[mi][nj][2 * h + 1];
                if (EPI == 0) {
                    float b0 = bias ? bias[cc] : 0.f, b1 = bias ? bias[cc + 1] : 0.f;
                    float2 o = make_float2(v0 + b0, v1 + b1);
                    *(float2*)(C + coff + (size_t)row * ldc + cc) = o;
                } else if (EPI == 1 || EPI == 6) {
                    float o0 = v0 + (bias ? bias[cc] : 0.f);
                    float o1 = v1 + (bias ? bias[cc + 1] : 0.f);
                    if (EPI == 1) { o0 = gelu_tanh(o0); o1 = gelu_tanh(o1); }
                    *(uint32_t*)(C16 + coff + (size_t)row * ldc + cc) = pack_h2(o0, o1);
                } else if (EPI == 9) {
                    float o0 = v0 + bias[cc];
                    float o1 = v1 + bias[cc + 1];
                    if (hh < 2) {
                        *(uint32_t*)(C16 + coff + (size_t)row * ldc + cc) = pack_h2(o0, o1);
                    } else {
                        const int b_ = row >> 11, s_ = row & 2047;
                        const int h0 = cc >> 6, d0 = cc & 63;
                        const int h1 = (cc + 1) >> 6, d1 = (cc + 1) & 63;
                        C16[coff + ((size_t)((b_ * Hc + h0) * DHc + d0)) * Sc + s_] = __float2half(o0);
                        C16[coff + ((size_t)((b_ * Hc + h1) * DHc + d1)) * Sc + s_] = __float2half(o1);
                    }
                }
            }
        }
    }
}

static const int SMEM_NT128 = STAGES * (128 + 128) * SPAD * 2;  // 110592

// ============================================================================
// FlashAttention-2 fused attention (R8 version, q-tile 64 — the proven one).
// Grid: (S/64 q-tiles, B*H). 128 threads = 4 warps; warp = 16 q rows.
// ============================================================================
#define SP1 72     // K/Q smem row stride (halves)
#define SP2 136    // V^T smem row stride (halves)
static const int SMEM_FA = 64 * SP1 * 2 + 2 * 128 * SP1 * 2 + 2 * 64 * SP2 * 2; // 80896

__global__ __launch_bounds__(128)
void flash_attn(const __half* __restrict__ Qg, const __half* __restrict__ Kg,
                const __half* __restrict__ Vt, const __half* __restrict__ Mk,
                __half* __restrict__ Og)
{
    extern __shared__ __half sm[];
    const int tid = threadIdx.x, wid = tid >> 5, lane = tid & 31;
    const int q0 = blockIdx.x * 64;
    const int z = blockIdx.y, bb = z >> 4, hh = z & 15;

    const uint32_t qs  = smem_u32(sm);
    const uint32_t ks0 = qs + 64 * SP1 * 2;
    const uint32_t KBUF = 128 * SP1 * 2;
    const uint32_t vs0 = ks0 + 2 * KBUF;
    const uint32_t VBUF = 64 * SP2 * 2;

    const __half* Qb = Qg + ((size_t)bb * Sc + q0) * Dc + hh * DHc;
    const __half* Kb = Kg + (size_t)bb * Sc * Dc + hh * DHc;
    const __half* Vb = Vt + ((size_t)(bb * Hc + hh)) * DHc * Sc;
    const __half* Mb = Mk + (size_t)bb * Sc * Sc;

    auto loadKV = [&](int t, int buf) {
        const __half* ksrc = Kb + (size_t)(t * 128) * Dc;
#pragma unroll
        for (int it = 0; it < 8; it++) {
            int lin = it * 128 + tid, row = lin >> 3, seg = lin & 7;
            cp16(ks0 + buf * KBUF + row * (SP1 * 2) + seg * 16, ksrc + (size_t)row * Dc + seg * 8);
        }
#pragma unroll
        for (int it = 0; it < 8; it++) {
            int lin = it * 128 + tid, row = lin >> 4, seg = lin & 15;
            cp16(vs0 + buf * VBUF + row * (SP2 * 2) + seg * 16,
                 Vb + (size_t)row * Sc + t * 128 + seg * 8);
        }
    };

    // prologue: Q + KV(0)
#pragma unroll
    for (int it = 0; it < 4; it++) {
        int lin = it * 128 + tid, row = lin >> 3, seg = lin & 7;
        cp16(qs + row * (SP1 * 2) + seg * 16, Qb + (size_t)row * Dc + seg * 8);
    }
    loadKV(0, 0);
    CP_COMMIT();

    const uint32_t a_q = qs + (wid * 16 + (lane & 15)) * (SP1 * 2) + ((lane >> 4) * 8) * 2;
    const uint32_t b_k = (uint32_t)(((lane & 7) + ((lane >> 4) << 3)) * (SP1 * 2) + (((lane >> 3) & 1) * 8) * 2);
    const uint32_t b_v = (uint32_t)(((lane & 7) + ((lane >> 4) << 3)) * (SP2 * 2) + (((lane >> 3) & 1) * 8) * 2);

    const int r = lane >> 2;
    const int qrow = q0 + wid * 16 + r;

    float o[8][4];
#pragma unroll
    for (int j = 0; j < 8; j++) { o[j][0] = o[j][1] = o[j][2] = o[j][3] = 0.f; }
    float rm0 = -1e30f, rm1 = -1e30f, rl0 = 0.f, rl1 = 0.f;

    for (int t = 0; t < Sc / 128; t++) {
        __syncthreads();
        if (t + 1 < Sc / 128) loadKV(t + 1, (t + 1) & 1);
        CP_COMMIT();
        CP_WAIT(1);
        __syncthreads();

        const uint32_t kb = ks0 + (t & 1) * KBUF + b_k;
        const uint32_t vb = vs0 + (t & 1) * VBUF + b_v;

        // ---- S = Q K^T
        float s[16][4];
#pragma unroll
        for (int j = 0; j < 16; j++) { s[j][0] = s[j][1] = s[j][2] = s[j][3] = 0.f; }
#pragma unroll
        for (int ks = 0; ks < 4; ks++) {
            uint32_t af[4];
            ldm_x4(af, a_q + ks * 32);
#pragma unroll
            for (int p = 0; p < 8; p++) {
                uint32_t tt[4];
                ldm_x4(tt, kb + p * 16 * (SP1 * 2) + ks * 32);
                mma16816(s[2 * p], af, tt);
                mma16816(s[2 * p + 1], af, tt + 2);
            }
        }

        // ---- scale + mask + row max
        const __half* mr0 = Mb + (size_t)qrow * Sc + t * 128 + (lane & 3) * 2;
        const __half* mr1 = mr0 + 8 * Sc;
        float tm0 = -1e30f, tm1 = -1e30f;
#pragma unroll
        for (int j = 0; j < 16; j++) {
            float2 m0 = __half22float2(*(const __half2*)(mr0 + j * 8));
            float2 m1 = __half22float2(*(const __half2*)(mr1 + j * 8));
            s[j][0] = s[j][0] * 0.125f + m0.x;
            s[j][1] = s[j][1] * 0.125f + m0.y;
            s[j][2] = s[j][2] * 0.125f + m1.x;
            s[j][3] = s[j][3] * 0.125f + m1.y;
            tm0 = fmaxf(tm0, fmaxf(s[j][0], s[j][1]));
            tm1 = fmaxf(tm1, fmaxf(s[j][2], s[j][3]));
        }
#pragma unroll
        for (int off = 1; off <= 2; off <<= 1) {
            tm0 = fmaxf(tm0, __shfl_xor_sync(0xffffffffu, tm0, off));
            tm1 = fmaxf(tm1, __shfl_xor_sync(0xffffffffu, tm1, off));
        }
        const float mn0 = fmaxf(rm0, tm0), mn1 = fmaxf(rm1, tm1);
        const float cr0 = __expf(rm0 - mn0), cr1 = __expf(rm1 - mn1);
        rm0 = mn0; rm1 = mn1;

        // ---- exp + pack P
        uint32_t pk[16][2];
        float ps0 = 0.f, ps1 = 0.f;
#pragma unroll
        for (int j = 0; j < 16; j++) {
            float p0 = __expf(s[j][0] - mn0), p1 = __expf(s[j][1] - mn0);
            float p2 = __expf(s[j][2] - mn1), p3 = __expf(s[j][3] - mn1);
            ps0 += p0 + p1; ps1 += p2 + p3;
            pk[j][0] = pack_h2(p0, p1);
            pk[j][1] = pack_h2(p2, p3);
        }
#pragma unroll
        for (int off = 1; off <= 2; off <<= 1) {
            ps0 += __shfl_xor_sync(0xffffffffu, ps0, off);
            ps1 += __shfl_xor_sync(0xffffffffu, ps1, off);
        }
        rl0 = rl0 * cr0 + ps0;
        rl1 = rl1 * cr1 + ps1;

        // ---- rescale O
#pragma unroll
        for (int j = 0; j < 8; j++) {
            o[j][0] *= cr0; o[j][1] *= cr0;
            o[j][2] *= cr1; o[j][3] *= cr1;
        }

        // ---- O += P @ V
#pragma unroll
        for (int ks = 0; ks < 8; ks++) {
            uint32_t af[4] = { pk[2 * ks][0], pk[2 * ks][1], pk[2 * ks + 1][0], pk[2 * ks + 1][1] };
#pragma unroll
            for (int p = 0; p < 4; p++) {
                uint32_t tt[4];
                ldm_x4(tt, vb + p * 16 * (SP2 * 2) + ks * 32);
                mma16816(o[2 * p], af, tt);
                mma16816(o[2 * p + 1], af, tt + 2);
            }
        }
    }

    // ---- write O
    const float i0 = 1.0f / rl0, i1 = 1.0f / rl1;
    __half* or0 = Og + ((size_t)bb * Sc + qrow) * Dc + hh * DHc + (lane & 3) * 2;
    __half* or1 = or0 + 8 * Dc;
#pragma unroll
    for (int j = 0; j < 8; j++) {
        *(uint32_t*)(or0 + j * 8) = pack_h2(o[j][0] * i0, o[j][1] * i0);
        *(uint32_t*)(or1 + j * 8) = pack_h2(o[j][2] * i1, o[j][3] * i1);
    }
}

// ---------------- small kernels ----------------
// one launch: hidden fp32->fp16, mask fp32->fp16, QKV bias pack
__global__ void conv_all(const float* __restrict__ hid, __half* __restrict__ hid16,
                         const float* __restrict__ msk, __half* __restrict__ msk16,
                         const float* __restrict__ bq, const float* __restrict__ bk,
                         const float* __restrict__ bv, float* __restrict__ qkvb)
{
    int i = blockIdx.x * blockDim.x + threadIdx.x;   // grid sized for mask (largest)
    {
        float4 v = ((const float4*)msk)[i];
        uint2 u;
        u.x = pack_h2(v.x, v.y); u.y = pack_h2(v.z, v.w);
        ((uint2*)msk16)[i] = u;
    }
    if (i < NTOK * Dc / 4) {
        float4 v = ((const float4*)hid)[i];
        uint2 u;
        u.x = pack_h2(v.x, v.y); u.y = pack_h2(v.z, v.w);
        ((uint2*)hid16)[i] = u;
    }
    if (i < Dc) { qkvb[i] = bq[i]; qkvb[Dc + i] = bk[i]; qkvb[2 * Dc + i] = bv[i]; }
}

__global__ void tconv_all(const float* __restrict__ wq, const float* __restrict__ wk,
                          const float* __restrict__ wv, const float* __restrict__ wo,
                          const float* __restrict__ w1, const float* __restrict__ w2,
                          __half* __restrict__ dstbase)
{
    __shared__ float t[32][33];
    int b = blockIdx.x;
    const float* src; __half* dst; int K, N;
    if (b < 4096) {
        int m = b >> 10; b &= 1023;
        src = (m == 0) ? wq : (m == 1) ? wk : (m == 2) ? wv : wo;
        dst = dstbase + (size_t)m * Dc * Dc; K = Dc; N = Dc;
    } else if (b < 4096 + 32768) {
        b -= 4096; int e = b >> 12; b &= 4095;
        src = w1 + (size_t)e * Dc * Fc;
        dst = dstbase + 4 * (size_t)Dc * Dc + (size_t)e * Dc * Fc; K = Dc; N = Fc;
    } else {
        b -= 36864; int e = b >> 12; b &= 4095;
        src = w2 + (size_t)e * Fc * Dc;
        dst = dstbase + 4 * (size_t)Dc * Dc + (size_t)Ec * Dc * Fc + (size_t)e * Fc * Dc;
        K = Fc; N = Dc;
    }
    const int ntx = N / 32;
    const int k0 = (b / ntx) * 32, n0 = (b % ntx) * 32;
    const int x = threadIdx.x, y = threadIdx.y;
#pragma unroll
    for (int i = 0; i < 32; i += 8)
        t[y + i][x] = src[(size_t)(k0 + y + i) * N + n0 + x];
    __syncthreads();
#pragma unroll
    for (int i = 0; i < 32; i += 8)
        dst[(size_t)(n0 + y + i) * K + k0 + x] = __float2half(t[x][y + i]);
}

// LN1(attn + hidden) -> inter (fp32 + fp16)  AND  gate = softmax(inter @ gw + gb)
__global__ void ln1_gate(const float* __restrict__ x, const float* __restrict__ r,
                         const float* __restrict__ g, const float* __restrict__ b,
                         const float* __restrict__ gw, const float* __restrict__ gb,
                         float* __restrict__ out, __half* __restrict__ out16,
                         float* __restrict__ gate, float* __restrict__ gate_out)
{
    __shared__ float red[256];
    __shared__ float wsum[8][Ec];
    __shared__ float logits[Ec];
    const int m = blockIdx.x;
    const size_t base = (size_t)m * Dc;
    const int tid = threadIdx.x, wid = tid >> 5, lane = tid & 31;

    float v[4]; float s = 0.f;
#pragma unroll
    for (int i = 0; i < 4; i++) { const int c = tid + i * 256; v[i] = x[base + c] + r[base + c]; s += v[i]; }
    red[tid] = s; __syncthreads();
    for (int st = 128; st > 0; st >>= 1) { if (tid < st) red[tid] += red[tid + st]; __syncthreads(); }
    const float mean = red[0] * (1.0f / Dc); __syncthreads();
    float ss = 0.f;
#pragma unroll
    for (int i = 0; i < 4; i++) { const float d = v[i] - mean; ss += d * d; }
    red[tid] = ss; __syncthreads();
    for (int st = 128; st > 0; st >>= 1) { if (tid < st) red[tid] += red[tid + st]; __syncthreads(); }
    const float rstd = rsqrtf(red[0] * (1.0f / Dc) + LN_EPS);

    float ge[Ec];
#pragma unroll
    for (int e = 0; e < Ec; e++) ge[e] = 0.f;

#pragma unroll
    for (int i = 0; i < 4; i++) {
        const int c = tid + i * 256;
        const float o = (v[i] - mean) * rstd * g[c] + b[c];
        out[base + c] = o;
        out16[base + c] = __float2half(o);
        const float4 w0 = *(const float4*)(gw + (size_t)c * Ec);
        const float4 w1 = *(const float4*)(gw + (size_t)c * Ec + 4);
        ge[0] += o * w0.x; ge[1] += o * w0.y; ge[2] += o * w0.z; ge[3] += o * w0.w;
        ge[4] += o * w1.x; ge[5] += o * w1.y; ge[6] += o * w1.z; ge[7] += o * w1.w;
    }
    // warp reduce each expert sum
#pragma unroll
    for (int off = 16; off > 0; off >>= 1)
#pragma unroll
        for (int e = 0; e < Ec; e++)
            ge[e] += __shfl_down_sync(0xffffffffu, ge[e], off);
    if (lane == 0)
#pragma unroll
        for (int e = 0; e < Ec; e++) wsum[wid][e] = ge[e];
    __syncthreads();
    if (tid < Ec) {
        float t = gb[tid];
#pragma unroll
        for (int w = 0; w < 8; w++) t += wsum[w][tid];
        logits[tid] = t;
    }
    __syncthreads();
    if (tid == 0) {
        float mx = logits[0];
#pragma unroll
        for (int e = 1; e < Ec; e++) mx = fmaxf(mx, logits[e]);
        float p[Ec]; float sum = 0.f;
#pragma unroll
        for (int e = 0; e < Ec; e++) { p[e] = expf(logits[e] - mx); sum += p[e]; }
        const float inv = 1.0f / sum;
#pragma unroll
        for (int e = 0; e < Ec; e++) {
            const float pv = p[e] * inv;
            gate[(size_t)m * Ec + e] = pv;
            if (gate_out) gate_out[(size_t)m * Ec + e] = pv;
        }
    }
}

// fused: out = LN2( sum_e gate[e]*p2[e] + inter )
__global__ void ln2_moe(const __half* __restrict__ part, const float* __restrict__ gate,
                        const float* __restrict__ inter,
                        const float* __restrict__ g, const float* __restrict__ b,
                        float* __restrict__ out)
{
    __shared__ float red[256];
    __shared__ float gs[Ec];
    const int m = blockIdx.x, tid = threadIdx.x;
    if (tid < Ec) gs[tid] = gate[(size_t)m * Ec + tid];
    __syncthreads();
    const size_t base = (size_t)m * Dc;

    float v[4]; float s = 0.f;
#pragma unroll
    for (int i = 0; i < 2; i++) {
        const int c = tid * 2 + i * 512;
        float2 acc = *(const float2*)(inter + base + c);
#pragma unroll
        for (int e = 0; e < Ec; e++) {
            float2 f = __half22float2(*(const __half2*)(part + (size_t)e * NTOK * Dc + base + c));
            acc.x += gs[e] * f.x;
            acc.y += gs[e] * f.y;
        }
        v[2 * i] = acc.x; v[2 * i + 1] = acc.y;
        s += acc.x + acc.y;
    }
    red[tid] = s; __syncthreads();
    for (int st = 128; st > 0; st >>= 1) { if (tid < st) red[tid] += red[tid + st]; __syncthreads(); }
    const float mean = red[0] * (1.0f / Dc); __syncthreads();
    float ss = 0.f;
#pragma unroll
    for (int j = 0; j < 4; j++) { const float d = v[j] - mean; ss += d * d; }
    red[tid] = ss; __syncthreads();
    for (int st = 128; st > 0; st >>= 1) { if (tid < st) red[tid] += red[tid + st]; __syncthreads(); }
    const float rstd = rsqrtf(red[0] * (1.0f / Dc) + LN_EPS);
#pragma unroll
    for (int i = 0; i < 2; i++) {
        const int c = tid * 2 + i * 512;
        float2 o;
        o.x = (v[2 * i]     - mean) * rstd * g[c]     + b[c];
        o.y = (v[2 * i + 1] - mean) * rstd * g[c + 1] + b[c + 1];
        *(float2*)(out + base + c) = o;
    }
}

// ---------------- launch ----------------------------------------------------
extern "C" void kernel_launch(void* const* d_in, const int* in_sizes, int n_in,
                              void* d_out, int out_size)
{
    const float* hidden = (const float*)d_in[0];
    const float* mask   = (const float*)d_in[1];
    const float* wq = (const float*)d_in[2];  const float* bq = (const float*)d_in[3];
    const float* wk = (const float*)d_in[4];  const float* bk = (const float*)d_in[5];
    const float* wv = (const float*)d_in[6];  const float* bv = (const float*)d_in[7];
    const float* wo = (const float*)d_in[8];  const float* bo = (const float*)d_in[9];
    const float* ln1_g = (const float*)d_in[10]; const float* ln1_b = (const float*)d_in[11];
    const float* gate_w = (const float*)d_in[12]; const float* gate_b = (const float*)d_in[13];
    const float* w1 = (const float*)d_in[14]; const float* b1 = (const float*)d_in[15];
    const float* w2 = (const float*)d_in[16]; const float* b2 = (const float*)d_in[17];
    const float* ln2_g = (const float*)d_in[18]; const float* ln2_b = (const float*)d_in[19];

    float* f32 = nullptr;  __half* f16 = nullptr;
    cudaGetSymbolAddress((void**)&f32, g_f32);
    cudaGetSymbolAddress((void**)&f16, g_f16);

    float*  attn   = f32 + F_ATTN;
    float*  inter  = f32 + F_INT;
    float*  gate   = f32 + F_GATE;
    float*  qkvb   = f32 + F_QKVB;
    __half* hid16  = f16 + H_HID;
    __half* q16    = f16 + H_Q;
    __half* k16    = f16 + H_K;
    __half* vT16   = f16 + H_VT;
    __half* ctx16  = f16 + H_CTX;
    __half* int16_ = f16 + H_INT;
    __half* msk16  = f16 + H_MSK;
    __half* h16    = f16 + H_HB;
    __half* p2     = f16 + H_P2;
    __half* wqT = f16 + H_WQ;
    __half* woT = f16 + H_WQ + 3 * (size_t)Dc * Dc;
    __half* w1T = f16 + H_W1; __half* w2T = f16 + H_W2;

    float* out = (float*)d_out;
    float* gate_out = nullptr;
    if ((size_t)out_size >= (size_t)NTOK * Dc + (size_t)NTOK * Ec)
        gate_out = out + (size_t)NTOK * Dc;

    cudaFuncSetAttribute(hgemm<128,0>, cudaFuncAttributeMaxDynamicSharedMemorySize, SMEM_NT128);
    cudaFuncSetAttribute(hgemm<128,1>, cudaFuncAttributeMaxDynamicSharedMemorySize, SMEM_NT128);
    cudaFuncSetAttribute(hgemm<128,6>, cudaFuncAttributeMaxDynamicSharedMemorySize, SMEM_NT128);
    cudaFuncSetAttribute(hgemm<128,9>, cudaFuncAttributeMaxDynamicSharedMemorySize, SMEM_NT128);
    cudaFuncSetAttribute(flash_attn,   cudaFuncAttributeMaxDynamicSharedMemorySize, SMEM_FA);

    const dim3 blk(256);
    const dim3 tblk(32, 8);

    // 0) hidden + mask conversion + bias pack (one launch; grid sized for mask)
    conv_all<<<(int)((size_t)Bc * Sc * Sc / 4 / 256), 256>>>(
        hidden, hid16, mask, msk16, bq, bk, bv, qkvb);
    // 1) all weight transposes
    tconv_all<<<69632, tblk>>>(wq, wk, wv, wo, w1, w2, wqT);

    // 2) fused Q/K/V projection (z = 0,1,2 -> q16, k16, vT scatter)
    {
        dim3 grid(Dc / 128, NTOK / 128, 3);
        hgemm<128,9><<<grid, blk, SMEM_NT128>>>(hid16, wqT, nullptr, q16, qkvb,
            Dc, Dc, Dc, Dc, 3,
            0, 0,
            0, (long long)Dc * Dc,
            0, (long long)NTOK * Dc,
            (long long)Dc);
    }

    // 3) fused attention (q-tile 64) -> ctx16
    {
        dim3 grid(Sc / 64, Bc * Hc);
        flash_attn<<<grid, 128, SMEM_FA>>>(q16, k16, vT16, msk16, ctx16);
    }

    // 4) output projection -> fp32 attn
    {
        dim3 grid(Dc / 128, NTOK / 128, 1);
        hgemm<128,0><<<grid, blk, SMEM_NT128>>>(ctx16, woT, attn, nullptr, bo,
            Dc, Dc, Dc, Dc, 1, 0,0,0,0,0,0,0);
    }

    // 5) inter = LN1(attn + hidden) fused with gate softmax
    ln1_gate<<<NTOK, 256>>>(attn, hidden, ln1_g, ln1_b, gate_w, gate_b,
                            inter, int16_, gate, gate_out);

    // 6-7) MoE batched across experts (z = expert) — R8 128x128 config
    {
        dim3 gh(Fc / 128, NTOK / 128, Ec);
        hgemm<128,1><<<gh, blk, SMEM_NT128>>>(int16_, w1T, nullptr, h16, b1,
            Dc, Dc, Dc, Fc, Ec,
            0, 0,
            0, (long long)Dc * Fc,
            0, (long long)NTOK * Fc,
            (long long)Fc);

        dim3 gy(Dc / 128, NTOK / 128, Ec);
        hgemm<128,6><<<gy, blk, SMEM_NT128>>>(h16, w2T, nullptr, p2, b2,
            Fc, Fc, Fc, Dc, Ec,
            0, (long long)NTOK * Fc,
            0, (long long)Fc * Dc,
            0, (long long)NTOK * Dc,
            (long long)Dc);
    }

    // 8) fused gate-weighted reduce + LN2 -> out
    ln2_moe<<<NTOK, 256>>>(p2, gate, inter, ln2_g, ln2_b, out);
}

// round 14
// speedup vs baseline: 1.1326x; 1.0181x over previous
#include <cuda_runtime.h>
#include <cuda_fp16.h>
#include <math.h>
#include <stdint.h>

// ---------------- problem constants ----------------
#define Bc 2
#define Sc 2048
#define Dc 1024
#define Hc 16
#define DHc 64
#define Fc 4096
#define Ec 8
#define NTOK (Bc * Sc)
#define LN_EPS 1e-6f

// ---------------- fp32 scratch ----------------
static const size_t F_ATTN  = 0;
static const size_t F_INT   = F_ATTN + (size_t)NTOK * Dc;
static const size_t F_GATE  = F_INT  + (size_t)NTOK * Dc;
static const size_t F_QKVB  = F_GATE + (size_t)NTOK * Ec;
static const size_t F_TOTAL = F_QKVB + 3 * (size_t)Dc;
__device__ float g_f32[F_TOTAL];

// ---------------- fp16 scratch ----------------
static const size_t H_HID  = 0;
static const size_t H_Q    = H_HID + (size_t)NTOK * Dc;
static const size_t H_K    = H_Q   + (size_t)NTOK * Dc;     // contiguous with Q
static const size_t H_VT   = H_K   + (size_t)NTOK * Dc;     // [B,H,DH,S]
static const size_t H_CTX  = H_VT  + (size_t)NTOK * Dc;
static const size_t H_INT  = H_CTX + (size_t)NTOK * Dc;
static const size_t H_MSK  = H_INT + (size_t)NTOK * Dc;                 // fp16 mask [B,S,S]
static const size_t H_HB   = H_MSK + (size_t)Bc * Sc * Sc;
static const size_t H_P2   = H_HB  + (size_t)Ec * NTOK * Fc;
static const size_t H_WQ   = H_P2  + (size_t)Ec * NTOK * Dc;
static const size_t H_W1   = H_WQ  + 4 * (size_t)Dc * Dc;   // [E][N=F,K=D]
static const size_t H_W2   = H_W1  + (size_t)Ec * Dc * Fc;  // [E][N=D,K=F]
static const size_t H_TOTAL= H_W2  + (size_t)Ec * Fc * Dc;
__device__ __half g_f16[H_TOTAL];

// ---------------- PTX helpers ----------------
__device__ __forceinline__ uint32_t smem_u32(const void* p) {
    uint32_t a;
    asm("{ .reg .u64 t; cvta.to.shared.u64 t, %1; cvt.u32.u64 %0, t; }" : "=r"(a) : "l"(p));
    return a;
}
__device__ __forceinline__ void cp16(uint32_t s, const void* g) {
    asm volatile("cp.async.cg.shared.global [%0], [%1], 16;" :: "r"(s), "l"(g));
}
#define CP_COMMIT() asm volatile("cp.async.commit_group;" ::: "memory")
#define CP_WAIT(n)  asm volatile("cp.async.wait_group %0;" :: "n"(n) : "memory")

__device__ __forceinline__ void ldm_x4(uint32_t* r, uint32_t addr) {
    asm volatile("ldmatrix.sync.aligned.m8n8.x4.shared.b16 {%0,%1,%2,%3}, [%4];"
        : "=r"(r[0]), "=r"(r[1]), "=r"(r[2]), "=r"(r[3]) : "r"(addr));
}
__device__ __forceinline__ void mma16816(float* c, const uint32_t* a, const uint32_t* b) {
    asm volatile(
        "mma.sync.aligned.m16n8k16.row.col.f32.f16.f16.f32 "
        "{%0,%1,%2,%3}, {%4,%5,%6,%7}, {%8,%9}, {%0,%1,%2,%3};"
        : "+f"(c[0]), "+f"(c[1]), "+f"(c[2]), "+f"(c[3])
        : "r"(a[0]), "r"(a[1]), "r"(a[2]), "r"(a[3]), "r"(b[0]), "r"(b[1]));
}

__device__ __forceinline__ float gelu_tanh(float x) {
    float x3 = x * x * x;
    float t  = tanhf(0.7978845608028654f * (x + 0.044715f * x3));
    return 0.5f * x * (1.0f + t);
}
__device__ __forceinline__ uint32_t pack_h2(float a, float b) {
    __half2 h = __floats2half2_rn(a, b);
    return *reinterpret_cast<uint32_t*>(&h);
}

// ============================================================================
// HMMA GEMM (R8 core, verbatim): C[128,NT] = A[M,K] * B[N,K]^T, BK=64, 3 stages
// EPI: 0 = fp32 C = acc + bias?
//      1 = fp16 C16 = gelu(acc + bias)
//      6 = fp16 C16 = acc + bias?
//      9 = QKV route: hh<2 plain fp16; hh==2 V^T scatter
// ============================================================================
#define SPAD 72
#define STAGES 3

template <int NT, int EPI>
__global__ __launch_bounds__(256)
void hgemm(const __half* __restrict__ A, const __half* __restrict__ B,
           float* __restrict__ C, __half* __restrict__ C16,
           const float* __restrict__ bias,
           int K, int lda, int ldb, int ldc, int Hdim,
           long long aOB, long long aOH, long long bOB, long long bOH,
           long long cOB, long long cOH, long long biasOH)
{
    extern __shared__ __half smem[];

    const int tid = threadIdx.x, wid = tid >> 5, lane = tid & 31;
    const int wm = wid & 3, wn = wid >> 2;
    constexpr int WN = NT / 2;
    constexpr int NF = WN / 8;

    const int m0 = blockIdx.y * 128, n0 = blockIdx.x * NT;
    const int z = blockIdx.z, bb = z / Hdim, hh = z - bb * Hdim;
    A += (size_t)bb * aOB + (size_t)hh * aOH;
    B += (size_t)bb * bOB + (size_t)hh * bOH;
    if (bias) bias += (size_t)hh * biasOH;
    const long long coff = (long long)bb * cOB + (long long)hh * cOH;

    const uint32_t ABUF = 128 * SPAD * 2;
    const uint32_t BBUF = (uint32_t)NT * SPAD * 2;
    const uint32_t abase = smem_u32(smem);
    const uint32_t bbase = abase + STAGES * ABUF;

    const uint32_t a_off = (uint32_t)((wm * 32 + (lane & 15)) * (SPAD * 2) + ((lane >> 4) * 8) * 2);
    const uint32_t b_off = (uint32_t)((wn * WN + (lane & 7) + ((lane >> 4) << 3)) * (SPAD * 2)
                                      + (((lane >> 3) & 1) * 8) * 2);

    float acc[2][NF][4];
#pragma unroll
    for (int i = 0; i < 2; i++)
#pragma unroll
        for (int j = 0; j < NF; j++)
#pragma unroll
            for (int r = 0; r < 4; r++) acc[i][j][r] = 0.0f;

    const int nc = K >> 6;

    auto load_tile = [&](int c, int buf) {
        const __half* Ab = A + (size_t)m0 * lda + (size_t)c * 64;
#pragma unroll
        for (int it = 0; it < 4; it++) {
            int lin = it * 256 + tid;
            int row = lin >> 3, seg = lin & 7;
            cp16(abase + buf * ABUF + row * (SPAD * 2) + seg * 16,
                 Ab + (size_t)row * lda + seg * 8);
        }
        const __half* Bb = B + (size_t)n0 * ldb + (size_t)c * 64;
#pragma unroll
        for (int it = 0; it < NT / 32; it++) {
            int lin = it * 256 + tid;
            int row = lin >> 3, seg = lin & 7;
            cp16(bbase + buf * BBUF + row * (SPAD * 2) + seg * 16,
                 Bb + (size_t)row * ldb + seg * 8);
        }
    };

#pragma unroll
    for (int s = 0; s < STAGES - 1; s++) {
        if (s < nc) load_tile(s, s);
        CP_COMMIT();
    }

    for (int c = 0; c < nc; c++) {
        CP_WAIT(STAGES - 2);
        __syncthreads();
        const int nxt = c + STAGES - 1;
        if (nxt < nc) load_tile(nxt, nxt % STAGES);
        CP_COMMIT();

        const int buf = c % STAGES;
        const uint32_t ab = abase + buf * ABUF + a_off;
        const uint32_t bbf = bbase + buf * BBUF + b_off;

#pragma unroll
        for (int ks = 0; ks < 4; ks++) {
            uint32_t af[2][4];
#pragma unroll
            for (int mi = 0; mi < 2; mi++)
                ldm_x4(af[mi], ab + mi * 16 * (SPAD * 2) + ks * 32);
            uint32_t bf[NF][2];
#pragma unroll
            for (int p = 0; p < NF / 2; p++) {
                uint32_t t[4];
                ldm_x4(t, bbf + p * 16 * (SPAD * 2) + ks * 32);
                bf[2 * p][0] = t[0]; bf[2 * p][1] = t[1];
                bf[2 * p + 1][0] = t[2]; bf[2 * p + 1][1] = t[3];
            }
#pragma unroll
            for (int mi = 0; mi < 2; mi++)
#pragma unroll
                for (int nj = 0; nj < NF; nj++)
                    mma16816(acc[mi][nj], af[mi], bf[nj]);
        }
    }

#pragma unroll
    for (int mi = 0; mi < 2; mi++) {
#pragma unroll
        for (int nj = 0; nj < NF; nj++) {
            const int r0 = m0 + wm * 32 + mi * 16 + (lane >> 2);
            const int cc = n0 + wn * WN + nj * 8 + (lane & 3) * 2;
#pragma unroll
            for (int h = 0; h < 2; h++) {
                const int row = r0 + h * 8;
                const float v0 = acc[mi][nj][2 * h + 0];
                const float v1 = acc[mi][nj][2 * h + 1];
                if (EPI == 0) {
                    float b0 = bias ? bias[cc] : 0.f, b1 = bias ? bias[cc + 1] : 0.f;
                    float2 o = make_float2(v0 + b0, v1 + b1);
                    *(float2*)(C + coff + (size_t)row * ldc + cc) = o;
                } else if (EPI == 1 || EPI == 6) {
                    float o0 = v0 + (bias ? bias[cc] : 0.f);
                    float o1 = v1 + (bias ? bias[cc + 1] : 0.f);
                    if (EPI == 1) { o0 = gelu_tanh(o0); o1 = gelu_tanh(o1); }
                    *(uint32_t*)(C16 + coff + (size_t)row * ldc + cc) = pack_h2(o0, o1);
                } else if (EPI == 9) {
                    float o0 = v0 + bias[cc];
                    float o1 = v1 + bias[cc + 1];
                    if (hh < 2) {
                        *(uint32_t*)(C16 + coff + (size_t)row * ldc + cc) = pack_h2(o0, o1);
                    } else {
                        const int b_ = row >> 11, s_ = row & 2047;
                        const int h0 = cc >> 6, d0 = cc & 63;
                        const int h1 = (cc + 1) >> 6, d1 = (cc + 1) & 63;
                        C16[coff + ((size_t)((b_ * Hc + h0) * DHc + d0)) * Sc + s_] = __float2half(o0);
                        C16[coff + ((size_t)((b_ * Hc + h1) * DHc + d1)) * Sc + s_] = __float2half(o1);
                    }
                }
            }
        }
    }
}

static const int SMEM_NT128 = STAGES * (128 + 128) * SPAD * 2;  // 110592

// ============================================================================
// FlashAttention-2 fused attention, q-tile 64, XOR-swizzled smem (no padding).
// Q/K rows 128B, V rows 256B; swizzle: byte chunk c ^= (row&7)<<4.
// Smem 72 KB -> 3 CTAs/SM (launch_bounds(128,3) caps regs at 170).
// ============================================================================
static const int KROWB = 128;     // Q/K row bytes
static const int VROWB = 256;     // V^T row bytes
static const int SMEM_FA = 64 * KROWB + 2 * 128 * KROWB + 2 * 64 * VROWB; // 73728

__global__ __launch_bounds__(128, 3)
void flash_attn(const __half* __restrict__ Qg, const __half* __restrict__ Kg,
                const __half* __restrict__ Vt, const __half* __restrict__ Mk,
                __half* __restrict__ Og)
{
    extern __shared__ __half sm[];
    const int tid = threadIdx.x, wid = tid >> 5, lane = tid & 31;
    const int q0 = blockIdx.x * 64;
    const int z = blockIdx.y, bb = z >> 4, hh = z & 15;

    const uint32_t qs  = smem_u32(sm);
    const uint32_t ks0 = qs + 64 * KROWB;
    const uint32_t KBUF = 128 * KROWB;
    const uint32_t vs0 = ks0 + 2 * KBUF;
    const uint32_t VBUF = 64 * VROWB;

    const __half* Qb = Qg + ((size_t)bb * Sc + q0) * Dc + hh * DHc;
    const __half* Kb = Kg + (size_t)bb * Sc * Dc + hh * DHc;
    const __half* Vb = Vt + ((size_t)(bb * Hc + hh)) * DHc * Sc;
    const __half* Mb = Mk + (size_t)bb * Sc * Sc;

    auto loadKV = [&](int t, int buf) {
        const __half* ksrc = Kb + (size_t)(t * 128) * Dc;
#pragma unroll
        for (int it = 0; it < 8; it++) {
            int lin = it * 128 + tid, row = lin >> 3, seg = lin & 7;
            uint32_t c = (uint32_t)(seg * 16) ^ (((uint32_t)row & 7u) << 4);
            cp16(ks0 + buf * KBUF + row * KROWB + c, ksrc + (size_t)row * Dc + seg * 8);
        }
#pragma unroll
        for (int it = 0; it < 8; it++) {
            int lin = it * 128 + tid, row = lin >> 4, seg = lin & 15;
            uint32_t c = (uint32_t)(seg * 16) ^ (((uint32_t)row & 7u) << 4);
            cp16(vs0 + buf * VBUF + row * VROWB + c,
                 Vb + (size_t)row * Sc + t * 128 + seg * 8);
        }
    };

    // prologue: Q + KV(0)
#pragma unroll
    for (int it = 0; it < 4; it++) {
        int lin = it * 128 + tid, row = lin >> 3, seg = lin & 7;
        uint32_t c = (uint32_t)(seg * 16) ^ (((uint32_t)row & 7u) << 4);
        cp16(qs + row * KROWB + c, Qb + (size_t)row * Dc + seg * 8);
    }
    loadKV(0, 0);
    CP_COMMIT();

    // ---- per-thread swizzle-folded constants
    const uint32_t xm   = ((uint32_t)lane & 7u) << 4;      // row-xor mask (bits 4-6)
    const uint32_t xm60 = xm & 0x60;                       // bits 5-6 (xor with ks*32)
    const uint32_t xm10 = xm & 0x10;                       // bit 4
    // Q: row = wid*16 + (lane&15); col sel = (lane>>4)*16
    const uint32_t qrb = qs + (uint32_t)(wid * 16 + (lane & 15)) * KROWB
                       + (((uint32_t)(lane >> 4) * 16) ^ xm10);
    // K/V: row = (lane&7) + ((lane>>4)<<3); col sel = ((lane>>3)&1)*16
    const uint32_t kvsel = (((uint32_t)(lane >> 3) & 1u) * 16) ^ xm10;
    const uint32_t krb = (uint32_t)((lane & 7) + ((lane >> 4) << 3)) * KROWB + kvsel;
    const uint32_t vrb = (uint32_t)((lane & 7) + ((lane >> 4) << 3)) * VROWB + kvsel;

    const int r = lane >> 2;
    const int qrow = q0 + wid * 16 + r;

    float o[8][4];
#pragma unroll
    for (int j = 0; j < 8; j++) { o[j][0] = o[j][1] = o[j][2] = o[j][3] = 0.f; }
    float rm0 = -1e30f, rm1 = -1e30f, rl0 = 0.f, rl1 = 0.f;

    for (int t = 0; t < Sc / 128; t++) {
        __syncthreads();
        if (t + 1 < Sc / 128) loadKV(t + 1, (t + 1) & 1);
        CP_COMMIT();
        CP_WAIT(1);
        __syncthreads();

        const uint32_t kb = ks0 + (t & 1) * KBUF + krb;
        const uint32_t vb = vs0 + (t & 1) * VBUF + vrb;

        // ---- S = Q K^T
        float s[16][4];
#pragma unroll
        for (int j = 0; j < 16; j++) { s[j][0] = s[j][1] = s[j][2] = s[j][3] = 0.f; }
#pragma unroll
        for (int ks = 0; ks < 4; ks++) {
            uint32_t af[4];
            ldm_x4(af, qrb + ((uint32_t)(ks * 32) ^ xm60));
#pragma unroll
            for (int p = 0; p < 8; p++) {
                uint32_t tt[4];
                ldm_x4(tt, kb + p * 16 * KROWB + ((uint32_t)(ks * 32) ^ xm60));
                mma16816(s[2 * p], af, tt);
                mma16816(s[2 * p + 1], af, tt + 2);
            }
        }

        // ---- scale + mask + row max
        const __half* mr0 = Mb + (size_t)qrow * Sc + t * 128 + (lane & 3) * 2;
        const __half* mr1 = mr0 + 8 * Sc;
        float tm0 = -1e30f, tm1 = -1e30f;
#pragma unroll
        for (int j = 0; j < 16; j++) {
            float2 m0 = __half22float2(*(const __half2*)(mr0 + j * 8));
            float2 m1 = __half22float2(*(const __half2*)(mr1 + j * 8));
            s[j][0] = s[j][0] * 0.125f + m0.x;
            s[j][1] = s[j][1] * 0.125f + m0.y;
            s[j][2] = s[j][2] * 0.125f + m1.x;
            s[j][3] = s[j][3] * 0.125f + m1.y;
            tm0 = fmaxf(tm0, fmaxf(s[j][0], s[j][1]));
            tm1 = fmaxf(tm1, fmaxf(s[j][2], s[j][3]));
        }
#pragma unroll
        for (int off = 1; off <= 2; off <<= 1) {
            tm0 = fmaxf(tm0, __shfl_xor_sync(0xffffffffu, tm0, off));
            tm1 = fmaxf(tm1, __shfl_xor_sync(0xffffffffu, tm1, off));
        }
        const float mn0 = fmaxf(rm0, tm0), mn1 = fmaxf(rm1, tm1);
        const float cr0 = __expf(rm0 - mn0), cr1 = __expf(rm1 - mn1);
        rm0 = mn0; rm1 = mn1;

        // ---- exp + pack P
        uint32_t pk[16][2];
        float ps0 = 0.f, ps1 = 0.f;
#pragma unroll
        for (int j = 0; j < 16; j++) {
            float p0 = __expf(s[j][0] - mn0), p1 = __expf(s[j][1] - mn0);
            float p2 = __expf(s[j][2] - mn1), p3 = __expf(s[j][3] - mn1);
            ps0 += p0 + p1; ps1 += p2 + p3;
            pk[j][0] = pack_h2(p0, p1);
            pk[j][1] = pack_h2(p2, p3);
        }
#pragma unroll
        for (int off = 1; off <= 2; off <<= 1) {
            ps0 += __shfl_xor_sync(0xffffffffu, ps0, off);
            ps1 += __shfl_xor_sync(0xffffffffu, ps1, off);
        }
        rl0 = rl0 * cr0 + ps0;
        rl1 = rl1 * cr1 + ps1;

        // ---- rescale O
#pragma unroll
        for (int j = 0; j < 8; j++) {
            o[j][0] *= cr0; o[j][1] *= cr0;
            o[j][2] *= cr1; o[j][3] *= cr1;
        }

        // ---- O += P @ V
#pragma unroll
        for (int ks = 0; ks < 8; ks++) {
            uint32_t af[4] = { pk[2 * ks][0], pk[2 * ks][1], pk[2 * ks + 1][0], pk[2 * ks + 1][1] };
#pragma unroll
            for (int p = 0; p < 4; p++) {
                uint32_t tt[4];
                ldm_x4(tt, vb + p * 16 * VROWB + ((uint32_t)(ks * 32) ^ xm60));
                mma16816(o[2 * p], af, tt);
                mma16816(o[2 * p + 1], af, tt + 2);
            }
        }
    }

    // ---- write O
    const float i0 = 1.0f / rl0, i1 = 1.0f / rl1;
    __half* or0 = Og + ((size_t)bb * Sc + qrow) * Dc + hh * DHc + (lane & 3) * 2;
    __half* or1 = or0 + 8 * Dc;
#pragma unroll
    for (int j = 0; j < 8; j++) {
        *(uint32_t*)(or0 + j * 8) = pack_h2(o[j][0] * i0, o[j][1] * i0);
        *(uint32_t*)(or1 + j * 8) = pack_h2(o[j][2] * i1, o[j][3] * i1);
    }
}

// ---------------- small kernels ----------------
// one launch: hidden fp32->fp16, mask fp32->fp16, QKV bias pack
__global__ void conv_all(const float* __restrict__ hid, __half* __restrict__ hid16,
                         const float* __restrict__ msk, __half* __restrict__ msk16,
                         const float* __restrict__ bq, const float* __restrict__ bk,
                         const float* __restrict__ bv, float* __restrict__ qkvb)
{
    int i = blockIdx.x * blockDim.x + threadIdx.x;
    {
        float4 v = ((const float4*)msk)[i];
        uint2 u;
        u.x = pack_h2(v.x, v.y); u.y = pack_h2(v.z, v.w);
        ((uint2*)msk16)[i] = u;
    }
    if (i < NTOK * Dc / 4) {
        float4 v = ((const float4*)hid)[i];
        uint2 u;
        u.x = pack_h2(v.x, v.y); u.y = pack_h2(v.z, v.w);
        ((uint2*)hid16)[i] = u;
    }
    if (i < Dc) { qkvb[i] = bq[i]; qkvb[Dc + i] = bk[i]; qkvb[2 * Dc + i] = bv[i]; }
}

__global__ void tconv_all(const float* __restrict__ wq, const float* __restrict__ wk,
                          const float* __restrict__ wv, const float* __restrict__ wo,
                          const float* __restrict__ w1, const float* __restrict__ w2,
                          __half* __restrict__ dstbase)
{
    __shared__ float t[32][33];
    int b = blockIdx.x;
    const float* src; __half* dst; int K, N;
    if (b < 4096) {
        int m = b >> 10; b &= 1023;
        src = (m == 0) ? wq : (m == 1) ? wk : (m == 2) ? wv : wo;
        dst = dstbase + (size_t)m * Dc * Dc; K = Dc; N = Dc;
    } else if (b < 4096 + 32768) {
        b -= 4096; int e = b >> 12; b &= 4095;
        src = w1 + (size_t)e * Dc * Fc;
        dst = dstbase + 4 * (size_t)Dc * Dc + (size_t)e * Dc * Fc; K = Dc; N = Fc;
    } else {
        b -= 36864; int e = b >> 12; b &= 4095;
        src = w2 + (size_t)e * Fc * Dc;
        dst = dstbase + 4 * (size_t)Dc * Dc + (size_t)Ec * Dc * Fc + (size_t)e * Fc * Dc;
        K = Fc; N = Dc;
    }
    const int ntx = N / 32;
    const int k0 = (b / ntx) * 32, n0 = (b % ntx) * 32;
    const int x = threadIdx.x, y = threadIdx.y;
#pragma unroll
    for (int i = 0; i < 32; i += 8)
        t[y + i][x] = src[(size_t)(k0 + y + i) * N + n0 + x];
    __syncthreads();
#pragma unroll
    for (int i = 0; i < 32; i += 8)
        dst[(size_t)(n0 + y + i) * K + k0 + x] = __float2half(t[x][y + i]);
}

// LN1(attn + hidden) -> inter (fp32 + fp16)  AND  gate = softmax(inter @ gw + gb)
__global__ void ln1_gate(const float* __restrict__ x, const float* __restrict__ r,
                         const float* __restrict__ g, const float* __restrict__ b,
                         const float* __restrict__ gw, const float* __restrict__ gb,
                         float* __restrict__ out, __half* __restrict__ out16,
                         float* __restrict__ gate, float* __restrict__ gate_out)
{
    __shared__ float red[256];
    __shared__ float wsum[8][Ec];
    __shared__ float logits[Ec];
    const int m = blockIdx.x;
    const size_t base = (size_t)m * Dc;
    const int tid = threadIdx.x, wid = tid >> 5, lane = tid & 31;

    float v[4]; float s = 0.f;
#pragma unroll
    for (int i = 0; i < 4; i++) { const int c = tid + i * 256; v[i] = x[base + c] + r[base + c]; s += v[i]; }
    red[tid] = s; __syncthreads();
    for (int st = 128; st > 0; st >>= 1) { if (tid < st) red[tid] += red[tid + st]; __syncthreads(); }
    const float mean = red[0] * (1.0f / Dc); __syncthreads();
    float ss = 0.f;
#pragma unroll
    for (int i = 0; i < 4; i++) { const float d = v[i] - mean; ss += d * d; }
    red[tid] = ss; __syncthreads();
    for (int st = 128; st > 0; st >>= 1) { if (tid < st) red[tid] += red[tid + st]; __syncthreads(); }
    const float rstd = rsqrtf(red[0] * (1.0f / Dc) + LN_EPS);

    float ge[Ec];
#pragma unroll
    for (int e = 0; e < Ec; e++) ge[e] = 0.f;

#pragma unroll
    for (int i = 0; i < 4; i++) {
        const int c = tid + i * 256;
        const float o = (v[i] - mean) * rstd * g[c] + b[c];
        out[base + c] = o;
        out16[base + c] = __float2half(o);
        const float4 w0 = *(const float4*)(gw + (size_t)c * Ec);
        const float4 w1 = *(const float4*)(gw + (size_t)c * Ec + 4);
        ge[0] += o * w0.x; ge[1] += o * w0.y; ge[2] += o * w0.z; ge[3] += o * w0.w;
        ge[4] += o * w1.x; ge[5] += o * w1.y; ge[6] += o * w1.z; ge[7] += o * w1.w;
    }
#pragma unroll
    for (int off = 16; off > 0; off >>= 1)
#pragma unroll
        for (int e = 0; e < Ec; e++)
            ge[e] += __shfl_down_sync(0xffffffffu, ge[e], off);
    if (lane == 0)
#pragma unroll
        for (int e = 0; e < Ec; e++) wsum[wid][e] = ge[e];
    __syncthreads();
    if (tid < Ec) {
        float t = gb[tid];
#pragma unroll
        for (int w = 0; w < 8; w++) t += wsum[w][tid];
        logits[tid] = t;
    }
    __syncthreads();
    if (tid == 0) {
        float mx = logits[0];
#pragma unroll
        for (int e = 1; e < Ec; e++) mx = fmaxf(mx, logits[e]);
        float p[Ec]; float sum = 0.f;
#pragma unroll
        for (int e = 0; e < Ec; e++) { p[e] = expf(logits[e] - mx); sum += p[e]; }
        const float inv = 1.0f / sum;
#pragma unroll
        for (int e = 0; e < Ec; e++) {
            const float pv = p[e] * inv;
            gate[(size_t)m * Ec + e] = pv;
            if (gate_out) gate_out[(size_t)m * Ec + e] = pv;
        }
    }
}

// fused: out = LN2( sum_e gate[e]*p2[e] + inter )
__global__ void ln2_moe(const __half* __restrict__ part, const float* __restrict__ gate,
                        const float* __restrict__ inter,
                        const float* __restrict__ g, const float* __restrict__ b,
                        float* __restrict__ out)
{
    __shared__ float red[256];
    __shared__ float gs[Ec];
    const int m = blockIdx.x, tid = threadIdx.x;
    if (tid < Ec) gs[tid] = gate[(size_t)m * Ec + tid];
    __syncthreads();
    const size_t base = (size_t)m * Dc;

    float v[4]; float s = 0.f;
#pragma unroll
    for (int i = 0; i < 2; i++) {
        const int c = tid * 2 + i * 512;
        float2 acc = *(const float2*)(inter + base + c);
#pragma unroll
        for (int e = 0; e < Ec; e++) {
            float2 f = __half22float2(*(const __half2*)(part + (size_t)e * NTOK * Dc + base + c));
            acc.x += gs[e] * f.x;
            acc.y += gs[e] * f.y;
        }
        v[2 * i] = acc.x; v[2 * i + 1] = acc.y;
        s += acc.x + acc.y;
    }
    red[tid] = s; __syncthreads();
    for (int st = 128; st > 0; st >>= 1) { if (tid < st) red[tid] += red[tid + st]; __syncthreads(); }
    const float mean = red[0] * (1.0f / Dc); __syncthreads();
    float ss = 0.f;
#pragma unroll
    for (int j = 0; j < 4; j++) { const float d = v[j] - mean; ss += d * d; }
    red[tid] = ss; __syncthreads();
    for (int st = 128; st > 0; st >>= 1) { if (tid < st) red[tid] += red[tid + st]; __syncthreads(); }
    const float rstd = rsqrtf(red[0] * (1.0f / Dc) + LN_EPS);
#pragma unroll
    for (int i = 0; i < 2; i++) {
        const int c = tid * 2 + i * 512;
        float2 o;
        o.x = (v[2 * i]     - mean) * rstd * g[c]     + b[c];
        o.y = (v[2 * i + 1] - mean) * rstd * g[c + 1] + b[c + 1];
        *(float2*)(out + base + c) = o;
    }
}

// ---------------- launch ----------------------------------------------------
extern "C" void kernel_launch(void* const* d_in, const int* in_sizes, int n_in,
                              void* d_out, int out_size)
{
    const float* hidden = (const float*)d_in[0];
    const float* mask   = (const float*)d_in[1];
    const float* wq = (const float*)d_in[2];  const float* bq = (const float*)d_in[3];
    const float* wk = (const float*)d_in[4];  const float* bk = (const float*)d_in[5];
    const float* wv = (const float*)d_in[6];  const float* bv = (const float*)d_in[7];
    const float* wo = (const float*)d_in[8];  const float* bo = (const float*)d_in[9];
    const float* ln1_g = (const float*)d_in[10]; const float* ln1_b = (const float*)d_in[11];
    const float* gate_w = (const float*)d_in[12]; const float* gate_b = (const float*)d_in[13];
    const float* w1 = (const float*)d_in[14]; const float* b1 = (const float*)d_in[15];
    const float* w2 = (const float*)d_in[16]; const float* b2 = (const float*)d_in[17];
    const float* ln2_g = (const float*)d_in[18]; const float* ln2_b = (const float*)d_in[19];

    float* f32 = nullptr;  __half* f16 = nullptr;
    cudaGetSymbolAddress((void**)&f32, g_f32);
    cudaGetSymbolAddress((void**)&f16, g_f16);

    float*  attn   = f32 + F_ATTN;
    float*  inter  = f32 + F_INT;
    float*  gate   = f32 + F_GATE;
    float*  qkvb   = f32 + F_QKVB;
    __half* hid16  = f16 + H_HID;
    __half* q16    = f16 + H_Q;
    __half* k16    = f16 + H_K;
    __half* vT16   = f16 + H_VT;
    __half* ctx16  = f16 + H_CTX;
    __half* int16_ = f16 + H_INT;
    __half* msk16  = f16 + H_MSK;
    __half* h16    = f16 + H_HB;
    __half* p2     = f16 + H_P2;
    __half* wqT = f16 + H_WQ;
    __half* woT = f16 + H_WQ + 3 * (size_t)Dc * Dc;
    __half* w1T = f16 + H_W1; __half* w2T = f16 + H_W2;

    float* out = (float*)d_out;
    float* gate_out = nullptr;
    if ((size_t)out_size >= (size_t)NTOK * Dc + (size_t)NTOK * Ec)
        gate_out = out + (size_t)NTOK * Dc;

    cudaFuncSetAttribute(hgemm<128,0>, cudaFuncAttributeMaxDynamicSharedMemorySize, SMEM_NT128);
    cudaFuncSetAttribute(hgemm<128,1>, cudaFuncAttributeMaxDynamicSharedMemorySize, SMEM_NT128);
    cudaFuncSetAttribute(hgemm<128,6>, cudaFuncAttributeMaxDynamicSharedMemorySize, SMEM_NT128);
    cudaFuncSetAttribute(hgemm<128,9>, cudaFuncAttributeMaxDynamicSharedMemorySize, SMEM_NT128);
    cudaFuncSetAttribute(flash_attn,   cudaFuncAttributeMaxDynamicSharedMemorySize, SMEM_FA);

    const dim3 blk(256);
    const dim3 tblk(32, 8);

    // 0) hidden + mask conversion + bias pack (one launch; grid sized for mask)
    conv_all<<<(int)((size_t)Bc * Sc * Sc / 4 / 256), 256>>>(
        hidden, hid16, mask, msk16, bq, bk, bv, qkvb);
    // 1) all weight transposes
    tconv_all<<<69632, tblk>>>(wq, wk, wv, wo, w1, w2, wqT);

    // 2) fused Q/K/V projection (z = 0,1,2 -> q16, k16, vT scatter)
    {
        dim3 grid(Dc / 128, NTOK / 128, 3);
        hgemm<128,9><<<grid, blk, SMEM_NT128>>>(hid16, wqT, nullptr, q16, qkvb,
            Dc, Dc, Dc, Dc, 3,
            0, 0,
            0, (long long)Dc * Dc,
            0, (long long)NTOK * Dc,
            (long long)Dc);
    }

    // 3) fused attention (q-tile 64, swizzled smem) -> ctx16
    {
        dim3 grid(Sc / 64, Bc * Hc);
        flash_attn<<<grid, 128, SMEM_FA>>>(q16, k16, vT16, msk16, ctx16);
    }

    // 4) output projection -> fp32 attn
    {
        dim3 grid(Dc / 128, NTOK / 128, 1);
        hgemm<128,0><<<grid, blk, SMEM_NT128>>>(ctx16, woT, attn, nullptr, bo,
            Dc, Dc, Dc, Dc, 1, 0,0,0,0,0,0,0);
    }

    // 5) inter = LN1(attn + hidden) fused with gate softmax
    ln1_gate<<<NTOK, 256>>>(attn, hidden, ln1_g, ln1_b, gate_w, gate_b,
                            inter, int16_, gate, gate_out);

    // 6-7) MoE batched across experts (z = expert)
    {
        dim3 gh(Fc / 128, NTOK / 128, Ec);
        hgemm<128,1><<<gh, blk, SMEM_NT128>>>(int16_, w1T, nullptr, h16, b1,
            Dc, Dc, Dc, Fc, Ec,
            0, 0,
            0, (long long)Dc * Fc,
            0, (long long)NTOK * Fc,
            (long long)Fc);

        dim3 gy(Dc / 128, NTOK / 128, Ec);
        hgemm<128,6><<<gy, blk, SMEM_NT128>>>(h16, w2T, nullptr, p2, b2,
            Fc, Fc, Fc, Dc, Ec,
            0, (long long)NTOK * Fc,
            0, (long long)Fc * Dc,
            0, (long long)NTOK * Dc,
            (long long)Dc);
    }

    // 8) fused gate-weighted reduce + LN2 -> out
    ln2_moe<<<NTOK, 256>>>(p2, gate, inter, ln2_g, ln2_b, out);
}

// round 15
// speedup vs baseline: 1.1426x; 1.0089x over previous
#include <cuda_runtime.h>
#include <cuda_fp16.h>
#include <math.h>
#include <stdint.h>

// ---------------- problem constants ----------------
#define Bc 2
#define Sc 2048
#define Dc 1024
#define Hc 16
#define DHc 64
#define Fc 4096
#define Ec 8
#define NTOK (Bc * Sc)
#define LN_EPS 1e-6f

// ---------------- fp32 scratch ----------------
static const size_t F_ATTN  = 0;
static const size_t F_INT   = F_ATTN + (size_t)NTOK * Dc;
static const size_t F_GATE  = F_INT  + (size_t)NTOK * Dc;
static const size_t F_QKVB  = F_GATE + (size_t)NTOK * Ec;
static const size_t F_TOTAL = F_QKVB + 3 * (size_t)Dc;
__device__ float g_f32[F_TOTAL];

// ---------------- fp16 scratch ----------------
static const size_t H_HID  = 0;
static const size_t H_Q    = H_HID + (size_t)NTOK * Dc;
static const size_t H_K    = H_Q   + (size_t)NTOK * Dc;     // contiguous with Q
static const size_t H_VT   = H_K   + (size_t)NTOK * Dc;     // [B,H,DH,S]
static const size_t H_CTX  = H_VT  + (size_t)NTOK * Dc;
static const size_t H_INT  = H_CTX + (size_t)NTOK * Dc;
static const size_t H_MSK  = H_INT + (size_t)NTOK * Dc;                 // fp16 mask [B,S,S]
static const size_t H_HB   = H_MSK + (size_t)Bc * Sc * Sc;
static const size_t H_P2   = H_HB  + (size_t)Ec * NTOK * Fc;
static const size_t H_WQ   = H_P2  + (size_t)Ec * NTOK * Dc;
static const size_t H_W1   = H_WQ  + 4 * (size_t)Dc * Dc;   // [E][N=F,K=D]
static const size_t H_W2   = H_W1  + (size_t)Ec * Dc * Fc;  // [E][N=D,K=F]
static const size_t H_TOTAL= H_W2  + (size_t)Ec * Fc * Dc;
__device__ __half g_f16[H_TOTAL];

// ---------------- PTX helpers ----------------
__device__ __forceinline__ uint32_t smem_u32(const void* p) {
    uint32_t a;
    asm("{ .reg .u64 t; cvta.to.shared.u64 t, %1; cvt.u32.u64 %0, t; }" : "=r"(a) : "l"(p));
    return a;
}
__device__ __forceinline__ void cp16(uint32_t s, const void* g) {
    asm volatile("cp.async.cg.shared.global [%0], [%1], 16;" :: "r"(s), "l"(g));
}
#define CP_COMMIT() asm volatile("cp.async.commit_group;" ::: "memory")
#define CP_WAIT(n)  asm volatile("cp.async.wait_group %0;" :: "n"(n) : "memory")

__device__ __forceinline__ void ldm_x4(uint32_t* r, uint32_t addr) {
    asm volatile("ldmatrix.sync.aligned.m8n8.x4.shared.b16 {%0,%1,%2,%3}, [%4];"
        : "=r"(r[0]), "=r"(r[1]), "=r"(r[2]), "=r"(r[3]) : "r"(addr));
}
__device__ __forceinline__ void mma16816(float* c, const uint32_t* a, const uint32_t* b) {
    asm volatile(
        "mma.sync.aligned.m16n8k16.row.col.f32.f16.f16.f32 "
        "{%0,%1,%2,%3}, {%4,%5,%6,%7}, {%8,%9}, {%0,%1,%2,%3};"
        : "+f"(c[0]), "+f"(c[1]), "+f"(c[2]), "+f"(c[3])
        : "r"(a[0]), "r"(a[1]), "r"(a[2]), "r"(a[3]), "r"(b[0]), "r"(b[1]));
}

__device__ __forceinline__ float gelu_tanh(float x) {
    float x3 = x * x * x;
    float t  = tanhf(0.7978845608028654f * (x + 0.044715f * x3));
    return 0.5f * x * (1.0f + t);
}
__device__ __forceinline__ uint32_t pack_h2(float a, float b) {
    __half2 h = __floats2half2_rn(a, b);
    return *reinterpret_cast<uint32_t*>(&h);
}

// ============================================================================
// HMMA GEMM (R8 core, verbatim): C[128,NT] = A[M,K] * B[N,K]^T, BK=64, 3 stages
// EPI: 0 = fp32 C = acc + bias?
//      1 = fp16 C16 = gelu(acc + bias)
//      6 = fp16 C16 = acc + bias?
//      9 = QKV route: hh<2 plain fp16; hh==2 V^T scatter
// ============================================================================
#define SPAD 72
#define STAGES 3

template <int NT, int EPI>
__global__ __launch_bounds__(256)
void hgemm(const __half* __restrict__ A, const __half* __restrict__ B,
           float* __restrict__ C, __half* __restrict__ C16,
           const float* __restrict__ bias,
           int K, int lda, int ldb, int ldc, int Hdim,
           long long aOB, long long aOH, long long bOB, long long bOH,
           long long cOB, long long cOH, long long biasOH)
{
    extern __shared__ __half smem[];

    const int tid = threadIdx.x, wid = tid >> 5, lane = tid & 31;
    const int wm = wid & 3, wn = wid >> 2;
    constexpr int WN = NT / 2;
    constexpr int NF = WN / 8;

    const int m0 = blockIdx.y * 128, n0 = blockIdx.x * NT;
    const int z = blockIdx.z, bb = z / Hdim, hh = z - bb * Hdim;
    A += (size_t)bb * aOB + (size_t)hh * aOH;
    B += (size_t)bb * bOB + (size_t)hh * bOH;
    if (bias) bias += (size_t)hh * biasOH;
    const long long coff = (long long)bb * cOB + (long long)hh * cOH;

    const uint32_t ABUF = 128 * SPAD * 2;
    const uint32_t BBUF = (uint32_t)NT * SPAD * 2;
    const uint32_t abase = smem_u32(smem);
    const uint32_t bbase = abase + STAGES * ABUF;

    const uint32_t a_off = (uint32_t)((wm * 32 + (lane & 15)) * (SPAD * 2) + ((lane >> 4) * 8) * 2);
    const uint32_t b_off = (uint32_t)((wn * WN + (lane & 7) + ((lane >> 4) << 3)) * (SPAD * 2)
                                      + (((lane >> 3) & 1) * 8) * 2);

    float acc[2][NF][4];
#pragma unroll
    for (int i = 0; i < 2; i++)
#pragma unroll
        for (int j = 0; j < NF; j++)
#pragma unroll
            for (int r = 0; r < 4; r++) acc[i][j][r] = 0.0f;

    const int nc = K >> 6;

    auto load_tile = [&](int c, int buf) {
        const __half* Ab = A + (size_t)m0 * lda + (size_t)c * 64;
#pragma unroll
        for (int it = 0; it < 4; it++) {
            int lin = it * 256 + tid;
            int row = lin >> 3, seg = lin & 7;
            cp16(abase + buf * ABUF + row * (SPAD * 2) + seg * 16,
                 Ab + (size_t)row * lda + seg * 8);
        }
        const __half* Bb = B + (size_t)n0 * ldb + (size_t)c * 64;
#pragma unroll
        for (int it = 0; it < NT / 32; it++) {
            int lin = it * 256 + tid;
            int row = lin >> 3, seg = lin & 7;
            cp16(bbase + buf * BBUF + row * (SPAD * 2) + seg * 16,
                 Bb + (size_t)row * ldb + seg * 8);
        }
    };

#pragma unroll
    for (int s = 0; s < STAGES - 1; s++) {
        if (s < nc) load_tile(s, s);
        CP_COMMIT();
    }

    for (int c = 0; c < nc; c++) {
        CP_WAIT(STAGES - 2);
        __syncthreads();
        const int nxt = c + STAGES - 1;
        if (nxt < nc) load_tile(nxt, nxt % STAGES);
        CP_COMMIT();

        const int buf = c % STAGES;
        const uint32_t ab = abase + buf * ABUF + a_off;
        const uint32_t bbf = bbase + buf * BBUF + b_off;

#pragma unroll
        for (int ks = 0; ks < 4; ks++) {
            uint32_t af[2][4];
#pragma unroll
            for (int mi = 0; mi < 2; mi++)
                ldm_x4(af[mi], ab + mi * 16 * (SPAD * 2) + ks * 32);
            uint32_t bf[NF][2];
#pragma unroll
            for (int p = 0; p < NF / 2; p++) {
                uint32_t t[4];
                ldm_x4(t, bbf + p * 16 * (SPAD * 2) + ks * 32);
                bf[2 * p][0] = t[0]; bf[2 * p][1] = t[1];
                bf[2 * p + 1][0] = t[2]; bf[2 * p + 1][1] = t[3];
            }
#pragma unroll
            for (int mi = 0; mi < 2; mi++)
#pragma unroll
                for (int nj = 0; nj < NF; nj++)
                    mma16816(acc[mi][nj], af[mi], bf[nj]);
        }
    }

#pragma unroll
    for (int mi = 0; mi < 2; mi++) {
#pragma unroll
        for (int nj = 0; nj < NF; nj++) {
            const int r0 = m0 + wm * 32 + mi * 16 + (lane >> 2);
            const int cc = n0 + wn * WN + nj * 8 + (lane & 3) * 2;
#pragma unroll
            for (int h = 0; h < 2; h++) {
                const int row = r0 + h * 8;
                const float v0 = acc[mi][nj][2 * h + 0];
                const float v1 = acc[mi][nj][2 * h + 1];
                if (EPI == 0) {
                    float b0 = bias ? bias[cc] : 0.f, b1 = bias ? bias[cc + 1] : 0.f;
                    float2 o = make_float2(v0 + b0, v1 + b1);
                    *(float2*)(C + coff + (size_t)row * ldc + cc) = o;
                } else if (EPI == 1 || EPI == 6) {
                    float o0 = v0 + (bias ? bias[cc] : 0.f);
                    float o1 = v1 + (bias ? bias[cc + 1] : 0.f);
                    if (EPI == 1) { o0 = gelu_tanh(o0); o1 = gelu_tanh(o1); }
                    *(uint32_t*)(C16 + coff + (size_t)row * ldc + cc) = pack_h2(o0, o1);
                } else if (EPI == 9) {
                    float o0 = v0 + bias[cc];
                    float o1 = v1 + bias[cc + 1];
                    if (hh < 2) {
                        *(uint32_t*)(C16 + coff + (size_t)row * ldc + cc) = pack_h2(o0, o1);
                    } else {
                        const int b_ = row >> 11, s_ = row & 2047;
                        const int h0 = cc >> 6, d0 = cc & 63;
                        const int h1 = (cc + 1) >> 6, d1 = (cc + 1) & 63;
                        C16[coff + ((size_t)((b_ * Hc + h0) * DHc + d0)) * Sc + s_] = __float2half(o0);
                        C16[coff + ((size_t)((b_ * Hc + h1) * DHc + d1)) * Sc + s_] = __float2half(o1);
                    }
                }
            }
        }
    }
}

static const int SMEM_NT128 = STAGES * (128 + 128) * SPAD * 2;  // 110592

// ============================================================================
// FlashAttention-2 fused attention, q-tile 64, kv-tile 64, XOR-swizzled smem.
// Smem 40 KB; launch_bounds(128,4) -> 4 CTAs = 16 warps/SM.
// ============================================================================
static const int KROWB = 128;     // Q/K row bytes (64 halves of head dim)
static const int VROWB = 128;     // V^T row bytes (64 kv halves)
static const int SMEM_FA = 64 * KROWB + 2 * 64 * KROWB + 2 * 64 * VROWB; // 40960

__global__ __launch_bounds__(128, 4)
void flash_attn(const __half* __restrict__ Qg, const __half* __restrict__ Kg,
                const __half* __restrict__ Vt, const __half* __restrict__ Mk,
                __half* __restrict__ Og)
{
    extern __shared__ __half sm[];
    const int tid = threadIdx.x, wid = tid >> 5, lane = tid & 31;
    const int q0 = blockIdx.x * 64;
    const int z = blockIdx.y, bb = z >> 4, hh = z & 15;

    const uint32_t qs  = smem_u32(sm);
    const uint32_t ks0 = qs + 64 * KROWB;
    const uint32_t KBUF = 64 * KROWB;
    const uint32_t vs0 = ks0 + 2 * KBUF;
    const uint32_t VBUF = 64 * VROWB;

    const __half* Qb = Qg + ((size_t)bb * Sc + q0) * Dc + hh * DHc;
    const __half* Kb = Kg + (size_t)bb * Sc * Dc + hh * DHc;
    const __half* Vb = Vt + ((size_t)(bb * Hc + hh)) * DHc * Sc;
    const __half* Mb = Mk + (size_t)bb * Sc * Sc;

    auto loadKV = [&](int t, int buf) {
        const __half* ksrc = Kb + (size_t)(t * 64) * Dc;
#pragma unroll
        for (int it = 0; it < 4; it++) {
            int lin = it * 128 + tid, row = lin >> 3, seg = lin & 7;
            uint32_t c = (uint32_t)(seg * 16) ^ (((uint32_t)row & 7u) << 4);
            cp16(ks0 + buf * KBUF + row * KROWB + c, ksrc + (size_t)row * Dc + seg * 8);
        }
#pragma unroll
        for (int it = 0; it < 4; it++) {
            int lin = it * 128 + tid, row = lin >> 3, seg = lin & 7;
            uint32_t c = (uint32_t)(seg * 16) ^ (((uint32_t)row & 7u) << 4);
            cp16(vs0 + buf * VBUF + row * VROWB + c,
                 Vb + (size_t)row * Sc + t * 64 + seg * 8);
        }
    };

    // prologue: Q + KV(0)
#pragma unroll
    for (int it = 0; it < 4; it++) {
        int lin = it * 128 + tid, row = lin >> 3, seg = lin & 7;
        uint32_t c = (uint32_t)(seg * 16) ^ (((uint32_t)row & 7u) << 4);
        cp16(qs + row * KROWB + c, Qb + (size_t)row * Dc + seg * 8);
    }
    loadKV(0, 0);
    CP_COMMIT();

    // ---- per-thread swizzle-folded constants
    const uint32_t xm   = ((uint32_t)lane & 7u) << 4;
    const uint32_t xm60 = xm & 0x60;
    const uint32_t xm10 = xm & 0x10;
    const uint32_t qrb = qs + (uint32_t)(wid * 16 + (lane & 15)) * KROWB
                       + (((uint32_t)(lane >> 4) * 16) ^ xm10);
    const uint32_t kvsel = (((uint32_t)(lane >> 3) & 1u) * 16) ^ xm10;
    const uint32_t krb = (uint32_t)((lane & 7) + ((lane >> 4) << 3)) * KROWB + kvsel;
    const uint32_t vrb = (uint32_t)((lane & 7) + ((lane >> 4) << 3)) * VROWB + kvsel;

    const int r = lane >> 2;
    const int qrow = q0 + wid * 16 + r;

    float o[8][4];
#pragma unroll
    for (int j = 0; j < 8; j++) { o[j][0] = o[j][1] = o[j][2] = o[j][3] = 0.f; }
    float rm0 = -1e30f, rm1 = -1e30f, rl0 = 0.f, rl1 = 0.f;

    for (int t = 0; t < Sc / 64; t++) {
        __syncthreads();
        if (t + 1 < Sc / 64) loadKV(t + 1, (t + 1) & 1);
        CP_COMMIT();
        CP_WAIT(1);
        __syncthreads();

        const uint32_t kb = ks0 + (t & 1) * KBUF + krb;
        const uint32_t vb = vs0 + (t & 1) * VBUF + vrb;

        // ---- S = Q K^T  (16 q rows x 64 k cols per warp)
        float s[8][4];
#pragma unroll
        for (int j = 0; j < 8; j++) { s[j][0] = s[j][1] = s[j][2] = s[j][3] = 0.f; }
#pragma unroll
        for (int ks = 0; ks < 4; ks++) {
            uint32_t af[4];
            ldm_x4(af, qrb + ((uint32_t)(ks * 32) ^ xm60));
#pragma unroll
            for (int p = 0; p < 4; p++) {
                uint32_t tt[4];
                ldm_x4(tt, kb + p * 16 * KROWB + ((uint32_t)(ks * 32) ^ xm60));
                mma16816(s[2 * p], af, tt);
                mma16816(s[2 * p + 1], af, tt + 2);
            }
        }

        // ---- scale + mask + row max
        const __half* mr0 = Mb + (size_t)qrow * Sc + t * 64 + (lane & 3) * 2;
        const __half* mr1 = mr0 + 8 * Sc;
        float tm0 = -1e30f, tm1 = -1e30f;
#pragma unroll
        for (int j = 0; j < 8; j++) {
            float2 m0 = __half22float2(*(const __half2*)(mr0 + j * 8));
            float2 m1 = __half22float2(*(const __half2*)(mr1 + j * 8));
            s[j][0] = s[j][0] * 0.125f + m0.x;
            s[j][1] = s[j][1] * 0.125f + m0.y;
            s[j][2] = s[j][2] * 0.125f + m1.x;
            s[j][3] = s[j][3] * 0.125f + m1.y;
            tm0 = fmaxf(tm0, fmaxf(s[j][0], s[j][1]));
            tm1 = fmaxf(tm1, fmaxf(s[j][2], s[j][3]));
        }
#pragma unroll
        for (int off = 1; off <= 2; off <<= 1) {
            tm0 = fmaxf(tm0, __shfl_xor_sync(0xffffffffu, tm0, off));
            tm1 = fmaxf(tm1, __shfl_xor_sync(0xffffffffu, tm1, off));
        }
        const float mn0 = fmaxf(rm0, tm0), mn1 = fmaxf(rm1, tm1);
        const float cr0 = __expf(rm0 - mn0), cr1 = __expf(rm1 - mn1);
        rm0 = mn0; rm1 = mn1;

        // ---- exp + pack P
        uint32_t pk[8][2];
        float ps0 = 0.f, ps1 = 0.f;
#pragma unroll
        for (int j = 0; j < 8; j++) {
            float p0 = __expf(s[j][0] - mn0), p1 = __expf(s[j][1] - mn0);
            float p2 = __expf(s[j][2] - mn1), p3 = __expf(s[j][3] - mn1);
            ps0 += p0 + p1; ps1 += p2 + p3;
            pk[j][0] = pack_h2(p0, p1);
            pk[j][1] = pack_h2(p2, p3);
        }
#pragma unroll
        for (int off = 1; off <= 2; off <<= 1) {
            ps0 += __shfl_xor_sync(0xffffffffu, ps0, off);
            ps1 += __shfl_xor_sync(0xffffffffu, ps1, off);
        }
        rl0 = rl0 * cr0 + ps0;
        rl1 = rl1 * cr1 + ps1;

        // ---- rescale O
#pragma unroll
        for (int j = 0; j < 8; j++) {
            o[j][0] *= cr0; o[j][1] *= cr0;
            o[j][2] *= cr1; o[j][3] *= cr1;
        }

        // ---- O += P @ V  (k = 64 s-keys, 4 k-steps)
#pragma unroll
        for (int ks = 0; ks < 4; ks++) {
            uint32_t af[4] = { pk[2 * ks][0], pk[2 * ks][1], pk[2 * ks + 1][0], pk[2 * ks + 1][1] };
#pragma unroll
            for (int p = 0; p < 4; p++) {
                uint32_t tt[4];
                ldm_x4(tt, vb + p * 16 * VROWB + ((uint32_t)(ks * 32) ^ xm60));
                mma16816(o[2 * p], af, tt);
                mma16816(o[2 * p + 1], af, tt + 2);
            }
        }
    }

    // ---- write O
    const float i0 = 1.0f / rl0, i1 = 1.0f / rl1;
    __half* or0 = Og + ((size_t)bb * Sc + qrow) * Dc + hh * DHc + (lane & 3) * 2;
    __half* or1 = or0 + 8 * Dc;
#pragma unroll
    for (int j = 0; j < 8; j++) {
        *(uint32_t*)(or0 + j * 8) = pack_h2(o[j][0] * i0, o[j][1] * i0);
        *(uint32_t*)(or1 + j * 8) = pack_h2(o[j][2] * i1, o[j][3] * i1);
    }
}

// ---------------- small kernels ----------------
// one launch: hidden fp32->fp16, mask fp32->fp16, QKV bias pack
__global__ void conv_all(const float* __restrict__ hid, __half* __restrict__ hid16,
                         const float* __restrict__ msk, __half* __restrict__ msk16,
                         const float* __restrict__ bq, const float* __restrict__ bk,
                         const float* __restrict__ bv, float* __restrict__ qkvb)
{
    int i = blockIdx.x * blockDim.x + threadIdx.x;
    {
        float4 v = ((const float4*)msk)[i];
        uint2 u;
        u.x = pack_h2(v.x, v.y); u.y = pack_h2(v.z, v.w);
        ((uint2*)msk16)[i] = u;
    }
    if (i < NTOK * Dc / 4) {
        float4 v = ((const float4*)hid)[i];
        uint2 u;
        u.x = pack_h2(v.x, v.y); u.y = pack_h2(v.z, v.w);
        ((uint2*)hid16)[i] = u;
    }
    if (i < Dc) { qkvb[i] = bq[i]; qkvb[Dc + i] = bk[i]; qkvb[2 * Dc + i] = bv[i]; }
}

__global__ void tconv_all(const float* __restrict__ wq, const float* __restrict__ wk,
                          const float* __restrict__ wv, const float* __restrict__ wo,
                          const float* __restrict__ w1, const float* __restrict__ w2,
                          __half* __restrict__ dstbase)
{
    __shared__ float t[32][33];
    int b = blockIdx.x;
    const float* src; __half* dst; int K, N;
    if (b < 4096) {
        int m = b >> 10; b &= 1023;
        src = (m == 0) ? wq : (m == 1) ? wk : (m == 2) ? wv : wo;
        dst = dstbase + (size_t)m * Dc * Dc; K = Dc; N = Dc;
    } else if (b < 4096 + 32768) {
        b -= 4096; int e = b >> 12; b &= 4095;
        src = w1 + (size_t)e * Dc * Fc;
        dst = dstbase + 4 * (size_t)Dc * Dc + (size_t)e * Dc * Fc; K = Dc; N = Fc;
    } else {
        b -= 36864; int e = b >> 12; b &= 4095;
        src = w2 + (size_t)e * Fc * Dc;
        dst = dstbase + 4 * (size_t)Dc * Dc + (size_t)Ec * Dc * Fc + (size_t)e * Fc * Dc;
        K = Fc; N = Dc;
    }
    const int ntx = N / 32;
    const int k0 = (b / ntx) * 32, n0 = (b % ntx) * 32;
    const int x = threadIdx.x, y = threadIdx.y;
#pragma unroll
    for (int i = 0; i < 32; i += 8)
        t[y + i][x] = src[(size_t)(k0 + y + i) * N + n0 + x];
    __syncthreads();
#pragma unroll
    for (int i = 0; i < 32; i += 8)
        dst[(size_t)(n0 + y + i) * K + k0 + x] = __float2half(t[x][y + i]);
}

// LN1(attn + hidden) -> inter (fp32 + fp16)  AND  gate = softmax(inter @ gw + gb)
__global__ void ln1_gate(const float* __restrict__ x, const float* __restrict__ r,
                         const float* __restrict__ g, const float* __restrict__ b,
                         const float* __restrict__ gw, const float* __restrict__ gb,
                         float* __restrict__ out, __half* __restrict__ out16,
                         float* __restrict__ gate, float* __restrict__ gate_out)
{
    __shared__ float red[256];
    __shared__ float wsum[8][Ec];
    __shared__ float logits[Ec];
    const int m = blockIdx.x;
    const size_t base = (size_t)m * Dc;
    const int tid = threadIdx.x, wid = tid >> 5, lane = tid & 31;

    float v[4]; float s = 0.f;
#pragma unroll
    for (int i = 0; i < 4; i++) { const int c = tid + i * 256; v[i] = x[base + c] + r[base + c]; s += v[i]; }
    red[tid] = s; __syncthreads();
    for (int st = 128; st > 0; st >>= 1) { if (tid < st) red[tid] += red[tid + st]; __syncthreads(); }
    const float mean = red[0] * (1.0f / Dc); __syncthreads();
    float ss = 0.f;
#pragma unroll
    for (int i = 0; i < 4; i++) { const float d = v[i] - mean; ss += d * d; }
    red[tid] = ss; __syncthreads();
    for (int st = 128; st > 0; st >>= 1) { if (tid < st) red[tid] += red[tid + st]; __syncthreads(); }
    const float rstd = rsqrtf(red[0] * (1.0f / Dc) + LN_EPS);

    float ge[Ec];
#pragma unroll
    for (int e = 0; e < Ec; e++) ge[e] = 0.f;

#pragma unroll
    for (int i = 0; i < 4; i++) {
        const int c = tid + i * 256;
        const float o = (v[i] - mean) * rstd * g[c] + b[c];
        out[base + c] = o;
        out16[base + c] = __float2half(o);
        const float4 w0 = *(const float4*)(gw + (size_t)c * Ec);
        const float4 w1 = *(const float4*)(gw + (size_t)c * Ec + 4);
        ge[0] += o * w0.x; ge[1] += o * w0.y; ge[2] += o * w0.z; ge[3] += o * w0.w;
        ge[4] += o * w1.x; ge[5] += o * w1.y; ge[6] += o * w1.z; ge[7] += o * w1.w;
    }
#pragma unroll
    for (int off = 16; off > 0; off >>= 1)
#pragma unroll
        for (int e = 0; e < Ec; e++)
            ge[e] += __shfl_down_sync(0xffffffffu, ge[e], off);
    if (lane == 0)
#pragma unroll
        for (int e = 0; e < Ec; e++) wsum[wid][e] = ge[e];
    __syncthreads();
    if (tid < Ec) {
        float t = gb[tid];
#pragma unroll
        for (int w = 0; w < 8; w++) t += wsum[w][tid];
        logits[tid] = t;
    }
    __syncthreads();
    if (tid == 0) {
        float mx = logits[0];
#pragma unroll
        for (int e = 1; e < Ec; e++) mx = fmaxf(mx, logits[e]);
        float p[Ec]; float sum = 0.f;
#pragma unroll
        for (int e = 0; e < Ec; e++) { p[e] = expf(logits[e] - mx); sum += p[e]; }
        const float inv = 1.0f / sum;
#pragma unroll
        for (int e = 0; e < Ec; e++) {
            const float pv = p[e] * inv;
            gate[(size_t)m * Ec + e] = pv;
            if (gate_out) gate_out[(size_t)m * Ec + e] = pv;
        }
    }
}

// fused: out = LN2( sum_e gate[e]*p2[e] + inter )
__global__ void ln2_moe(const __half* __restrict__ part, const float* __restrict__ gate,
                        const float* __restrict__ inter,
                        const float* __restrict__ g, const float* __restrict__ b,
                        float* __restrict__ out)
{
    __shared__ float red[256];
    __shared__ float gs[Ec];
    const int m = blockIdx.x, tid = threadIdx.x;
    if (tid < Ec) gs[tid] = gate[(size_t)m * Ec + tid];
    __syncthreads();
    const size_t base = (size_t)m * Dc;

    float v[4]; float s = 0.f;
#pragma unroll
    for (int i = 0; i < 2; i++) {
        const int c = tid * 2 + i * 512;
        float2 acc = *(const float2*)(inter + base + c);
#pragma unroll
        for (int e = 0; e < Ec; e++) {
            float2 f = __half22float2(*(const __half2*)(part + (size_t)e * NTOK * Dc + base + c));
            acc.x += gs[e] * f.x;
            acc.y += gs[e] * f.y;
        }
        v[2 * i] = acc.x; v[2 * i + 1] = acc.y;
        s += acc.x + acc.y;
    }
    red[tid] = s; __syncthreads();
    for (int st = 128; st > 0; st >>= 1) { if (tid < st) red[tid] += red[tid + st]; __syncthreads(); }
    const float mean = red[0] * (1.0f / Dc); __syncthreads();
    float ss = 0.f;
#pragma unroll
    for (int j = 0; j < 4; j++) { const float d = v[j] - mean; ss += d * d; }
    red[tid] = ss; __syncthreads();
    for (int st = 128; st > 0; st >>= 1) { if (tid < st) red[tid] += red[tid + st]; __syncthreads(); }
    const float rstd = rsqrtf(red[0] * (1.0f / Dc) + LN_EPS);
#pragma unroll
    for (int i = 0; i < 2; i++) {
        const int c = tid * 2 + i * 512;
        float2 o;
        o.x = (v[2 * i]     - mean) * rstd * g[c]     + b[c];
        o.y = (v[2 * i + 1] - mean) * rstd * g[c + 1] + b[c + 1];
        *(float2*)(out + base + c) = o;
    }
}

// ---------------- launch ----------------------------------------------------
extern "C" void kernel_launch(void* const* d_in, const int* in_sizes, int n_in,
                              void* d_out, int out_size)
{
    const float* hidden = (const float*)d_in[0];
    const float* mask   = (const float*)d_in[1];
    const float* wq = (const float*)d_in[2];  const float* bq = (const float*)d_in[3];
    const float* wk = (const float*)d_in[4];  const float* bk = (const float*)d_in[5];
    const float* wv = (const float*)d_in[6];  const float* bv = (const float*)d_in[7];
    const float* wo = (const float*)d_in[8];  const float* bo = (const float*)d_in[9];
    const float* ln1_g = (const float*)d_in[10]; const float* ln1_b = (const float*)d_in[11];
    const float* gate_w = (const float*)d_in[12]; const float* gate_b = (const float*)d_in[13];
    const float* w1 = (const float*)d_in[14]; const float* b1 = (const float*)d_in[15];
    const float* w2 = (const float*)d_in[16]; const float* b2 = (const float*)d_in[17];
    const float* ln2_g = (const float*)d_in[18]; const float* ln2_b = (const float*)d_in[19];

    float* f32 = nullptr;  __half* f16 = nullptr;
    cudaGetSymbolAddress((void**)&f32, g_f32);
    cudaGetSymbolAddress((void**)&f16, g_f16);

    float*  attn   = f32 + F_ATTN;
    float*  inter  = f32 + F_INT;
    float*  gate   = f32 + F_GATE;
    float*  qkvb   = f32 + F_QKVB;
    __half* hid16  = f16 + H_HID;
    __half* q16    = f16 + H_Q;
    __half* k16    = f16 + H_K;
    __half* vT16   = f16 + H_VT;
    __half* ctx16  = f16 + H_CTX;
    __half* int16_ = f16 + H_INT;
    __half* msk16  = f16 + H_MSK;
    __half* h16    = f16 + H_HB;
    __half* p2     = f16 + H_P2;
    __half* wqT = f16 + H_WQ;
    __half* woT = f16 + H_WQ + 3 * (size_t)Dc * Dc;
    __half* w1T = f16 + H_W1; __half* w2T = f16 + H_W2;

    float* out = (float*)d_out;
    float* gate_out = nullptr;
    if ((size_t)out_size >= (size_t)NTOK * Dc + (size_t)NTOK * Ec)
        gate_out = out + (size_t)NTOK * Dc;

    cudaFuncSetAttribute(hgemm<128,0>, cudaFuncAttributeMaxDynamicSharedMemorySize, SMEM_NT128);
    cudaFuncSetAttribute(hgemm<128,1>, cudaFuncAttributeMaxDynamicSharedMemorySize, SMEM_NT128);
    cudaFuncSetAttribute(hgemm<128,6>, cudaFuncAttributeMaxDynamicSharedMemorySize, SMEM_NT128);
    cudaFuncSetAttribute(hgemm<128,9>, cudaFuncAttributeMaxDynamicSharedMemorySize, SMEM_NT128);
    cudaFuncSetAttribute(flash_attn,   cudaFuncAttributeMaxDynamicSharedMemorySize, SMEM_FA);

    const dim3 blk(256);
    const dim3 tblk(32, 8);

    // 0) hidden + mask conversion + bias pack
    conv_all<<<(int)((size_t)Bc * Sc * Sc / 4 / 256), 256>>>(
        hidden, hid16, mask, msk16, bq, bk, bv, qkvb);
    // 1) all weight transposes
    tconv_all<<<69632, tblk>>>(wq, wk, wv, wo, w1, w2, wqT);

    // 2) fused Q/K/V projection (z = 0,1,2 -> q16, k16, vT scatter)
    {
        dim3 grid(Dc / 128, NTOK / 128, 3);
        hgemm<128,9><<<grid, blk, SMEM_NT128>>>(hid16, wqT, nullptr, q16, qkvb,
            Dc, Dc, Dc, Dc, 3,
            0, 0,
            0, (long long)Dc * Dc,
            0, (long long)NTOK * Dc,
            (long long)Dc);
    }

    // 3) fused attention (q64/kv64, swizzled, 4 CTAs/SM) -> ctx16
    {
        dim3 grid(Sc / 64, Bc * Hc);
        flash_attn<<<grid, 128, SMEM_FA>>>(q16, k16, vT16, msk16, ctx16);
    }

    // 4) output projection -> fp32 attn
    {
        dim3 grid(Dc / 128, NTOK / 128, 1);
        hgemm<128,0><<<grid, blk, SMEM_NT128>>>(ctx16, woT, attn, nullptr, bo,
            Dc, Dc, Dc, Dc, 1, 0,0,0,0,0,0,0);
    }

    // 5) inter = LN1(attn + hidden) fused with gate softmax
    ln1_gate<<<NTOK, 256>>>(attn, hidden, ln1_g, ln1_b, gate_w, gate_b,
                            inter, int16_, gate, gate_out);

    // 6-7) MoE batched across experts (z = expert)
    {
        dim3 gh(Fc / 128, NTOK / 128, Ec);
        hgemm<128,1><<<gh, blk, SMEM_NT128>>>(int16_, w1T, nullptr, h16, b1,
            Dc, Dc, Dc, Fc, Ec,
            0, 0,
            0, (long long)Dc * Fc,
            0, (long long)NTOK * Fc,
            (long long)Fc);

        dim3 gy(Dc / 128, NTOK / 128, Ec);
        hgemm<128,6><<<gy, blk, SMEM_NT128>>>(h16, w2T, nullptr, p2, b2,
            Fc, Fc, Fc, Dc, Ec,
            0, (long long)NTOK * Fc,
            0, (long long)Fc * Dc,
            0, (long long)NTOK * Dc,
            (long long)Dc);
    }

    // 8) fused gate-weighted reduce + LN2 -> out
    ln2_moe<<<NTOK, 256>>>(p2, gate, inter, ln2_g, ln2_b, out);
}